// round 12
// baseline (speedup 1.0000x reference)
#include <cuda_runtime.h>
#include <cuda_bf16.h>
#include <math.h>
#include <stdint.h>

#define BB 4
#define HH 256
#define WW 256
#define HWSZ 65536
#define NPX (BB*HWSZ)

// ---------------------------------------------------------------------------
// PTX helpers (plain sm_103-safe: ldmatrix + mma.sync + cp.async)
// ---------------------------------------------------------------------------
__device__ __forceinline__ uint32_t smem_u32(const void* p) {
    uint32_t a;
    asm("{ .reg .u64 t; cvta.to.shared.u64 t, %1; cvt.u32.u64 %0, t; }" : "=r"(a) : "l"(p));
    return a;
}

#define LDSM_X4(r0, r1, r2, r3, addr) \
    asm volatile("ldmatrix.sync.aligned.m8n8.x4.shared.b16 {%0,%1,%2,%3}, [%4];" \
        : "=r"(r0), "=r"(r1), "=r"(r2), "=r"(r3) : "r"(addr))

#define MMA_BF16(d, a, b0v, b1v) \
    asm volatile("mma.sync.aligned.m16n8k16.row.col.f32.bf16.bf16.f32 " \
        "{%0,%1,%2,%3},{%4,%5,%6,%7},{%8,%9},{%0,%1,%2,%3};" \
        : "+f"((d)[0]), "+f"((d)[1]), "+f"((d)[2]), "+f"((d)[3]) \
        : "r"((a)[0]), "r"((a)[1]), "r"((a)[2]), "r"((a)[3]), "r"(b0v), "r"(b1v))

#define CP_ASYNC16(dst, src, sz) \
    asm volatile("cp.async.cg.shared.global [%0], [%1], 16, %2;" \
        :: "r"(dst), "l"(src), "r"(sz) : "memory")
#define CP_COMMIT() asm volatile("cp.async.commit_group;" ::: "memory")
#define CP_WAIT1() asm volatile("cp.async.wait_group 1;" ::: "memory")
#define CP_WAIT0() asm volatile("cp.async.wait_group 0;" ::: "memory")

// Fast transcendentals for DCN offsets. Clamp keeps exp finite; tanh(15)==1 in fp32.
__device__ __forceinline__ float fast_tanh(float x) {
    float xc = fminf(fmaxf(x, -15.f), 15.f);
    float e2 = __expf(2.f * xc);
    return __fdividef(e2 - 1.f, e2 + 1.f);
}
__device__ __forceinline__ float fast_sigmoid(float x) {
    return __fdividef(1.f, 1.f + __expf(-x));
}

// ---------------------------------------------------------------------------
// Device global scratch
// ---------------------------------------------------------------------------
#define FEAT_ELEMS ((size_t)NPX*64)
__device__ __nv_bfloat16 g_wH[FEAT_ELEMS], g_wL[FEAT_ELEMS];     // warped supp
__device__ __nv_bfloat16 g_rH[FEAT_ELEMS], g_rL[FEAT_ELEMS];     // ref
__device__ __nv_bfloat16 g_t0H[FEAT_ELEMS], g_t0L[FEAT_ELEMS];   // feat0
__device__ __nv_bfloat16 g_tmpH[FEAT_ELEMS], g_tmpL[FEAT_ELEMS];
__device__ __nv_bfloat16 g_ftH[FEAT_ELEMS], g_ftL[FEAT_ELEMS];   // final feat
__device__ float g_f0F[FEAT_ELEMS];                               // feat0 fp32
__device__ float g_ffF[FEAT_ELEMS];                               // feat fp32 accum
__device__ float g_off[(size_t)BB*216*HWSZ];                      // NCHW
__device__ float g_sN[FEAT_ELEMS];                                // supp NHWC fp32
// 13 B-sets (fc0, fc1, c1..c6, off chunks 0..3, dcn); each 9 taps x 16KB
#define BSET 73728
__device__ __nv_bfloat16 g_B[13*BSET];

// ---------------------------------------------------------------------------
// Fused B prep: all 13 sets in one launch (blockIdx.y = set)
// ---------------------------------------------------------------------------
struct PrepDesc { const float* w; int cinTot, cin0, coutTot, cout0; };
struct PrepTable { PrepDesc d[13]; };

__global__ void prep_all_kernel(PrepTable tab, __nv_bfloat16* __restrict__ outB)
{
    int set = blockIdx.y;
    PrepDesc pd = tab.d[set];
    int idx = blockIdx.x * 256 + threadIdx.x;   // < 36864
    int c = idx & 63;
    int r = (idx >> 6) & 63;
    int t = idx >> 12;
    float v = 0.f;
    int co = pd.cout0 + r;
    if (co < pd.coutTot) v = pd.w[((size_t)co * pd.cinTot + pd.cin0 + c) * 9 + t];
    __nv_bfloat16 h = __float2bfloat16(v);
    __nv_bfloat16 l = __float2bfloat16(v - __bfloat162float(h));
    uint32_t off = (uint32_t)r * 128u + (uint32_t)c * 2u;
    uint32_t so = off ^ ((off >> 3) & 0x70u);
    char* ob = (char*)(outB + (size_t)set * BSET) + (size_t)t * 16384;
    *(__nv_bfloat16*)(ob + so) = h;
    *(__nv_bfloat16*)(ob + 8192 + so) = l;
}

// ---------------------------------------------------------------------------
// supp NCHW fp32 -> NHWC fp32 (smem-tiled transpose, 64px x 64ch per block)
// ---------------------------------------------------------------------------
__global__ void supp_nhwc_kernel(const float* __restrict__ src, float* __restrict__ dst)
{
    __shared__ float s[64 * 65];
    int b  = blockIdx.y;
    int x0 = blockIdx.x * 64;     // linear pixel base
    int tid = threadIdx.x;
    int lc = tid >> 6;            // 0..3
    int lp = tid & 63;
    #pragma unroll
    for (int i = 0; i < 16; i++) {
        int c = i * 4 + lc;
        s[lp * 65 + c] = src[((size_t)b * 64 + c) * HWSZ + x0 + lp];
    }
    __syncthreads();
    int px = tid >> 2, q4 = (tid & 3) * 16;
    float* dp = dst + ((size_t)b * HWSZ + x0 + px) * 64 + q4;
    const float* sp = s + px * 65 + q4;
    #pragma unroll
    for (int q = 0; q < 4; q++)
        ((float4*)dp)[q] = make_float4(sp[q*4], sp[q*4+1], sp[q*4+2], sp[q*4+3]);
}

// ---------------------------------------------------------------------------
// flow_warp (reads NHWC fp32 supp, vectorized corners) -> NHWC bf16 hi/lo
// ---------------------------------------------------------------------------
__global__ void warp_nhwc_kernel(const float* __restrict__ suppN, const float* __restrict__ flow,
                                 __nv_bfloat16* __restrict__ oH, __nv_bfloat16* __restrict__ oL)
{
    int p = blockIdx.x * 256 + threadIdx.x;
    int b = blockIdx.y;
    int y = p >> 8, x = p & 255;
    float fx = flow[((size_t)b*2    )*HWSZ + p];
    float fy = flow[((size_t)b*2 + 1)*HWSZ + p];
    float sy = (float)y + fy, sx = (float)x + fx;
    float y0f = floorf(sy), x0f = floorf(sx);
    int iy0 = (int)y0f, ix0 = (int)x0f, iy1 = iy0+1, ix1 = ix0+1;
    float wy = sy - y0f, wx = sx - x0f;
    bool vy0 = ((unsigned)iy0 < HH), vy1 = ((unsigned)iy1 < HH);
    bool vx0 = ((unsigned)ix0 < WW), vx1 = ((unsigned)ix1 < WW);
    float w00 = (1.f-wy)*(1.f-wx) * ((vy0&&vx0)?1.f:0.f);
    float w01 = (1.f-wy)*wx       * ((vy0&&vx1)?1.f:0.f);
    float w10 = wy*(1.f-wx)       * ((vy1&&vx0)?1.f:0.f);
    float w11 = wy*wx             * ((vy1&&vx1)?1.f:0.f);
    int cy0 = min(max(iy0,0),HH-1), cy1 = min(max(iy1,0),HH-1);
    int cx0 = min(max(ix0,0),WW-1), cx1 = min(max(ix1,0),WW-1);
    size_t i00 = (size_t)(cy0*WW+cx0)*64, i01 = (size_t)(cy0*WW+cx1)*64;
    size_t i10 = (size_t)(cy1*WW+cx0)*64, i11 = (size_t)(cy1*WW+cx1)*64;
    const float* sb = suppN + (size_t)b*HWSZ*64;
    __nv_bfloat16* ohp = oH + ((size_t)b*HWSZ + p)*64;
    __nv_bfloat16* olp = oL + ((size_t)b*HWSZ + p)*64;
    #pragma unroll 1
    for (int g = 0; g < 8; g++) {
        const float4* p00 = (const float4*)(sb + i00 + g*8);
        const float4* p01 = (const float4*)(sb + i01 + g*8);
        const float4* p10 = (const float4*)(sb + i10 + g*8);
        const float4* p11 = (const float4*)(sb + i11 + g*8);
        float v[8];
        #pragma unroll
        for (int h = 0; h < 2; h++) {
            float4 a = p00[h], bb = p01[h], cc = p10[h], dd = p11[h];
            v[h*4+0] = w00*a.x + w01*bb.x + w10*cc.x + w11*dd.x;
            v[h*4+1] = w00*a.y + w01*bb.y + w10*cc.y + w11*dd.y;
            v[h*4+2] = w00*a.z + w01*bb.z + w10*cc.z + w11*dd.z;
            v[h*4+3] = w00*a.w + w01*bb.w + w10*cc.w + w11*dd.w;
        }
        uint4 uh, ul;
        uint32_t* ph = (uint32_t*)&uh;
        uint32_t* pl = (uint32_t*)&ul;
        #pragma unroll
        for (int q = 0; q < 4; q++) {
            __nv_bfloat162 h2 = __floats2bfloat162_rn(v[q*2], v[q*2+1]);
            float2 hf = __bfloat1622float2(h2);
            __nv_bfloat162 l2 = __floats2bfloat162_rn(v[q*2] - hf.x, v[q*2+1] - hf.y);
            ph[q] = *(uint32_t*)&h2;
            pl[q] = *(uint32_t*)&l2;
        }
        ((uint4*)ohp)[g] = uh;
        ((uint4*)olp)[g] = ul;
    }
}

// NCHW fp32 -> NHWC bf16 hi/lo (ref)
__global__ void to_nhwc_kernel(const float* __restrict__ src,
                               __nv_bfloat16* __restrict__ oH, __nv_bfloat16* __restrict__ oL)
{
    int p = blockIdx.x * 256 + threadIdx.x;
    int b = blockIdx.y;
    const float* sp = src + (size_t)b*64*HWSZ + p;
    __nv_bfloat16* ohp = oH + ((size_t)b*HWSZ + p)*64;
    __nv_bfloat16* olp = oL + ((size_t)b*HWSZ + p)*64;
    for (int g = 0; g < 8; g++) {
        uint4 uh, ul;
        uint32_t* ph = (uint32_t*)&uh;
        uint32_t* pl = (uint32_t*)&ul;
        #pragma unroll
        for (int q = 0; q < 4; q++) {
            float v0 = sp[(size_t)(g*8 + q*2    )*HWSZ];
            float v1 = sp[(size_t)(g*8 + q*2 + 1)*HWSZ];
            __nv_bfloat162 h2 = __floats2bfloat162_rn(v0, v1);
            float2 hf = __bfloat1622float2(h2);
            __nv_bfloat162 l2 = __floats2bfloat162_rn(v0 - hf.x, v1 - hf.y);
            ph[q] = *(uint32_t*)&h2;
            pl[q] = *(uint32_t*)&l2;
        }
        ((uint4*)ohp)[g] = uh;
        ((uint4*)olp)[g] = ul;
    }
}

// ---------------------------------------------------------------------------
// mma.sync conv (unchanged, passing): single A buffer per ki group,
// double-buffered B, 3 CTAs/SM; group-accounting invariant in the wait logic.
// ---------------------------------------------------------------------------
template<int DIL, int EPI, int HASBIAS, int NT>
__global__ void __launch_bounds__(256, 3)
conv_mma_kernel(const __nv_bfloat16* __restrict__ inH,
                const __nv_bfloat16* __restrict__ inL,
                const __nv_bfloat16* __restrict__ inH2,
                const __nv_bfloat16* __restrict__ inL2,
                const __nv_bfloat16* __restrict__ Bimg,
                const float* __restrict__ bias,
                int nchunk, int coutTot,
                float* __restrict__ outF,
                __nv_bfloat16* __restrict__ outH,
                __nv_bfloat16* __restrict__ outL,
                const float* __restrict__ resF,
                float* __restrict__ outNCHW)
{
    constexpr uint32_t R = 128 + 2 * DIL;
    constexpr uint32_t AHALF = R * 128u;
    constexpr uint32_t ABUF = 2u * AHALF;

    extern __shared__ char smem[];
    uint32_t base = (smem_u32(smem) + 1023u) & ~1023u;

    int tid = threadIdx.x;
    int lane = tid & 31, w = tid >> 5;
    int z = blockIdx.z;
    int b = z / nchunk, chunk = z - b * nchunk;
    int y = blockIdx.y, x0 = blockIdx.x * 128;

    const char* Bbase = (const char*)Bimg + (size_t)chunk * 147456;

    auto stageA = [&](int s) {
        int ki = (NT == 18 && s >= 3) ? s - 3 : s;
        const __nv_bfloat16* iH = (NT == 18 && s >= 3) ? inH2 : inH;
        const __nv_bfloat16* iL = (NT == 18 && s >= 3) ? inL2 : inL;
        int gy = y + (ki - 1) * DIL;
        bool rowok = ((unsigned)gy < HH);
        for (int i = tid; i < (int)(R * 8); i += 256) {
            int r = i >> 3, j = i & 7;
            int gx = x0 - DIL + r;
            bool ok = rowok && ((unsigned)gx < WW);
            size_t gidx = ok ? ((((size_t)b * HH + gy) * WW + gx) * 64) : 0;
            int sz = ok ? 16 : 0;
            uint32_t dst = base + (uint32_t)r * 128u +
                           (((uint32_t)j * 16u) ^ (((uint32_t)r & 7u) * 16u));
            CP_ASYNC16(dst, (const char*)(iH + gidx) + j * 16, sz);
            CP_ASYNC16(dst + AHALF, (const char*)(iL + gidx) + j * 16, sz);
        }
    };
    auto stageB = [&](int t2) {
        const char* bsrc = Bbase + (size_t)t2 * 16384;
        uint32_t bB = base + ABUF + (uint32_t)(t2 & 1) * 16384u;
        #pragma unroll
        for (int kk = 0; kk < 4; kk++)
            CP_ASYNC16(bB + (uint32_t)tid * 16u + (uint32_t)kk * 4096u,
                       bsrc + tid * 16 + kk * 4096, 16);
    };

    stageA(0);
    stageB(0);
    CP_COMMIT();

    int mbase = (w & 3) * 32;
    int nbase = (w >> 2) * 32;

    float acc[2][4][4];
    #pragma unroll
    for (int i = 0; i < 2; i++)
        #pragma unroll
        for (int j = 0; j < 4; j++)
            #pragma unroll
            for (int q = 0; q < 4; q++) acc[i][j][q] = 0.f;

    int lr = (lane & 7) + ((lane >> 3) & 1) * 8;
    int kq = (lane >> 4) * 16;

    #pragma unroll 1
    for (int tt = 0; tt < NT; tt++) {
        if (tt + 1 < NT && (tt + 1) % 3 != 0) {
            stageB(tt + 1);
            CP_COMMIT();
            CP_WAIT1();
        } else {
            CP_WAIT0();
        }
        __syncthreads();

        int s = tt / 3, kj = tt - s * 3;
        uint32_t Bt = base + ABUF + (uint32_t)(tt & 1) * 16384u;
        uint32_t rowA0 = (uint32_t)(kj * DIL + mbase + lr);
        uint32_t rowB0 = (uint32_t)(nbase + lr);

        #pragma unroll
        for (int ks = 0; ks < 4; ks++) {
            uint32_t kb = (uint32_t)(ks * 32 + kq);
            uint32_t ah0[4], ah1[4], al0[4], al1[4];
            uint32_t bh0[4], bh1[4], bl0[4], bl1[4];
            {
                uint32_t r0 = rowA0, r1 = rowA0 + 16u;
                uint32_t o0 = r0*128u + (kb ^ ((r0 & 7u)*16u));
                uint32_t o1 = r1*128u + (kb ^ ((r1 & 7u)*16u));
                LDSM_X4(ah0[0], ah0[1], ah0[2], ah0[3], base + o0);
                LDSM_X4(ah1[0], ah1[1], ah1[2], ah1[3], base + o1);
                LDSM_X4(al0[0], al0[1], al0[2], al0[3], base + AHALF + o0);
                LDSM_X4(al1[0], al1[1], al1[2], al1[3], base + AHALF + o1);
            }
            {
                uint32_t r0 = rowB0, r1 = rowB0 + 16u;
                uint32_t o0 = r0*128u + (kb ^ ((r0 & 7u)*16u));
                uint32_t o1 = r1*128u + (kb ^ ((r1 & 7u)*16u));
                LDSM_X4(bh0[0], bh0[1], bh0[2], bh0[3], Bt + o0);
                LDSM_X4(bh1[0], bh1[1], bh1[2], bh1[3], Bt + o1);
                LDSM_X4(bl0[0], bl0[1], bl0[2], bl0[3], Bt + 8192u + o0);
                LDSM_X4(bl1[0], bl1[1], bl1[2], bl1[3], Bt + 8192u + o1);
            }
            MMA_BF16(acc[0][0], ah0, bh0[0], bh0[2]);
            MMA_BF16(acc[0][1], ah0, bh0[1], bh0[3]);
            MMA_BF16(acc[0][2], ah0, bh1[0], bh1[2]);
            MMA_BF16(acc[0][3], ah0, bh1[1], bh1[3]);
            MMA_BF16(acc[1][0], ah1, bh0[0], bh0[2]);
            MMA_BF16(acc[1][1], ah1, bh0[1], bh0[3]);
            MMA_BF16(acc[1][2], ah1, bh1[0], bh1[2]);
            MMA_BF16(acc[1][3], ah1, bh1[1], bh1[3]);
            MMA_BF16(acc[0][0], ah0, bl0[0], bl0[2]);
            MMA_BF16(acc[0][1], ah0, bl0[1], bl0[3]);
            MMA_BF16(acc[0][2], ah0, bl1[0], bl1[2]);
            MMA_BF16(acc[0][3], ah0, bl1[1], bl1[3]);
            MMA_BF16(acc[1][0], ah1, bl0[0], bl0[2]);
            MMA_BF16(acc[1][1], ah1, bl0[1], bl0[3]);
            MMA_BF16(acc[1][2], ah1, bl1[0], bl1[2]);
            MMA_BF16(acc[1][3], ah1, bl1[1], bl1[3]);
            MMA_BF16(acc[0][0], al0, bh0[0], bh0[2]);
            MMA_BF16(acc[0][1], al0, bh0[1], bh0[3]);
            MMA_BF16(acc[0][2], al0, bh1[0], bh1[2]);
            MMA_BF16(acc[0][3], al0, bh1[1], bh1[3]);
            MMA_BF16(acc[1][0], al1, bh0[0], bh0[2]);
            MMA_BF16(acc[1][1], al1, bh0[1], bh0[3]);
            MMA_BF16(acc[1][2], al1, bh1[0], bh1[2]);
            MMA_BF16(acc[1][3], al1, bh1[1], bh1[3]);
        }
        __syncthreads();

        if (tt + 1 < NT && (tt + 1) % 3 == 0) {
            stageA((tt + 1) / 3);
            stageB(tt + 1);
            CP_COMMIT();
        }
    }

    // ---- epilogue ----
    float bs2[4][2];
    #pragma unroll
    for (int nb = 0; nb < 4; nb++) {
        int co = chunk * 64 + nbase + nb * 8 + (lane & 3) * 2;
        bs2[nb][0] = (HASBIAS && co     < coutTot) ? bias[co]     : 0.f;
        bs2[nb][1] = (HASBIAS && co + 1 < coutTot) ? bias[co + 1] : 0.f;
    }
    #pragma unroll
    for (int mt = 0; mt < 2; mt++) {
        #pragma unroll
        for (int rh = 0; rh < 2; rh++) {
            int px = x0 + mbase + mt * 16 + (lane >> 2) + rh * 8;
            size_t P = ((size_t)b * HH + y) * WW + px;
            #pragma unroll
            for (int nb = 0; nb < 4; nb++) {
                int cl = nbase + nb * 8 + (lane & 3) * 2;
                float v0 = acc[mt][nb][rh * 2 + 0] + bs2[nb][0];
                float v1 = acc[mt][nb][rh * 2 + 1] + bs2[nb][1];
                size_t ob = P * 64 + cl;

                if (EPI == 1) {
                    v0 = (v0 > 0.f) ? v0 : 0.1f * v0;
                    v1 = (v1 > 0.f) ? v1 : 0.1f * v1;
                    *(float2*)(outF + ob) = make_float2(v0, v1);
                    __nv_bfloat162 h2 = __floats2bfloat162_rn(v0, v1);
                    float2 hf = __bfloat1622float2(h2);
                    __nv_bfloat162 l2 = __floats2bfloat162_rn(v0 - hf.x, v1 - hf.y);
                    *(uint32_t*)(outH + ob) = *(uint32_t*)&h2;
                    *(uint32_t*)(outL + ob) = *(uint32_t*)&l2;
                } else if (EPI == 2) {
                    v0 = fmaxf(v0, 0.f); v1 = fmaxf(v1, 0.f);
                    __nv_bfloat162 h2 = __floats2bfloat162_rn(v0, v1);
                    float2 hf = __bfloat1622float2(h2);
                    __nv_bfloat162 l2 = __floats2bfloat162_rn(v0 - hf.x, v1 - hf.y);
                    *(uint32_t*)(outH + ob) = *(uint32_t*)&h2;
                    *(uint32_t*)(outL + ob) = *(uint32_t*)&l2;
                } else if (EPI == 3) {
                    float2 rv = *(const float2*)(resF + ob);
                    v0 = rv.x + fmaxf(v0, 0.f);
                    v1 = rv.y + fmaxf(v1, 0.f);
                    *(float2*)(outF + ob) = make_float2(v0, v1);
                } else if (EPI == 4) {
                    float2 rv = *(const float2*)(outF + ob);
                    v0 = rv.x + 0.1f * fmaxf(v0, 0.f);
                    v1 = rv.y + 0.1f * fmaxf(v1, 0.f);
                    *(float2*)(outF + ob) = make_float2(v0, v1);
                } else if (EPI == 5) {
                    float2 rv = *(const float2*)(resF + ob);
                    v0 = rv.x + 0.1f * fmaxf(v0, 0.f);
                    v1 = rv.y + 0.1f * fmaxf(v1, 0.f);
                    __nv_bfloat162 h2 = __floats2bfloat162_rn(v0, v1);
                    float2 hf = __bfloat1622float2(h2);
                    __nv_bfloat162 l2 = __floats2bfloat162_rn(v0 - hf.x, v1 - hf.y);
                    *(uint32_t*)(outH + ob) = *(uint32_t*)&h2;
                    *(uint32_t*)(outL + ob) = *(uint32_t*)&l2;
                } else if (EPI == 6) {
                    int co = chunk * 64 + cl;
                    size_t pix = ((size_t)y << 8) + px;
                    if (co < coutTot)
                        outNCHW[(((size_t)b * coutTot + co) << 16) + pix] = v0;
                    if (co + 1 < coutTot)
                        outNCHW[(((size_t)b * coutTot + co + 1) << 16) + pix] = v1;
                }
            }
        }
    }
}

// ---------------------------------------------------------------------------
// Modulated deformable conv, tensorized; NHWC fp32 gathers + fast
// transcendentals (EX2-based tanh/sigmoid); 3 CTAs/SM.
// ---------------------------------------------------------------------------
__global__ void __launch_bounds__(256, 3)
dcn_mma_kernel(const float* __restrict__ suppN, const float* __restrict__ off,
               const float* __restrict__ flow, const __nv_bfloat16* __restrict__ Bimg,
               const float* __restrict__ bias, float* __restrict__ out)
{
    extern __shared__ char smem[];
    uint32_t base = (smem_u32(smem) + 1023u) & ~1023u;
    const uint32_t SM_S = base;            // 32KB: hi 16K | lo 16K
    const uint32_t SM_Bd = base + 32768u;  // 2 x 16KB B double buffer

    int tid = threadIdx.x;
    int lane = tid & 31, w = tid >> 5;
    int b = blockIdx.z, y = blockIdx.y, x0 = blockIdx.x * 128;

    #pragma unroll
    for (int kk = 0; kk < 4; kk++)
        CP_ASYNC16(SM_Bd + (uint32_t)tid * 16u + (uint32_t)kk * 4096u,
                   (const char*)Bimg + tid * 16 + kk * 4096, 16);
    CP_COMMIT();

    int mbase = (w & 3) * 32;
    int nbase = (w >> 2) * 32;
    float acc[2][4][4];
    #pragma unroll
    for (int i = 0; i < 2; i++)
        #pragma unroll
        for (int j = 0; j < 4; j++)
            #pragma unroll
            for (int q = 0; q < 4; q++) acc[i][j][q] = 0.f;

    int lr = (lane & 7) + ((lane >> 3) & 1) * 8;
    int kq = (lane >> 4) * 16;

    const float* fxp  = flow + ((size_t)b*2 + 0)*HWSZ + y*WW + x0;
    const float* fyp  = flow + ((size_t)b*2 + 1)*HWSZ + y*WW + x0;
    const float* offb = off  + (size_t)b*216*HWSZ + y*WW + x0;
    const float* sb   = suppN + (size_t)b*HWSZ*64;

    #pragma unroll 1
    for (int k = 0; k < 9; k++) {
        if (k < 8) {
            const char* bsrc = (const char*)Bimg + (size_t)(k + 1) * 16384;
            uint32_t bB = SM_Bd + (uint32_t)((k + 1) & 1) * 16384u;
            #pragma unroll
            for (int kk = 0; kk < 4; kk++)
                CP_ASYNC16(bB + (uint32_t)tid * 16u + (uint32_t)kk * 4096u,
                           bsrc + tid * 16 + kk * 4096, 16);
            CP_COMMIT();
        }

        int ki = k / 3, kj = k - ki * 3;
        #pragma unroll 1
        for (int it = 0; it < 4; it++) {
            int task = tid + it * 256;
            int px = task & 127;
            int g  = task >> 7;
            int cdy = g*18 + k*2;
            float rawdy = offb[(size_t)cdy          *HWSZ + px];
            float rawdx = offb[(size_t)(cdy + 1)    *HWSZ + px];
            float rawm  = offb[(size_t)(144 + g*9+k)*HWSZ + px];
            float fx = fxp[px], fy = fyp[px];
            float ady = 25.f * fast_tanh(rawdy) + ((cdy     < 72) ? fx : fy);
            float adx = 25.f * fast_tanh(rawdx) + ((cdy + 1 < 72) ? fx : fy);
            float m   = fast_sigmoid(rawm);
            float sy = (float)y         + (float)(ki - 1) + ady;
            float sx = (float)(x0 + px) + (float)(kj - 1) + adx;
            float y0f = floorf(sy), x0f = floorf(sx);
            int iy0 = (int)y0f, ix0 = (int)x0f;
            int iy1 = iy0 + 1,  ix1 = ix0 + 1;
            float wy = sy - y0f, wx = sx - x0f;
            bool vy0 = ((unsigned)iy0 < HH), vy1 = ((unsigned)iy1 < HH);
            bool vx0 = ((unsigned)ix0 < WW), vx1 = ((unsigned)ix1 < WW);
            float w00 = (1.f - wy)*(1.f - wx) * ((vy0 && vx0) ? 1.f : 0.f) * m;
            float w01 = (1.f - wy)*wx         * ((vy0 && vx1) ? 1.f : 0.f) * m;
            float w10 = wy*(1.f - wx)         * ((vy1 && vx0) ? 1.f : 0.f) * m;
            float w11 = wy*wx                 * ((vy1 && vx1) ? 1.f : 0.f) * m;
            int cy0 = min(max(iy0, 0), HH-1), cy1 = min(max(iy1, 0), HH-1);
            int cx0 = min(max(ix0, 0), WW-1), cx1 = min(max(ix1, 0), WW-1);
            const float4* p00 = (const float4*)(sb + (size_t)(cy0*WW + cx0)*64 + g*8);
            const float4* p01 = (const float4*)(sb + (size_t)(cy0*WW + cx1)*64 + g*8);
            const float4* p10 = (const float4*)(sb + (size_t)(cy1*WW + cx0)*64 + g*8);
            const float4* p11 = (const float4*)(sb + (size_t)(cy1*WW + cx1)*64 + g*8);
            float v[8];
            #pragma unroll
            for (int h = 0; h < 2; h++) {
                float4 a = p00[h], bb = p01[h], cc = p10[h], dd = p11[h];
                v[h*4+0] = w00*a.x + w01*bb.x + w10*cc.x + w11*dd.x;
                v[h*4+1] = w00*a.y + w01*bb.y + w10*cc.y + w11*dd.y;
                v[h*4+2] = w00*a.z + w01*bb.z + w10*cc.z + w11*dd.z;
                v[h*4+3] = w00*a.w + w01*bb.w + w10*cc.w + w11*dd.w;
            }
            uint32_t hpk[4], lpk[4];
            #pragma unroll
            for (int q = 0; q < 4; q++) {
                __nv_bfloat162 h2 = __floats2bfloat162_rn(v[q*2], v[q*2+1]);
                float2 hf = __bfloat1622float2(h2);
                __nv_bfloat162 l2 = __floats2bfloat162_rn(v[q*2] - hf.x, v[q*2+1] - hf.y);
                hpk[q] = *(uint32_t*)&h2;
                lpk[q] = *(uint32_t*)&l2;
            }
            uint32_t so = (uint32_t)px * 128u +
                          (((uint32_t)g * 16u) ^ (((uint32_t)px & 7u) * 16u));
            asm volatile("st.shared.v4.b32 [%0], {%1,%2,%3,%4};"
                :: "r"(SM_S + so), "r"(hpk[0]), "r"(hpk[1]), "r"(hpk[2]), "r"(hpk[3]) : "memory");
            asm volatile("st.shared.v4.b32 [%0], {%1,%2,%3,%4};"
                :: "r"(SM_S + 16384u + so), "r"(lpk[0]), "r"(lpk[1]), "r"(lpk[2]), "r"(lpk[3]) : "memory");
        }

        if (k < 8) CP_WAIT1(); else CP_WAIT0();
        __syncthreads();

        uint32_t Bt = SM_Bd + (uint32_t)(k & 1) * 16384u;
        uint32_t rowA0 = (uint32_t)(mbase + lr);
        uint32_t rowB0 = (uint32_t)(nbase + lr);
        #pragma unroll
        for (int ks = 0; ks < 4; ks++) {
            uint32_t kb = (uint32_t)(ks * 32 + kq);
            uint32_t ah0[4], ah1[4], al0[4], al1[4];
            uint32_t bh0[4], bh1[4], bl0[4], bl1[4];
            {
                uint32_t r0 = rowA0, r1 = rowA0 + 16u;
                uint32_t o0 = r0*128u + (kb ^ ((r0 & 7u)*16u));
                uint32_t o1 = r1*128u + (kb ^ ((r1 & 7u)*16u));
                LDSM_X4(ah0[0], ah0[1], ah0[2], ah0[3], SM_S + o0);
                LDSM_X4(ah1[0], ah1[1], ah1[2], ah1[3], SM_S + o1);
                LDSM_X4(al0[0], al0[1], al0[2], al0[3], SM_S + 16384u + o0);
                LDSM_X4(al1[0], al1[1], al1[2], al1[3], SM_S + 16384u + o1);
            }
            {
                uint32_t r0 = rowB0, r1 = rowB0 + 16u;
                uint32_t o0 = r0*128u + (kb ^ ((r0 & 7u)*16u));
                uint32_t o1 = r1*128u + (kb ^ ((r1 & 7u)*16u));
                LDSM_X4(bh0[0], bh0[1], bh0[2], bh0[3], Bt + o0);
                LDSM_X4(bh1[0], bh1[1], bh1[2], bh1[3], Bt + o1);
                LDSM_X4(bl0[0], bl0[1], bl0[2], bl0[3], Bt + 8192u + o0);
                LDSM_X4(bl1[0], bl1[1], bl1[2], bl1[3], Bt + 8192u + o1);
            }
            MMA_BF16(acc[0][0], ah0, bh0[0], bh0[2]);
            MMA_BF16(acc[0][1], ah0, bh0[1], bh0[3]);
            MMA_BF16(acc[0][2], ah0, bh1[0], bh1[2]);
            MMA_BF16(acc[0][3], ah0, bh1[1], bh1[3]);
            MMA_BF16(acc[1][0], ah1, bh0[0], bh0[2]);
            MMA_BF16(acc[1][1], ah1, bh0[1], bh0[3]);
            MMA_BF16(acc[1][2], ah1, bh1[0], bh1[2]);
            MMA_BF16(acc[1][3], ah1, bh1[1], bh1[3]);
            MMA_BF16(acc[0][0], ah0, bl0[0], bl0[2]);
            MMA_BF16(acc[0][1], ah0, bl0[1], bl0[3]);
            MMA_BF16(acc[0][2], ah0, bl1[0], bl1[2]);
            MMA_BF16(acc[0][3], ah0, bl1[1], bl1[3]);
            MMA_BF16(acc[1][0], ah1, bl0[0], bl0[2]);
            MMA_BF16(acc[1][1], ah1, bl0[1], bl0[3]);
            MMA_BF16(acc[1][2], ah1, bl1[0], bl1[2]);
            MMA_BF16(acc[1][3], ah1, bl1[1], bl1[3]);
            MMA_BF16(acc[0][0], al0, bh0[0], bh0[2]);
            MMA_BF16(acc[0][1], al0, bh0[1], bh0[3]);
            MMA_BF16(acc[0][2], al0, bh1[0], bh1[2]);
            MMA_BF16(acc[0][3], al0, bh1[1], bh1[3]);
            MMA_BF16(acc[1][0], al1, bh0[0], bh0[2]);
            MMA_BF16(acc[1][1], al1, bh0[1], bh0[3]);
            MMA_BF16(acc[1][2], al1, bh1[0], bh1[2]);
            MMA_BF16(acc[1][3], al1, bh1[1], bh1[3]);
        }
        __syncthreads();
    }

    // ---- epilogue: bias + NCHW fp32 store ----
    float bs2[4][2];
    #pragma unroll
    for (int nb = 0; nb < 4; nb++) {
        int co = nbase + nb * 8 + (lane & 3) * 2;
        bs2[nb][0] = bias[co];
        bs2[nb][1] = bias[co + 1];
    }
    #pragma unroll
    for (int mt = 0; mt < 2; mt++) {
        #pragma unroll
        for (int rh = 0; rh < 2; rh++) {
            int px = x0 + mbase + mt * 16 + (lane >> 2) + rh * 8;
            size_t pix = ((size_t)y << 8) + px;
            #pragma unroll
            for (int nb = 0; nb < 4; nb++) {
                int co = nbase + nb * 8 + (lane & 3) * 2;
                out[(((size_t)b * 64 + co    ) << 16) + pix] = acc[mt][nb][rh*2+0] + bs2[nb][0];
                out[(((size_t)b * 64 + co + 1) << 16) + pix] = acc[mt][nb][rh*2+1] + bs2[nb][1];
            }
        }
    }
}

// ---------------------------------------------------------------------------
// Launch
// ---------------------------------------------------------------------------
extern "C" void kernel_launch(void* const* d_in, const int* in_sizes, int n_in,
                              void* d_out, int out_size)
{
    const float* ref   = (const float*)d_in[0];
    const float* supp  = (const float*)d_in[1];
    const float* flow  = (const float*)d_in[2];
    const float* fc_w  = (const float*)d_in[3];
    const float* fc_b  = (const float*)d_in[4];
    const float* cw[6], *cb[6];
    for (int i = 0; i < 6; i++) {
        cw[i] = (const float*)d_in[5 + 2*i];
        cb[i] = (const float*)d_in[6 + 2*i];
    }
    const float* off_w = (const float*)d_in[17];
    const float* off_b = (const float*)d_in[18];
    const float* dcn_w = (const float*)d_in[19];
    const float* dcn_b = (const float*)d_in[20];
    float* out = (float*)d_out;

    __nv_bfloat16 *wH, *wL, *rH, *rL, *t0H, *t0L, *tmpH, *tmpL, *ftH, *ftL, *Bg;
    float *f0F, *ffF, *offbuf, *suppN;
    cudaGetSymbolAddress((void**)&wH,  g_wH);   cudaGetSymbolAddress((void**)&wL,  g_wL);
    cudaGetSymbolAddress((void**)&rH,  g_rH);   cudaGetSymbolAddress((void**)&rL,  g_rL);
    cudaGetSymbolAddress((void**)&t0H, g_t0H);  cudaGetSymbolAddress((void**)&t0L, g_t0L);
    cudaGetSymbolAddress((void**)&tmpH,g_tmpH); cudaGetSymbolAddress((void**)&tmpL,g_tmpL);
    cudaGetSymbolAddress((void**)&ftH, g_ftH);  cudaGetSymbolAddress((void**)&ftL, g_ftL);
    cudaGetSymbolAddress((void**)&Bg,  g_B);
    cudaGetSymbolAddress((void**)&f0F,   g_f0F);
    cudaGetSymbolAddress((void**)&ffF,   g_ffF);
    cudaGetSymbolAddress((void**)&offbuf,g_off);
    cudaGetSymbolAddress((void**)&suppN, g_sN);

    // smem per DIL: pad + single A (2*(128+2d)*128) + 2x16KB B
    const int SMB1 = 1024 + 2*(130*128) + 32768;   // 67072
    const int SMB2 = 1024 + 2*(132*128) + 32768;   // 67584
    const int SMB4 = 1024 + 2*(136*128) + 32768;   // 68608
    const int SMD  = 1024 + 32768 + 32768;         // 66560
    cudaFuncSetAttribute((const void*)conv_mma_kernel<1,1,1,18>, cudaFuncAttributeMaxDynamicSharedMemorySize, SMB1);
    cudaFuncSetAttribute((const void*)conv_mma_kernel<1,2,1,9>,  cudaFuncAttributeMaxDynamicSharedMemorySize, SMB1);
    cudaFuncSetAttribute((const void*)conv_mma_kernel<1,3,1,9>,  cudaFuncAttributeMaxDynamicSharedMemorySize, SMB1);
    cudaFuncSetAttribute((const void*)conv_mma_kernel<2,2,1,9>,  cudaFuncAttributeMaxDynamicSharedMemorySize, SMB2);
    cudaFuncSetAttribute((const void*)conv_mma_kernel<2,4,1,9>,  cudaFuncAttributeMaxDynamicSharedMemorySize, SMB2);
    cudaFuncSetAttribute((const void*)conv_mma_kernel<4,5,1,9>,  cudaFuncAttributeMaxDynamicSharedMemorySize, SMB4);
    cudaFuncSetAttribute((const void*)conv_mma_kernel<1,6,1,9>,  cudaFuncAttributeMaxDynamicSharedMemorySize, SMB1);
    cudaFuncSetAttribute((const void*)dcn_mma_kernel, cudaFuncAttributeMaxDynamicSharedMemorySize, SMD);

    // Fused weight prep (13 sets, one launch)
    PrepTable tab;
    tab.d[0]  = {fc_w, 128, 0,  64, 0};
    tab.d[1]  = {fc_w, 128, 64, 64, 0};
    for (int i = 0; i < 6; i++) tab.d[2+i] = {cw[i], 64, 0, 64, 0};
    for (int ch = 0; ch < 4; ch++) tab.d[8+ch] = {off_w, 64, 0, 216, ch*64};
    tab.d[12] = {dcn_w, 64, 0, 64, 0};
    prep_all_kernel<<<dim3(144, 13), 256>>>(tab, Bg);

    // supp NCHW -> NHWC fp32 (feeds warp + dcn gathers)
    supp_nhwc_kernel<<<dim3(HWSZ/64, BB), 256>>>(supp, suppN);
    // flow warp (reads NHWC supp)
    warp_nhwc_kernel<<<dim3(HWSZ/256, BB), 256>>>(suppN, flow, wH, wL);
    to_nhwc_kernel<<<dim3(HWSZ/256, BB), 256>>>(ref, rH, rL);

    dim3 cg(2, 256, 4);
    // fc (fused 18-tap): lrelu -> feat0 (f32 + hi/lo)
    conv_mma_kernel<1,1,1,18><<<cg, 256, SMB1>>>(wH, wL, rH, rL, Bg + 0*BSET, fc_b, 1, 64,
                                                 f0F, t0H, t0L, nullptr, nullptr);
    // c1: relu -> tmp
    conv_mma_kernel<1,2,1,9><<<cg, 256, SMB1>>>(t0H, t0L, nullptr, nullptr, Bg + 2*BSET, cb[0], 1, 64,
                                                nullptr, tmpH, tmpL, nullptr, nullptr);
    // c2: ff = feat0 + relu(v)
    conv_mma_kernel<1,3,1,9><<<cg, 256, SMB1>>>(tmpH, tmpL, nullptr, nullptr, Bg + 3*BSET, cb[1], 1, 64,
                                                ffF, nullptr, nullptr, f0F, nullptr);
    // c3 (dil2): relu -> tmp
    conv_mma_kernel<2,2,1,9><<<cg, 256, SMB2>>>(t0H, t0L, nullptr, nullptr, Bg + 4*BSET, cb[2], 1, 64,
                                                nullptr, tmpH, tmpL, nullptr, nullptr);
    // c4 (dil2): ff += 0.1*relu(v)
    conv_mma_kernel<2,4,1,9><<<cg, 256, SMB2>>>(tmpH, tmpL, nullptr, nullptr, Bg + 5*BSET, cb[3], 1, 64,
                                                ffF, nullptr, nullptr, nullptr, nullptr);
    // c5 (dil2): relu -> tmp
    conv_mma_kernel<2,2,1,9><<<cg, 256, SMB2>>>(t0H, t0L, nullptr, nullptr, Bg + 6*BSET, cb[4], 1, 64,
                                                nullptr, tmpH, tmpL, nullptr, nullptr);
    // c6 (dil4): feat = ff + 0.1*relu(v) -> hi/lo
    conv_mma_kernel<4,5,1,9><<<cg, 256, SMB4>>>(tmpH, tmpL, nullptr, nullptr, Bg + 7*BSET, cb[5], 1, 64,
                                                nullptr, ftH, ftL, ffF, nullptr);
    // offset conv: 216 couts, 4 chunks, NCHW out
    dim3 og(2, 256, 16);
    conv_mma_kernel<1,6,1,9><<<og, 256, SMB1>>>(ftH, ftL, nullptr, nullptr, Bg + 8*BSET, off_b, 4, 216,
                                                nullptr, nullptr, nullptr, nullptr, offbuf);
    // tensorized deformable conv (fast transcendentals, 3 CTAs/SM)
    dcn_mma_kernel<<<cg, 256, SMD>>>(suppN, offbuf, flow, Bg + 12*BSET, dcn_b, out);
}

// round 13
// speedup vs baseline: 1.1505x; 1.1505x over previous
#include <cuda_runtime.h>
#include <cuda_bf16.h>
#include <math.h>
#include <stdint.h>

#define BB 4
#define HH 256
#define WW 256
#define HWSZ 65536
#define NPX (BB*HWSZ)

// ---------------------------------------------------------------------------
// PTX helpers (plain sm_103-safe: ldmatrix + mma.sync + cp.async)
// ---------------------------------------------------------------------------
__device__ __forceinline__ uint32_t smem_u32(const void* p) {
    uint32_t a;
    asm("{ .reg .u64 t; cvta.to.shared.u64 t, %1; cvt.u32.u64 %0, t; }" : "=r"(a) : "l"(p));
    return a;
}

#define LDSM_X4(r0, r1, r2, r3, addr) \
    asm volatile("ldmatrix.sync.aligned.m8n8.x4.shared.b16 {%0,%1,%2,%3}, [%4];" \
        : "=r"(r0), "=r"(r1), "=r"(r2), "=r"(r3) : "r"(addr))

#define MMA_BF16(d, a, b0v, b1v) \
    asm volatile("mma.sync.aligned.m16n8k16.row.col.f32.bf16.bf16.f32 " \
        "{%0,%1,%2,%3},{%4,%5,%6,%7},{%8,%9},{%0,%1,%2,%3};" \
        : "+f"((d)[0]), "+f"((d)[1]), "+f"((d)[2]), "+f"((d)[3]) \
        : "r"((a)[0]), "r"((a)[1]), "r"((a)[2]), "r"((a)[3]), "r"(b0v), "r"(b1v))

#define CP_ASYNC16(dst, src, sz) \
    asm volatile("cp.async.cg.shared.global [%0], [%1], 16, %2;" \
        :: "r"(dst), "l"(src), "r"(sz) : "memory")
#define CP_COMMIT() asm volatile("cp.async.commit_group;" ::: "memory")
#define CP_WAIT1() asm volatile("cp.async.wait_group 1;" ::: "memory")
#define CP_WAIT0() asm volatile("cp.async.wait_group 0;" ::: "memory")

// Fast transcendentals for DCN offsets. Clamp keeps exp finite; tanh(15)==1 in fp32.
__device__ __forceinline__ float fast_tanh(float x) {
    float xc = fminf(fmaxf(x, -15.f), 15.f);
    float e2 = __expf(2.f * xc);
    return __fdividef(e2 - 1.f, e2 + 1.f);
}
__device__ __forceinline__ float fast_sigmoid(float x) {
    return __fdividef(1.f, 1.f + __expf(-x));
}

// ---------------------------------------------------------------------------
// Device global scratch
// ---------------------------------------------------------------------------
#define FEAT_ELEMS ((size_t)NPX*64)
__device__ __nv_bfloat16 g_wH[FEAT_ELEMS], g_wL[FEAT_ELEMS];     // warped supp
__device__ __nv_bfloat16 g_rH[FEAT_ELEMS], g_rL[FEAT_ELEMS];     // ref
__device__ __nv_bfloat16 g_t0H[FEAT_ELEMS], g_t0L[FEAT_ELEMS];   // feat0
__device__ __nv_bfloat16 g_tmpH[FEAT_ELEMS], g_tmpL[FEAT_ELEMS];
__device__ __nv_bfloat16 g_ftH[FEAT_ELEMS], g_ftL[FEAT_ELEMS];   // final feat
__device__ float g_f0F[FEAT_ELEMS];                               // feat0 fp32
__device__ float g_ffF[FEAT_ELEMS];                               // feat fp32 accum
__device__ float g_off[(size_t)BB*216*HWSZ];                      // NCHW
__device__ float g_sN[FEAT_ELEMS];                                // supp NHWC fp32
// 13 B-sets (fc0, fc1, c1..c6, off chunks 0..3, dcn); each 9 taps x 16KB
#define BSET 73728
__device__ __nv_bfloat16 g_B[13*BSET];

// ---------------------------------------------------------------------------
// Fused B prep: all 13 sets in one launch (blockIdx.y = set)
// ---------------------------------------------------------------------------
struct PrepDesc { const float* w; int cinTot, cin0, coutTot, cout0; };
struct PrepTable { PrepDesc d[13]; };

__global__ void prep_all_kernel(PrepTable tab, __nv_bfloat16* __restrict__ outB)
{
    int set = blockIdx.y;
    PrepDesc pd = tab.d[set];
    int idx = blockIdx.x * 256 + threadIdx.x;   // < 36864
    int c = idx & 63;
    int r = (idx >> 6) & 63;
    int t = idx >> 12;
    float v = 0.f;
    int co = pd.cout0 + r;
    if (co < pd.coutTot) v = pd.w[((size_t)co * pd.cinTot + pd.cin0 + c) * 9 + t];
    __nv_bfloat16 h = __float2bfloat16(v);
    __nv_bfloat16 l = __float2bfloat16(v - __bfloat162float(h));
    uint32_t off = (uint32_t)r * 128u + (uint32_t)c * 2u;
    uint32_t so = off ^ ((off >> 3) & 0x70u);
    char* ob = (char*)(outB + (size_t)set * BSET) + (size_t)t * 16384;
    *(__nv_bfloat16*)(ob + so) = h;
    *(__nv_bfloat16*)(ob + 8192 + so) = l;
}

// ---------------------------------------------------------------------------
// supp NCHW fp32 -> NHWC fp32 (smem-tiled transpose, 64px x 64ch per block)
// ---------------------------------------------------------------------------
__global__ void supp_nhwc_kernel(const float* __restrict__ src, float* __restrict__ dst)
{
    __shared__ float s[64 * 65];
    int b  = blockIdx.y;
    int x0 = blockIdx.x * 64;     // linear pixel base
    int tid = threadIdx.x;
    int lc = tid >> 6;            // 0..3
    int lp = tid & 63;
    #pragma unroll
    for (int i = 0; i < 16; i++) {
        int c = i * 4 + lc;
        s[lp * 65 + c] = src[((size_t)b * 64 + c) * HWSZ + x0 + lp];
    }
    __syncthreads();
    int px = tid >> 2, q4 = (tid & 3) * 16;
    float* dp = dst + ((size_t)b * HWSZ + x0 + px) * 64 + q4;
    const float* sp = s + px * 65 + q4;
    #pragma unroll
    for (int q = 0; q < 4; q++)
        ((float4*)dp)[q] = make_float4(sp[q*4], sp[q*4+1], sp[q*4+2], sp[q*4+3]);
}

// ---------------------------------------------------------------------------
// flow_warp (reads NHWC fp32 supp, vectorized corners) -> NHWC bf16 hi/lo
// ---------------------------------------------------------------------------
__global__ void warp_nhwc_kernel(const float* __restrict__ suppN, const float* __restrict__ flow,
                                 __nv_bfloat16* __restrict__ oH, __nv_bfloat16* __restrict__ oL)
{
    int p = blockIdx.x * 256 + threadIdx.x;
    int b = blockIdx.y;
    int y = p >> 8, x = p & 255;
    float fx = flow[((size_t)b*2    )*HWSZ + p];
    float fy = flow[((size_t)b*2 + 1)*HWSZ + p];
    float sy = (float)y + fy, sx = (float)x + fx;
    float y0f = floorf(sy), x0f = floorf(sx);
    int iy0 = (int)y0f, ix0 = (int)x0f, iy1 = iy0+1, ix1 = ix0+1;
    float wy = sy - y0f, wx = sx - x0f;
    bool vy0 = ((unsigned)iy0 < HH), vy1 = ((unsigned)iy1 < HH);
    bool vx0 = ((unsigned)ix0 < WW), vx1 = ((unsigned)ix1 < WW);
    float w00 = (1.f-wy)*(1.f-wx) * ((vy0&&vx0)?1.f:0.f);
    float w01 = (1.f-wy)*wx       * ((vy0&&vx1)?1.f:0.f);
    float w10 = wy*(1.f-wx)       * ((vy1&&vx0)?1.f:0.f);
    float w11 = wy*wx             * ((vy1&&vx1)?1.f:0.f);
    int cy0 = min(max(iy0,0),HH-1), cy1 = min(max(iy1,0),HH-1);
    int cx0 = min(max(ix0,0),WW-1), cx1 = min(max(ix1,0),WW-1);
    size_t i00 = (size_t)(cy0*WW+cx0)*64, i01 = (size_t)(cy0*WW+cx1)*64;
    size_t i10 = (size_t)(cy1*WW+cx0)*64, i11 = (size_t)(cy1*WW+cx1)*64;
    const float* sb = suppN + (size_t)b*HWSZ*64;
    __nv_bfloat16* ohp = oH + ((size_t)b*HWSZ + p)*64;
    __nv_bfloat16* olp = oL + ((size_t)b*HWSZ + p)*64;
    #pragma unroll 1
    for (int g = 0; g < 8; g++) {
        const float4* p00 = (const float4*)(sb + i00 + g*8);
        const float4* p01 = (const float4*)(sb + i01 + g*8);
        const float4* p10 = (const float4*)(sb + i10 + g*8);
        const float4* p11 = (const float4*)(sb + i11 + g*8);
        float v[8];
        #pragma unroll
        for (int h = 0; h < 2; h++) {
            float4 a = p00[h], bb = p01[h], cc = p10[h], dd = p11[h];
            v[h*4+0] = w00*a.x + w01*bb.x + w10*cc.x + w11*dd.x;
            v[h*4+1] = w00*a.y + w01*bb.y + w10*cc.y + w11*dd.y;
            v[h*4+2] = w00*a.z + w01*bb.z + w10*cc.z + w11*dd.z;
            v[h*4+3] = w00*a.w + w01*bb.w + w10*cc.w + w11*dd.w;
        }
        uint4 uh, ul;
        uint32_t* ph = (uint32_t*)&uh;
        uint32_t* pl = (uint32_t*)&ul;
        #pragma unroll
        for (int q = 0; q < 4; q++) {
            __nv_bfloat162 h2 = __floats2bfloat162_rn(v[q*2], v[q*2+1]);
            float2 hf = __bfloat1622float2(h2);
            __nv_bfloat162 l2 = __floats2bfloat162_rn(v[q*2] - hf.x, v[q*2+1] - hf.y);
            ph[q] = *(uint32_t*)&h2;
            pl[q] = *(uint32_t*)&l2;
        }
        ((uint4*)ohp)[g] = uh;
        ((uint4*)olp)[g] = ul;
    }
}

// NCHW fp32 -> NHWC bf16 hi/lo (ref)
__global__ void to_nhwc_kernel(const float* __restrict__ src,
                               __nv_bfloat16* __restrict__ oH, __nv_bfloat16* __restrict__ oL)
{
    int p = blockIdx.x * 256 + threadIdx.x;
    int b = blockIdx.y;
    const float* sp = src + (size_t)b*64*HWSZ + p;
    __nv_bfloat16* ohp = oH + ((size_t)b*HWSZ + p)*64;
    __nv_bfloat16* olp = oL + ((size_t)b*HWSZ + p)*64;
    for (int g = 0; g < 8; g++) {
        uint4 uh, ul;
        uint32_t* ph = (uint32_t*)&uh;
        uint32_t* pl = (uint32_t*)&ul;
        #pragma unroll
        for (int q = 0; q < 4; q++) {
            float v0 = sp[(size_t)(g*8 + q*2    )*HWSZ];
            float v1 = sp[(size_t)(g*8 + q*2 + 1)*HWSZ];
            __nv_bfloat162 h2 = __floats2bfloat162_rn(v0, v1);
            float2 hf = __bfloat1622float2(h2);
            __nv_bfloat162 l2 = __floats2bfloat162_rn(v0 - hf.x, v1 - hf.y);
            ph[q] = *(uint32_t*)&h2;
            pl[q] = *(uint32_t*)&l2;
        }
        ((uint4*)ohp)[g] = uh;
        ((uint4*)olp)[g] = ul;
    }
}

// ---------------------------------------------------------------------------
// mma.sync conv (unchanged, passing): single A buffer per ki group,
// double-buffered B, 3 CTAs/SM; group-accounting invariant in the wait logic.
// ---------------------------------------------------------------------------
template<int DIL, int EPI, int HASBIAS, int NT>
__global__ void __launch_bounds__(256, 3)
conv_mma_kernel(const __nv_bfloat16* __restrict__ inH,
                const __nv_bfloat16* __restrict__ inL,
                const __nv_bfloat16* __restrict__ inH2,
                const __nv_bfloat16* __restrict__ inL2,
                const __nv_bfloat16* __restrict__ Bimg,
                const float* __restrict__ bias,
                int nchunk, int coutTot,
                float* __restrict__ outF,
                __nv_bfloat16* __restrict__ outH,
                __nv_bfloat16* __restrict__ outL,
                const float* __restrict__ resF,
                float* __restrict__ outNCHW)
{
    constexpr uint32_t R = 128 + 2 * DIL;
    constexpr uint32_t AHALF = R * 128u;
    constexpr uint32_t ABUF = 2u * AHALF;

    extern __shared__ char smem[];
    uint32_t base = (smem_u32(smem) + 1023u) & ~1023u;

    int tid = threadIdx.x;
    int lane = tid & 31, w = tid >> 5;
    int z = blockIdx.z;
    int b = z / nchunk, chunk = z - b * nchunk;
    int y = blockIdx.y, x0 = blockIdx.x * 128;

    const char* Bbase = (const char*)Bimg + (size_t)chunk * 147456;

    auto stageA = [&](int s) {
        int ki = (NT == 18 && s >= 3) ? s - 3 : s;
        const __nv_bfloat16* iH = (NT == 18 && s >= 3) ? inH2 : inH;
        const __nv_bfloat16* iL = (NT == 18 && s >= 3) ? inL2 : inL;
        int gy = y + (ki - 1) * DIL;
        bool rowok = ((unsigned)gy < HH);
        for (int i = tid; i < (int)(R * 8); i += 256) {
            int r = i >> 3, j = i & 7;
            int gx = x0 - DIL + r;
            bool ok = rowok && ((unsigned)gx < WW);
            size_t gidx = ok ? ((((size_t)b * HH + gy) * WW + gx) * 64) : 0;
            int sz = ok ? 16 : 0;
            uint32_t dst = base + (uint32_t)r * 128u +
                           (((uint32_t)j * 16u) ^ (((uint32_t)r & 7u) * 16u));
            CP_ASYNC16(dst, (const char*)(iH + gidx) + j * 16, sz);
            CP_ASYNC16(dst + AHALF, (const char*)(iL + gidx) + j * 16, sz);
        }
    };
    auto stageB = [&](int t2) {
        const char* bsrc = Bbase + (size_t)t2 * 16384;
        uint32_t bB = base + ABUF + (uint32_t)(t2 & 1) * 16384u;
        #pragma unroll
        for (int kk = 0; kk < 4; kk++)
            CP_ASYNC16(bB + (uint32_t)tid * 16u + (uint32_t)kk * 4096u,
                       bsrc + tid * 16 + kk * 4096, 16);
    };

    stageA(0);
    stageB(0);
    CP_COMMIT();

    int mbase = (w & 3) * 32;
    int nbase = (w >> 2) * 32;

    float acc[2][4][4];
    #pragma unroll
    for (int i = 0; i < 2; i++)
        #pragma unroll
        for (int j = 0; j < 4; j++)
            #pragma unroll
            for (int q = 0; q < 4; q++) acc[i][j][q] = 0.f;

    int lr = (lane & 7) + ((lane >> 3) & 1) * 8;
    int kq = (lane >> 4) * 16;

    #pragma unroll 1
    for (int tt = 0; tt < NT; tt++) {
        if (tt + 1 < NT && (tt + 1) % 3 != 0) {
            stageB(tt + 1);
            CP_COMMIT();
            CP_WAIT1();
        } else {
            CP_WAIT0();
        }
        __syncthreads();

        int s = tt / 3, kj = tt - s * 3;
        uint32_t Bt = base + ABUF + (uint32_t)(tt & 1) * 16384u;
        uint32_t rowA0 = (uint32_t)(kj * DIL + mbase + lr);
        uint32_t rowB0 = (uint32_t)(nbase + lr);

        #pragma unroll
        for (int ks = 0; ks < 4; ks++) {
            uint32_t kb = (uint32_t)(ks * 32 + kq);
            uint32_t ah0[4], ah1[4], al0[4], al1[4];
            uint32_t bh0[4], bh1[4], bl0[4], bl1[4];
            {
                uint32_t r0 = rowA0, r1 = rowA0 + 16u;
                uint32_t o0 = r0*128u + (kb ^ ((r0 & 7u)*16u));
                uint32_t o1 = r1*128u + (kb ^ ((r1 & 7u)*16u));
                LDSM_X4(ah0[0], ah0[1], ah0[2], ah0[3], base + o0);
                LDSM_X4(ah1[0], ah1[1], ah1[2], ah1[3], base + o1);
                LDSM_X4(al0[0], al0[1], al0[2], al0[3], base + AHALF + o0);
                LDSM_X4(al1[0], al1[1], al1[2], al1[3], base + AHALF + o1);
            }
            {
                uint32_t r0 = rowB0, r1 = rowB0 + 16u;
                uint32_t o0 = r0*128u + (kb ^ ((r0 & 7u)*16u));
                uint32_t o1 = r1*128u + (kb ^ ((r1 & 7u)*16u));
                LDSM_X4(bh0[0], bh0[1], bh0[2], bh0[3], Bt + o0);
                LDSM_X4(bh1[0], bh1[1], bh1[2], bh1[3], Bt + o1);
                LDSM_X4(bl0[0], bl0[1], bl0[2], bl0[3], Bt + 8192u + o0);
                LDSM_X4(bl1[0], bl1[1], bl1[2], bl1[3], Bt + 8192u + o1);
            }
            MMA_BF16(acc[0][0], ah0, bh0[0], bh0[2]);
            MMA_BF16(acc[0][1], ah0, bh0[1], bh0[3]);
            MMA_BF16(acc[0][2], ah0, bh1[0], bh1[2]);
            MMA_BF16(acc[0][3], ah0, bh1[1], bh1[3]);
            MMA_BF16(acc[1][0], ah1, bh0[0], bh0[2]);
            MMA_BF16(acc[1][1], ah1, bh0[1], bh0[3]);
            MMA_BF16(acc[1][2], ah1, bh1[0], bh1[2]);
            MMA_BF16(acc[1][3], ah1, bh1[1], bh1[3]);
            MMA_BF16(acc[0][0], ah0, bl0[0], bl0[2]);
            MMA_BF16(acc[0][1], ah0, bl0[1], bl0[3]);
            MMA_BF16(acc[0][2], ah0, bl1[0], bl1[2]);
            MMA_BF16(acc[0][3], ah0, bl1[1], bl1[3]);
            MMA_BF16(acc[1][0], ah1, bl0[0], bl0[2]);
            MMA_BF16(acc[1][1], ah1, bl0[1], bl0[3]);
            MMA_BF16(acc[1][2], ah1, bl1[0], bl1[2]);
            MMA_BF16(acc[1][3], ah1, bl1[1], bl1[3]);
            MMA_BF16(acc[0][0], al0, bh0[0], bh0[2]);
            MMA_BF16(acc[0][1], al0, bh0[1], bh0[3]);
            MMA_BF16(acc[0][2], al0, bh1[0], bh1[2]);
            MMA_BF16(acc[0][3], al0, bh1[1], bh1[3]);
            MMA_BF16(acc[1][0], al1, bh0[0], bh0[2]);
            MMA_BF16(acc[1][1], al1, bh0[1], bh0[3]);
            MMA_BF16(acc[1][2], al1, bh1[0], bh1[2]);
            MMA_BF16(acc[1][3], al1, bh1[1], bh1[3]);
        }
        __syncthreads();

        if (tt + 1 < NT && (tt + 1) % 3 == 0) {
            stageA((tt + 1) / 3);
            stageB(tt + 1);
            CP_COMMIT();
        }
    }

    // ---- epilogue ----
    float bs2[4][2];
    #pragma unroll
    for (int nb = 0; nb < 4; nb++) {
        int co = chunk * 64 + nbase + nb * 8 + (lane & 3) * 2;
        bs2[nb][0] = (HASBIAS && co     < coutTot) ? bias[co]     : 0.f;
        bs2[nb][1] = (HASBIAS && co + 1 < coutTot) ? bias[co + 1] : 0.f;
    }
    #pragma unroll
    for (int mt = 0; mt < 2; mt++) {
        #pragma unroll
        for (int rh = 0; rh < 2; rh++) {
            int px = x0 + mbase + mt * 16 + (lane >> 2) + rh * 8;
            size_t P = ((size_t)b * HH + y) * WW + px;
            #pragma unroll
            for (int nb = 0; nb < 4; nb++) {
                int cl = nbase + nb * 8 + (lane & 3) * 2;
                float v0 = acc[mt][nb][rh * 2 + 0] + bs2[nb][0];
                float v1 = acc[mt][nb][rh * 2 + 1] + bs2[nb][1];
                size_t ob = P * 64 + cl;

                if (EPI == 1) {
                    v0 = (v0 > 0.f) ? v0 : 0.1f * v0;
                    v1 = (v1 > 0.f) ? v1 : 0.1f * v1;
                    *(float2*)(outF + ob) = make_float2(v0, v1);
                    __nv_bfloat162 h2 = __floats2bfloat162_rn(v0, v1);
                    float2 hf = __bfloat1622float2(h2);
                    __nv_bfloat162 l2 = __floats2bfloat162_rn(v0 - hf.x, v1 - hf.y);
                    *(uint32_t*)(outH + ob) = *(uint32_t*)&h2;
                    *(uint32_t*)(outL + ob) = *(uint32_t*)&l2;
                } else if (EPI == 2) {
                    v0 = fmaxf(v0, 0.f); v1 = fmaxf(v1, 0.f);
                    __nv_bfloat162 h2 = __floats2bfloat162_rn(v0, v1);
                    float2 hf = __bfloat1622float2(h2);
                    __nv_bfloat162 l2 = __floats2bfloat162_rn(v0 - hf.x, v1 - hf.y);
                    *(uint32_t*)(outH + ob) = *(uint32_t*)&h2;
                    *(uint32_t*)(outL + ob) = *(uint32_t*)&l2;
                } else if (EPI == 3) {
                    float2 rv = *(const float2*)(resF + ob);
                    v0 = rv.x + fmaxf(v0, 0.f);
                    v1 = rv.y + fmaxf(v1, 0.f);
                    *(float2*)(outF + ob) = make_float2(v0, v1);
                } else if (EPI == 4) {
                    float2 rv = *(const float2*)(outF + ob);
                    v0 = rv.x + 0.1f * fmaxf(v0, 0.f);
                    v1 = rv.y + 0.1f * fmaxf(v1, 0.f);
                    *(float2*)(outF + ob) = make_float2(v0, v1);
                } else if (EPI == 5) {
                    float2 rv = *(const float2*)(resF + ob);
                    v0 = rv.x + 0.1f * fmaxf(v0, 0.f);
                    v1 = rv.y + 0.1f * fmaxf(v1, 0.f);
                    __nv_bfloat162 h2 = __floats2bfloat162_rn(v0, v1);
                    float2 hf = __bfloat1622float2(h2);
                    __nv_bfloat162 l2 = __floats2bfloat162_rn(v0 - hf.x, v1 - hf.y);
                    *(uint32_t*)(outH + ob) = *(uint32_t*)&h2;
                    *(uint32_t*)(outL + ob) = *(uint32_t*)&l2;
                } else if (EPI == 6) {
                    int co = chunk * 64 + cl;
                    size_t pix = ((size_t)y << 8) + px;
                    if (co < coutTot)
                        outNCHW[(((size_t)b * coutTot + co) << 16) + pix] = v0;
                    if (co + 1 < coutTot)
                        outNCHW[(((size_t)b * coutTot + co + 1) << 16) + pix] = v1;
                }
            }
        }
    }
}

// ---------------------------------------------------------------------------
// Modulated deformable conv, tensorized; NHWC fp32 gathers + fast
// transcendentals; occupancy 2 (R12 showed occ-3 reg-caps spill the sampler).
// ---------------------------------------------------------------------------
__global__ void __launch_bounds__(256, 2)
dcn_mma_kernel(const float* __restrict__ suppN, const float* __restrict__ off,
               const float* __restrict__ flow, const __nv_bfloat16* __restrict__ Bimg,
               const float* __restrict__ bias, float* __restrict__ out)
{
    extern __shared__ char smem[];
    uint32_t base = (smem_u32(smem) + 1023u) & ~1023u;
    const uint32_t SM_S = base;            // 32KB: hi 16K | lo 16K
    const uint32_t SM_Bd = base + 32768u;  // 2 x 16KB B double buffer

    int tid = threadIdx.x;
    int lane = tid & 31, w = tid >> 5;
    int b = blockIdx.z, y = blockIdx.y, x0 = blockIdx.x * 128;

    #pragma unroll
    for (int kk = 0; kk < 4; kk++)
        CP_ASYNC16(SM_Bd + (uint32_t)tid * 16u + (uint32_t)kk * 4096u,
                   (const char*)Bimg + tid * 16 + kk * 4096, 16);
    CP_COMMIT();

    int mbase = (w & 3) * 32;
    int nbase = (w >> 2) * 32;
    float acc[2][4][4];
    #pragma unroll
    for (int i = 0; i < 2; i++)
        #pragma unroll
        for (int j = 0; j < 4; j++)
            #pragma unroll
            for (int q = 0; q < 4; q++) acc[i][j][q] = 0.f;

    int lr = (lane & 7) + ((lane >> 3) & 1) * 8;
    int kq = (lane >> 4) * 16;

    const float* fxp  = flow + ((size_t)b*2 + 0)*HWSZ + y*WW + x0;
    const float* fyp  = flow + ((size_t)b*2 + 1)*HWSZ + y*WW + x0;
    const float* offb = off  + (size_t)b*216*HWSZ + y*WW + x0;
    const float* sb   = suppN + (size_t)b*HWSZ*64;

    #pragma unroll 1
    for (int k = 0; k < 9; k++) {
        if (k < 8) {
            const char* bsrc = (const char*)Bimg + (size_t)(k + 1) * 16384;
            uint32_t bB = SM_Bd + (uint32_t)((k + 1) & 1) * 16384u;
            #pragma unroll
            for (int kk = 0; kk < 4; kk++)
                CP_ASYNC16(bB + (uint32_t)tid * 16u + (uint32_t)kk * 4096u,
                           bsrc + tid * 16 + kk * 4096, 16);
            CP_COMMIT();
        }

        int ki = k / 3, kj = k - ki * 3;
        #pragma unroll 1
        for (int it = 0; it < 4; it++) {
            int task = tid + it * 256;
            int px = task & 127;
            int g  = task >> 7;
            int cdy = g*18 + k*2;
            float rawdy = offb[(size_t)cdy          *HWSZ + px];
            float rawdx = offb[(size_t)(cdy + 1)    *HWSZ + px];
            float rawm  = offb[(size_t)(144 + g*9+k)*HWSZ + px];
            float fx = fxp[px], fy = fyp[px];
            float ady = 25.f * fast_tanh(rawdy) + ((cdy     < 72) ? fx : fy);
            float adx = 25.f * fast_tanh(rawdx) + ((cdy + 1 < 72) ? fx : fy);
            float m   = fast_sigmoid(rawm);
            float sy = (float)y         + (float)(ki - 1) + ady;
            float sx = (float)(x0 + px) + (float)(kj - 1) + adx;
            float y0f = floorf(sy), x0f = floorf(sx);
            int iy0 = (int)y0f, ix0 = (int)x0f;
            int iy1 = iy0 + 1,  ix1 = ix0 + 1;
            float wy = sy - y0f, wx = sx - x0f;
            bool vy0 = ((unsigned)iy0 < HH), vy1 = ((unsigned)iy1 < HH);
            bool vx0 = ((unsigned)ix0 < WW), vx1 = ((unsigned)ix1 < WW);
            float w00 = (1.f - wy)*(1.f - wx) * ((vy0 && vx0) ? 1.f : 0.f) * m;
            float w01 = (1.f - wy)*wx         * ((vy0 && vx1) ? 1.f : 0.f) * m;
            float w10 = wy*(1.f - wx)         * ((vy1 && vx0) ? 1.f : 0.f) * m;
            float w11 = wy*wx                 * ((vy1 && vx1) ? 1.f : 0.f) * m;
            int cy0 = min(max(iy0, 0), HH-1), cy1 = min(max(iy1, 0), HH-1);
            int cx0 = min(max(ix0, 0), WW-1), cx1 = min(max(ix1, 0), WW-1);
            const float4* p00 = (const float4*)(sb + (size_t)(cy0*WW + cx0)*64 + g*8);
            const float4* p01 = (const float4*)(sb + (size_t)(cy0*WW + cx1)*64 + g*8);
            const float4* p10 = (const float4*)(sb + (size_t)(cy1*WW + cx0)*64 + g*8);
            const float4* p11 = (const float4*)(sb + (size_t)(cy1*WW + cx1)*64 + g*8);
            float v[8];
            #pragma unroll
            for (int h = 0; h < 2; h++) {
                float4 a = p00[h], bb = p01[h], cc = p10[h], dd = p11[h];
                v[h*4+0] = w00*a.x + w01*bb.x + w10*cc.x + w11*dd.x;
                v[h*4+1] = w00*a.y + w01*bb.y + w10*cc.y + w11*dd.y;
                v[h*4+2] = w00*a.z + w01*bb.z + w10*cc.z + w11*dd.z;
                v[h*4+3] = w00*a.w + w01*bb.w + w10*cc.w + w11*dd.w;
            }
            uint32_t hpk[4], lpk[4];
            #pragma unroll
            for (int q = 0; q < 4; q++) {
                __nv_bfloat162 h2 = __floats2bfloat162_rn(v[q*2], v[q*2+1]);
                float2 hf = __bfloat1622float2(h2);
                __nv_bfloat162 l2 = __floats2bfloat162_rn(v[q*2] - hf.x, v[q*2+1] - hf.y);
                hpk[q] = *(uint32_t*)&h2;
                lpk[q] = *(uint32_t*)&l2;
            }
            uint32_t so = (uint32_t)px * 128u +
                          (((uint32_t)g * 16u) ^ (((uint32_t)px & 7u) * 16u));
            asm volatile("st.shared.v4.b32 [%0], {%1,%2,%3,%4};"
                :: "r"(SM_S + so), "r"(hpk[0]), "r"(hpk[1]), "r"(hpk[2]), "r"(hpk[3]) : "memory");
            asm volatile("st.shared.v4.b32 [%0], {%1,%2,%3,%4};"
                :: "r"(SM_S + 16384u + so), "r"(lpk[0]), "r"(lpk[1]), "r"(lpk[2]), "r"(lpk[3]) : "memory");
        }

        if (k < 8) CP_WAIT1(); else CP_WAIT0();
        __syncthreads();

        uint32_t Bt = SM_Bd + (uint32_t)(k & 1) * 16384u;
        uint32_t rowA0 = (uint32_t)(mbase + lr);
        uint32_t rowB0 = (uint32_t)(nbase + lr);
        #pragma unroll
        for (int ks = 0; ks < 4; ks++) {
            uint32_t kb = (uint32_t)(ks * 32 + kq);
            uint32_t ah0[4], ah1[4], al0[4], al1[4];
            uint32_t bh0[4], bh1[4], bl0[4], bl1[4];
            {
                uint32_t r0 = rowA0, r1 = rowA0 + 16u;
                uint32_t o0 = r0*128u + (kb ^ ((r0 & 7u)*16u));
                uint32_t o1 = r1*128u + (kb ^ ((r1 & 7u)*16u));
                LDSM_X4(ah0[0], ah0[1], ah0[2], ah0[3], SM_S + o0);
                LDSM_X4(ah1[0], ah1[1], ah1[2], ah1[3], SM_S + o1);
                LDSM_X4(al0[0], al0[1], al0[2], al0[3], SM_S + 16384u + o0);
                LDSM_X4(al1[0], al1[1], al1[2], al1[3], SM_S + 16384u + o1);
            }
            {
                uint32_t r0 = rowB0, r1 = rowB0 + 16u;
                uint32_t o0 = r0*128u + (kb ^ ((r0 & 7u)*16u));
                uint32_t o1 = r1*128u + (kb ^ ((r1 & 7u)*16u));
                LDSM_X4(bh0[0], bh0[1], bh0[2], bh0[3], Bt + o0);
                LDSM_X4(bh1[0], bh1[1], bh1[2], bh1[3], Bt + o1);
                LDSM_X4(bl0[0], bl0[1], bl0[2], bl0[3], Bt + 8192u + o0);
                LDSM_X4(bl1[0], bl1[1], bl1[2], bl1[3], Bt + 8192u + o1);
            }
            MMA_BF16(acc[0][0], ah0, bh0[0], bh0[2]);
            MMA_BF16(acc[0][1], ah0, bh0[1], bh0[3]);
            MMA_BF16(acc[0][2], ah0, bh1[0], bh1[2]);
            MMA_BF16(acc[0][3], ah0, bh1[1], bh1[3]);
            MMA_BF16(acc[1][0], ah1, bh0[0], bh0[2]);
            MMA_BF16(acc[1][1], ah1, bh0[1], bh0[3]);
            MMA_BF16(acc[1][2], ah1, bh1[0], bh1[2]);
            MMA_BF16(acc[1][3], ah1, bh1[1], bh1[3]);
            MMA_BF16(acc[0][0], ah0, bl0[0], bl0[2]);
            MMA_BF16(acc[0][1], ah0, bl0[1], bl0[3]);
            MMA_BF16(acc[0][2], ah0, bl1[0], bl1[2]);
            MMA_BF16(acc[0][3], ah0, bl1[1], bl1[3]);
            MMA_BF16(acc[1][0], ah1, bl0[0], bl0[2]);
            MMA_BF16(acc[1][1], ah1, bl0[1], bl0[3]);
            MMA_BF16(acc[1][2], ah1, bl1[0], bl1[2]);
            MMA_BF16(acc[1][3], ah1, bl1[1], bl1[3]);
            MMA_BF16(acc[0][0], al0, bh0[0], bh0[2]);
            MMA_BF16(acc[0][1], al0, bh0[1], bh0[3]);
            MMA_BF16(acc[0][2], al0, bh1[0], bh1[2]);
            MMA_BF16(acc[0][3], al0, bh1[1], bh1[3]);
            MMA_BF16(acc[1][0], al1, bh0[0], bh0[2]);
            MMA_BF16(acc[1][1], al1, bh0[1], bh0[3]);
            MMA_BF16(acc[1][2], al1, bh1[0], bh1[2]);
            MMA_BF16(acc[1][3], al1, bh1[1], bh1[3]);
        }
        __syncthreads();
    }

    // ---- epilogue: bias + NCHW fp32 store ----
    float bs2[4][2];
    #pragma unroll
    for (int nb = 0; nb < 4; nb++) {
        int co = nbase + nb * 8 + (lane & 3) * 2;
        bs2[nb][0] = bias[co];
        bs2[nb][1] = bias[co + 1];
    }
    #pragma unroll
    for (int mt = 0; mt < 2; mt++) {
        #pragma unroll
        for (int rh = 0; rh < 2; rh++) {
            int px = x0 + mbase + mt * 16 + (lane >> 2) + rh * 8;
            size_t pix = ((size_t)y << 8) + px;
            #pragma unroll
            for (int nb = 0; nb < 4; nb++) {
                int co = nbase + nb * 8 + (lane & 3) * 2;
                out[(((size_t)b * 64 + co    ) << 16) + pix] = acc[mt][nb][rh*2+0] + bs2[nb][0];
                out[(((size_t)b * 64 + co + 1) << 16) + pix] = acc[mt][nb][rh*2+1] + bs2[nb][1];
            }
        }
    }
}

// ---------------------------------------------------------------------------
// Launch
// ---------------------------------------------------------------------------
extern "C" void kernel_launch(void* const* d_in, const int* in_sizes, int n_in,
                              void* d_out, int out_size)
{
    const float* ref   = (const float*)d_in[0];
    const float* supp  = (const float*)d_in[1];
    const float* flow  = (const float*)d_in[2];
    const float* fc_w  = (const float*)d_in[3];
    const float* fc_b  = (const float*)d_in[4];
    const float* cw[6], *cb[6];
    for (int i = 0; i < 6; i++) {
        cw[i] = (const float*)d_in[5 + 2*i];
        cb[i] = (const float*)d_in[6 + 2*i];
    }
    const float* off_w = (const float*)d_in[17];
    const float* off_b = (const float*)d_in[18];
    const float* dcn_w = (const float*)d_in[19];
    const float* dcn_b = (const float*)d_in[20];
    float* out = (float*)d_out;

    __nv_bfloat16 *wH, *wL, *rH, *rL, *t0H, *t0L, *tmpH, *tmpL, *ftH, *ftL, *Bg;
    float *f0F, *ffF, *offbuf, *suppN;
    cudaGetSymbolAddress((void**)&wH,  g_wH);   cudaGetSymbolAddress((void**)&wL,  g_wL);
    cudaGetSymbolAddress((void**)&rH,  g_rH);   cudaGetSymbolAddress((void**)&rL,  g_rL);
    cudaGetSymbolAddress((void**)&t0H, g_t0H);  cudaGetSymbolAddress((void**)&t0L, g_t0L);
    cudaGetSymbolAddress((void**)&tmpH,g_tmpH); cudaGetSymbolAddress((void**)&tmpL,g_tmpL);
    cudaGetSymbolAddress((void**)&ftH, g_ftH);  cudaGetSymbolAddress((void**)&ftL, g_ftL);
    cudaGetSymbolAddress((void**)&Bg,  g_B);
    cudaGetSymbolAddress((void**)&f0F,   g_f0F);
    cudaGetSymbolAddress((void**)&ffF,   g_ffF);
    cudaGetSymbolAddress((void**)&offbuf,g_off);
    cudaGetSymbolAddress((void**)&suppN, g_sN);

    // smem per DIL: pad + single A (2*(128+2d)*128) + 2x16KB B
    const int SMB1 = 1024 + 2*(130*128) + 32768;   // 67072
    const int SMB2 = 1024 + 2*(132*128) + 32768;   // 67584
    const int SMB4 = 1024 + 2*(136*128) + 32768;   // 68608
    const int SMD  = 1024 + 32768 + 32768;         // 66560
    cudaFuncSetAttribute((const void*)conv_mma_kernel<1,1,1,18>, cudaFuncAttributeMaxDynamicSharedMemorySize, SMB1);
    cudaFuncSetAttribute((const void*)conv_mma_kernel<1,2,1,9>,  cudaFuncAttributeMaxDynamicSharedMemorySize, SMB1);
    cudaFuncSetAttribute((const void*)conv_mma_kernel<1,3,1,9>,  cudaFuncAttributeMaxDynamicSharedMemorySize, SMB1);
    cudaFuncSetAttribute((const void*)conv_mma_kernel<2,2,1,9>,  cudaFuncAttributeMaxDynamicSharedMemorySize, SMB2);
    cudaFuncSetAttribute((const void*)conv_mma_kernel<2,4,1,9>,  cudaFuncAttributeMaxDynamicSharedMemorySize, SMB2);
    cudaFuncSetAttribute((const void*)conv_mma_kernel<4,5,1,9>,  cudaFuncAttributeMaxDynamicSharedMemorySize, SMB4);
    cudaFuncSetAttribute((const void*)conv_mma_kernel<1,6,1,9>,  cudaFuncAttributeMaxDynamicSharedMemorySize, SMB1);
    cudaFuncSetAttribute((const void*)dcn_mma_kernel, cudaFuncAttributeMaxDynamicSharedMemorySize, SMD);

    // Fused weight prep (13 sets, one launch)
    PrepTable tab;
    tab.d[0]  = {fc_w, 128, 0,  64, 0};
    tab.d[1]  = {fc_w, 128, 64, 64, 0};
    for (int i = 0; i < 6; i++) tab.d[2+i] = {cw[i], 64, 0, 64, 0};
    for (int ch = 0; ch < 4; ch++) tab.d[8+ch] = {off_w, 64, 0, 216, ch*64};
    tab.d[12] = {dcn_w, 64, 0, 64, 0};
    prep_all_kernel<<<dim3(144, 13), 256>>>(tab, Bg);

    // supp NCHW -> NHWC fp32 (feeds warp + dcn gathers)
    supp_nhwc_kernel<<<dim3(HWSZ/64, BB), 256>>>(supp, suppN);
    // flow warp (reads NHWC supp)
    warp_nhwc_kernel<<<dim3(HWSZ/256, BB), 256>>>(suppN, flow, wH, wL);
    to_nhwc_kernel<<<dim3(HWSZ/256, BB), 256>>>(ref, rH, rL);

    dim3 cg(2, 256, 4);
    // fc (fused 18-tap): lrelu -> feat0 (f32 + hi/lo)
    conv_mma_kernel<1,1,1,18><<<cg, 256, SMB1>>>(wH, wL, rH, rL, Bg + 0*BSET, fc_b, 1, 64,
                                                 f0F, t0H, t0L, nullptr, nullptr);
    // c1: relu -> tmp
    conv_mma_kernel<1,2,1,9><<<cg, 256, SMB1>>>(t0H, t0L, nullptr, nullptr, Bg + 2*BSET, cb[0], 1, 64,
                                                nullptr, tmpH, tmpL, nullptr, nullptr);
    // c2: ff = feat0 + relu(v)
    conv_mma_kernel<1,3,1,9><<<cg, 256, SMB1>>>(tmpH, tmpL, nullptr, nullptr, Bg + 3*BSET, cb[1], 1, 64,
                                                ffF, nullptr, nullptr, f0F, nullptr);
    // c3 (dil2): relu -> tmp
    conv_mma_kernel<2,2,1,9><<<cg, 256, SMB2>>>(t0H, t0L, nullptr, nullptr, Bg + 4*BSET, cb[2], 1, 64,
                                                nullptr, tmpH, tmpL, nullptr, nullptr);
    // c4 (dil2): ff += 0.1*relu(v)
    conv_mma_kernel<2,4,1,9><<<cg, 256, SMB2>>>(tmpH, tmpL, nullptr, nullptr, Bg + 5*BSET, cb[3], 1, 64,
                                                ffF, nullptr, nullptr, nullptr, nullptr);
    // c5 (dil2): relu -> tmp
    conv_mma_kernel<2,2,1,9><<<cg, 256, SMB2>>>(t0H, t0L, nullptr, nullptr, Bg + 6*BSET, cb[4], 1, 64,
                                                nullptr, tmpH, tmpL, nullptr, nullptr);
    // c6 (dil4): feat = ff + 0.1*relu(v) -> hi/lo
    conv_mma_kernel<4,5,1,9><<<cg, 256, SMB4>>>(tmpH, tmpL, nullptr, nullptr, Bg + 7*BSET, cb[5], 1, 64,
                                                nullptr, ftH, ftL, ffF, nullptr);
    // offset conv: 216 couts, 4 chunks, NCHW out
    dim3 og(2, 256, 16);
    conv_mma_kernel<1,6,1,9><<<og, 256, SMB1>>>(ftH, ftL, nullptr, nullptr, Bg + 8*BSET, off_b, 4, 216,
                                                nullptr, nullptr, nullptr, nullptr, offbuf);
    // tensorized deformable conv (fast transcendentals, occupancy 2)
    dcn_mma_kernel<<<cg, 256, SMD>>>(suppN, offbuf, flow, Bg + 12*BSET, dcn_b, out);
}

// round 14
// speedup vs baseline: 1.1641x; 1.0118x over previous
#include <cuda_runtime.h>
#include <cuda_bf16.h>
#include <math.h>
#include <stdint.h>

#define BB 4
#define HH 256
#define WW 256
#define HWSZ 65536
#define NPX (BB*HWSZ)

// ---------------------------------------------------------------------------
// PTX helpers (plain sm_103-safe: ldmatrix + mma.sync + cp.async)
// ---------------------------------------------------------------------------
__device__ __forceinline__ uint32_t smem_u32(const void* p) {
    uint32_t a;
    asm("{ .reg .u64 t; cvta.to.shared.u64 t, %1; cvt.u32.u64 %0, t; }" : "=r"(a) : "l"(p));
    return a;
}

#define LDSM_X4(r0, r1, r2, r3, addr) \
    asm volatile("ldmatrix.sync.aligned.m8n8.x4.shared.b16 {%0,%1,%2,%3}, [%4];" \
        : "=r"(r0), "=r"(r1), "=r"(r2), "=r"(r3) : "r"(addr))

#define MMA_BF16(d, a, b0v, b1v) \
    asm volatile("mma.sync.aligned.m16n8k16.row.col.f32.bf16.bf16.f32 " \
        "{%0,%1,%2,%3},{%4,%5,%6,%7},{%8,%9},{%0,%1,%2,%3};" \
        : "+f"((d)[0]), "+f"((d)[1]), "+f"((d)[2]), "+f"((d)[3]) \
        : "r"((a)[0]), "r"((a)[1]), "r"((a)[2]), "r"((a)[3]), "r"(b0v), "r"(b1v))

#define CP_ASYNC16(dst, src, sz) \
    asm volatile("cp.async.cg.shared.global [%0], [%1], 16, %2;" \
        :: "r"(dst), "l"(src), "r"(sz) : "memory")
#define CP_COMMIT() asm volatile("cp.async.commit_group;" ::: "memory")
#define CP_WAIT1() asm volatile("cp.async.wait_group 1;" ::: "memory")
#define CP_WAIT0() asm volatile("cp.async.wait_group 0;" ::: "memory")

// Fast transcendentals for DCN offsets. Clamp keeps exp finite; tanh(15)==1 in fp32.
__device__ __forceinline__ float fast_tanh(float x) {
    float xc = fminf(fmaxf(x, -15.f), 15.f);
    float e2 = __expf(2.f * xc);
    return __fdividef(e2 - 1.f, e2 + 1.f);
}
__device__ __forceinline__ float fast_sigmoid(float x) {
    return __fdividef(1.f, 1.f + __expf(-x));
}

// ---------------------------------------------------------------------------
// Device global scratch
// ---------------------------------------------------------------------------
#define FEAT_ELEMS ((size_t)NPX*64)
__device__ __nv_bfloat16 g_wH[FEAT_ELEMS], g_wL[FEAT_ELEMS];     // warped supp
__device__ __nv_bfloat16 g_rH[FEAT_ELEMS], g_rL[FEAT_ELEMS];     // ref
__device__ __nv_bfloat16 g_t0H[FEAT_ELEMS], g_t0L[FEAT_ELEMS];   // feat0
__device__ __nv_bfloat16 g_tmpH[FEAT_ELEMS], g_tmpL[FEAT_ELEMS];
__device__ __nv_bfloat16 g_ftH[FEAT_ELEMS], g_ftL[FEAT_ELEMS];   // final feat
__device__ float g_f0F[FEAT_ELEMS];                               // feat0 fp32
__device__ float g_ffF[FEAT_ELEMS];                               // feat fp32 accum
__device__ float g_off[(size_t)BB*216*HWSZ];                      // NCHW
__device__ float g_sN[FEAT_ELEMS];                                // supp NHWC fp32
// 13 B-sets (fc0, fc1, c1..c6, off chunks 0..3, dcn); each 9 taps x 16KB
#define BSET 73728
__device__ __nv_bfloat16 g_B[13*BSET];

// ---------------------------------------------------------------------------
// Fused B prep: all 13 sets in one launch (blockIdx.y = set)
// ---------------------------------------------------------------------------
struct PrepDesc { const float* w; int cinTot, cin0, coutTot, cout0; };
struct PrepTable { PrepDesc d[13]; };

__global__ void prep_all_kernel(PrepTable tab, __nv_bfloat16* __restrict__ outB)
{
    int set = blockIdx.y;
    PrepDesc pd = tab.d[set];
    int idx = blockIdx.x * 256 + threadIdx.x;   // < 36864
    int c = idx & 63;
    int r = (idx >> 6) & 63;
    int t = idx >> 12;
    float v = 0.f;
    int co = pd.cout0 + r;
    if (co < pd.coutTot) v = pd.w[((size_t)co * pd.cinTot + pd.cin0 + c) * 9 + t];
    __nv_bfloat16 h = __float2bfloat16(v);
    __nv_bfloat16 l = __float2bfloat16(v - __bfloat162float(h));
    uint32_t off = (uint32_t)r * 128u + (uint32_t)c * 2u;
    uint32_t so = off ^ ((off >> 3) & 0x70u);
    char* ob = (char*)(outB + (size_t)set * BSET) + (size_t)t * 16384;
    *(__nv_bfloat16*)(ob + so) = h;
    *(__nv_bfloat16*)(ob + 8192 + so) = l;
}

// ---------------------------------------------------------------------------
// supp NCHW fp32 -> NHWC fp32 (smem-tiled transpose, 64px x 64ch per block)
// ---------------------------------------------------------------------------
__global__ void supp_nhwc_kernel(const float* __restrict__ src, float* __restrict__ dst)
{
    __shared__ float s[64 * 65];
    int b  = blockIdx.y;
    int x0 = blockIdx.x * 64;     // linear pixel base
    int tid = threadIdx.x;
    int lc = tid >> 6;            // 0..3
    int lp = tid & 63;
    #pragma unroll
    for (int i = 0; i < 16; i++) {
        int c = i * 4 + lc;
        s[lp * 65 + c] = src[((size_t)b * 64 + c) * HWSZ + x0 + lp];
    }
    __syncthreads();
    int px = tid >> 2, q4 = (tid & 3) * 16;
    float* dp = dst + ((size_t)b * HWSZ + x0 + px) * 64 + q4;
    const float* sp = s + px * 65 + q4;
    #pragma unroll
    for (int q = 0; q < 4; q++)
        ((float4*)dp)[q] = make_float4(sp[q*4], sp[q*4+1], sp[q*4+2], sp[q*4+3]);
}

// ---------------------------------------------------------------------------
// flow_warp (reads NHWC fp32 supp, vectorized corners) -> NHWC bf16 hi/lo
// ---------------------------------------------------------------------------
__global__ void warp_nhwc_kernel(const float* __restrict__ suppN, const float* __restrict__ flow,
                                 __nv_bfloat16* __restrict__ oH, __nv_bfloat16* __restrict__ oL)
{
    int p = blockIdx.x * 256 + threadIdx.x;
    int b = blockIdx.y;
    int y = p >> 8, x = p & 255;
    float fx = flow[((size_t)b*2    )*HWSZ + p];
    float fy = flow[((size_t)b*2 + 1)*HWSZ + p];
    float sy = (float)y + fy, sx = (float)x + fx;
    float y0f = floorf(sy), x0f = floorf(sx);
    int iy0 = (int)y0f, ix0 = (int)x0f, iy1 = iy0+1, ix1 = ix0+1;
    float wy = sy - y0f, wx = sx - x0f;
    bool vy0 = ((unsigned)iy0 < HH), vy1 = ((unsigned)iy1 < HH);
    bool vx0 = ((unsigned)ix0 < WW), vx1 = ((unsigned)ix1 < WW);
    float w00 = (1.f-wy)*(1.f-wx) * ((vy0&&vx0)?1.f:0.f);
    float w01 = (1.f-wy)*wx       * ((vy0&&vx1)?1.f:0.f);
    float w10 = wy*(1.f-wx)       * ((vy1&&vx0)?1.f:0.f);
    float w11 = wy*wx             * ((vy1&&vx1)?1.f:0.f);
    int cy0 = min(max(iy0,0),HH-1), cy1 = min(max(iy1,0),HH-1);
    int cx0 = min(max(ix0,0),WW-1), cx1 = min(max(ix1,0),WW-1);
    size_t i00 = (size_t)(cy0*WW+cx0)*64, i01 = (size_t)(cy0*WW+cx1)*64;
    size_t i10 = (size_t)(cy1*WW+cx0)*64, i11 = (size_t)(cy1*WW+cx1)*64;
    const float* sb = suppN + (size_t)b*HWSZ*64;
    __nv_bfloat16* ohp = oH + ((size_t)b*HWSZ + p)*64;
    __nv_bfloat16* olp = oL + ((size_t)b*HWSZ + p)*64;
    #pragma unroll 1
    for (int g = 0; g < 8; g++) {
        const float4* p00 = (const float4*)(sb + i00 + g*8);
        const float4* p01 = (const float4*)(sb + i01 + g*8);
        const float4* p10 = (const float4*)(sb + i10 + g*8);
        const float4* p11 = (const float4*)(sb + i11 + g*8);
        float v[8];
        #pragma unroll
        for (int h = 0; h < 2; h++) {
            float4 a = p00[h], bb = p01[h], cc = p10[h], dd = p11[h];
            v[h*4+0] = w00*a.x + w01*bb.x + w10*cc.x + w11*dd.x;
            v[h*4+1] = w00*a.y + w01*bb.y + w10*cc.y + w11*dd.y;
            v[h*4+2] = w00*a.z + w01*bb.z + w10*cc.z + w11*dd.z;
            v[h*4+3] = w00*a.w + w01*bb.w + w10*cc.w + w11*dd.w;
        }
        uint4 uh, ul;
        uint32_t* ph = (uint32_t*)&uh;
        uint32_t* pl = (uint32_t*)&ul;
        #pragma unroll
        for (int q = 0; q < 4; q++) {
            __nv_bfloat162 h2 = __floats2bfloat162_rn(v[q*2], v[q*2+1]);
            float2 hf = __bfloat1622float2(h2);
            __nv_bfloat162 l2 = __floats2bfloat162_rn(v[q*2] - hf.x, v[q*2+1] - hf.y);
            ph[q] = *(uint32_t*)&h2;
            pl[q] = *(uint32_t*)&l2;
        }
        ((uint4*)ohp)[g] = uh;
        ((uint4*)olp)[g] = ul;
    }
}

// NCHW fp32 -> NHWC bf16 hi/lo (ref)
__global__ void to_nhwc_kernel(const float* __restrict__ src,
                               __nv_bfloat16* __restrict__ oH, __nv_bfloat16* __restrict__ oL)
{
    int p = blockIdx.x * 256 + threadIdx.x;
    int b = blockIdx.y;
    const float* sp = src + (size_t)b*64*HWSZ + p;
    __nv_bfloat16* ohp = oH + ((size_t)b*HWSZ + p)*64;
    __nv_bfloat16* olp = oL + ((size_t)b*HWSZ + p)*64;
    for (int g = 0; g < 8; g++) {
        uint4 uh, ul;
        uint32_t* ph = (uint32_t*)&uh;
        uint32_t* pl = (uint32_t*)&ul;
        #pragma unroll
        for (int q = 0; q < 4; q++) {
            float v0 = sp[(size_t)(g*8 + q*2    )*HWSZ];
            float v1 = sp[(size_t)(g*8 + q*2 + 1)*HWSZ];
            __nv_bfloat162 h2 = __floats2bfloat162_rn(v0, v1);
            float2 hf = __bfloat1622float2(h2);
            __nv_bfloat162 l2 = __floats2bfloat162_rn(v0 - hf.x, v1 - hf.y);
            ph[q] = *(uint32_t*)&h2;
            pl[q] = *(uint32_t*)&l2;
        }
        ((uint4*)ohp)[g] = uh;
        ((uint4*)olp)[g] = ul;
    }
}

// ---------------------------------------------------------------------------
// mma.sync conv: single A buffer per ki group, double-buffered B (NCH chunk
// sets per tap), group-accounting wait invariant. NCH=1: 3 CTAs/SM (proven).
// NCH=2 (offset conv): 128 couts/CTA, A staged once for both B sets, 2 CTAs/SM.
// ---------------------------------------------------------------------------
template<int DIL, int EPI, int HASBIAS, int NT, int NCH>
__global__ void __launch_bounds__(256, (NCH == 2 ? 2 : 3))
conv_mma_kernel(const __nv_bfloat16* __restrict__ inH,
                const __nv_bfloat16* __restrict__ inL,
                const __nv_bfloat16* __restrict__ inH2,
                const __nv_bfloat16* __restrict__ inL2,
                const __nv_bfloat16* __restrict__ Bimg,
                const float* __restrict__ bias,
                int nchunk, int coutTot,
                float* __restrict__ outF,
                __nv_bfloat16* __restrict__ outH,
                __nv_bfloat16* __restrict__ outL,
                const float* __restrict__ resF,
                float* __restrict__ outNCHW)
{
    constexpr uint32_t R = 128 + 2 * DIL;
    constexpr uint32_t AHALF = R * 128u;
    constexpr uint32_t ABUF = 2u * AHALF;
    constexpr uint32_t BSTEP = (uint32_t)NCH * 16384u;

    extern __shared__ char smem[];
    uint32_t base = (smem_u32(smem) + 1023u) & ~1023u;

    int tid = threadIdx.x;
    int lane = tid & 31, w = tid >> 5;
    int z = blockIdx.z;
    int b = z / nchunk, chunk = z - b * nchunk;
    int y = blockIdx.y, x0 = blockIdx.x * 128;

    const char* Bbase = (const char*)Bimg + (size_t)chunk * NCH * 147456;

    auto stageA = [&](int s) {
        int ki = (NT == 18 && s >= 3) ? s - 3 : s;
        const __nv_bfloat16* iH = (NT == 18 && s >= 3) ? inH2 : inH;
        const __nv_bfloat16* iL = (NT == 18 && s >= 3) ? inL2 : inL;
        int gy = y + (ki - 1) * DIL;
        bool rowok = ((unsigned)gy < HH);
        for (int i = tid; i < (int)(R * 8); i += 256) {
            int r = i >> 3, j = i & 7;
            int gx = x0 - DIL + r;
            bool ok = rowok && ((unsigned)gx < WW);
            size_t gidx = ok ? ((((size_t)b * HH + gy) * WW + gx) * 64) : 0;
            int sz = ok ? 16 : 0;
            uint32_t dst = base + (uint32_t)r * 128u +
                           (((uint32_t)j * 16u) ^ (((uint32_t)r & 7u) * 16u));
            CP_ASYNC16(dst, (const char*)(iH + gidx) + j * 16, sz);
            CP_ASYNC16(dst + AHALF, (const char*)(iL + gidx) + j * 16, sz);
        }
    };
    auto stageB = [&](int t2) {
        uint32_t bB = base + ABUF + (uint32_t)(t2 & 1) * BSTEP;
        #pragma unroll
        for (int nc = 0; nc < NCH; nc++) {
            const char* bsrc = Bbase + (size_t)nc * 147456 + (size_t)t2 * 16384;
            #pragma unroll
            for (int kk = 0; kk < 4; kk++)
                CP_ASYNC16(bB + (uint32_t)nc * 16384u + (uint32_t)tid * 16u + (uint32_t)kk * 4096u,
                           bsrc + tid * 16 + kk * 4096, 16);
        }
    };

    stageA(0);
    stageB(0);
    CP_COMMIT();

    int mbase = (w & 3) * 32;
    int nbase = (w >> 2) * 32;

    float acc[NCH][2][4][4];
    #pragma unroll
    for (int nc = 0; nc < NCH; nc++)
        #pragma unroll
        for (int i = 0; i < 2; i++)
            #pragma unroll
            for (int j = 0; j < 4; j++)
                #pragma unroll
                for (int q = 0; q < 4; q++) acc[nc][i][j][q] = 0.f;

    int lr = (lane & 7) + ((lane >> 3) & 1) * 8;
    int kq = (lane >> 4) * 16;

    #pragma unroll 1
    for (int tt = 0; tt < NT; tt++) {
        if (tt + 1 < NT && (tt + 1) % 3 != 0) {
            stageB(tt + 1);
            CP_COMMIT();
            CP_WAIT1();
        } else {
            CP_WAIT0();
        }
        __syncthreads();

        int s = tt / 3, kj = tt - s * 3;
        uint32_t Bt = base + ABUF + (uint32_t)(tt & 1) * BSTEP;
        uint32_t rowA0 = (uint32_t)(kj * DIL + mbase + lr);
        uint32_t rowB0 = (uint32_t)(nbase + lr);

        #pragma unroll
        for (int ks = 0; ks < 4; ks++) {
            uint32_t kb = (uint32_t)(ks * 32 + kq);
            uint32_t ah0[4], ah1[4], al0[4], al1[4];
            {
                uint32_t r0 = rowA0, r1 = rowA0 + 16u;
                uint32_t o0 = r0*128u + (kb ^ ((r0 & 7u)*16u));
                uint32_t o1 = r1*128u + (kb ^ ((r1 & 7u)*16u));
                LDSM_X4(ah0[0], ah0[1], ah0[2], ah0[3], base + o0);
                LDSM_X4(ah1[0], ah1[1], ah1[2], ah1[3], base + o1);
                LDSM_X4(al0[0], al0[1], al0[2], al0[3], base + AHALF + o0);
                LDSM_X4(al1[0], al1[1], al1[2], al1[3], base + AHALF + o1);
            }
            #pragma unroll
            for (int nc = 0; nc < NCH; nc++) {
                uint32_t Bc = Bt + (uint32_t)nc * 16384u;
                uint32_t bh0[4], bh1[4], bl0[4], bl1[4];
                uint32_t r0 = rowB0, r1 = rowB0 + 16u;
                uint32_t o0 = r0*128u + (kb ^ ((r0 & 7u)*16u));
                uint32_t o1 = r1*128u + (kb ^ ((r1 & 7u)*16u));
                LDSM_X4(bh0[0], bh0[1], bh0[2], bh0[3], Bc + o0);
                LDSM_X4(bh1[0], bh1[1], bh1[2], bh1[3], Bc + o1);
                LDSM_X4(bl0[0], bl0[1], bl0[2], bl0[3], Bc + 8192u + o0);
                LDSM_X4(bl1[0], bl1[1], bl1[2], bl1[3], Bc + 8192u + o1);
                MMA_BF16(acc[nc][0][0], ah0, bh0[0], bh0[2]);
                MMA_BF16(acc[nc][0][1], ah0, bh0[1], bh0[3]);
                MMA_BF16(acc[nc][0][2], ah0, bh1[0], bh1[2]);
                MMA_BF16(acc[nc][0][3], ah0, bh1[1], bh1[3]);
                MMA_BF16(acc[nc][1][0], ah1, bh0[0], bh0[2]);
                MMA_BF16(acc[nc][1][1], ah1, bh0[1], bh0[3]);
                MMA_BF16(acc[nc][1][2], ah1, bh1[0], bh1[2]);
                MMA_BF16(acc[nc][1][3], ah1, bh1[1], bh1[3]);
                MMA_BF16(acc[nc][0][0], ah0, bl0[0], bl0[2]);
                MMA_BF16(acc[nc][0][1], ah0, bl0[1], bl0[3]);
                MMA_BF16(acc[nc][0][2], ah0, bl1[0], bl1[2]);
                MMA_BF16(acc[nc][0][3], ah0, bl1[1], bl1[3]);
                MMA_BF16(acc[nc][1][0], ah1, bl0[0], bl0[2]);
                MMA_BF16(acc[nc][1][1], ah1, bl0[1], bl0[3]);
                MMA_BF16(acc[nc][1][2], ah1, bl1[0], bl1[2]);
                MMA_BF16(acc[nc][1][3], ah1, bl1[1], bl1[3]);
                MMA_BF16(acc[nc][0][0], al0, bh0[0], bh0[2]);
                MMA_BF16(acc[nc][0][1], al0, bh0[1], bh0[3]);
                MMA_BF16(acc[nc][0][2], al0, bh1[0], bh1[2]);
                MMA_BF16(acc[nc][0][3], al0, bh1[1], bh1[3]);
                MMA_BF16(acc[nc][1][0], al1, bh0[0], bh0[2]);
                MMA_BF16(acc[nc][1][1], al1, bh0[1], bh0[3]);
                MMA_BF16(acc[nc][1][2], al1, bh1[0], bh1[2]);
                MMA_BF16(acc[nc][1][3], al1, bh1[1], bh1[3]);
            }
        }
        __syncthreads();

        if (tt + 1 < NT && (tt + 1) % 3 == 0) {
            stageA((tt + 1) / 3);
            stageB(tt + 1);
            CP_COMMIT();
        }
    }

    // ---- epilogue ----
    #pragma unroll
    for (int nc = 0; nc < NCH; nc++) {
        float bs2[4][2];
        #pragma unroll
        for (int nb = 0; nb < 4; nb++) {
            int co = (chunk * NCH + nc) * 64 + nbase + nb * 8 + (lane & 3) * 2;
            bs2[nb][0] = (HASBIAS && co     < coutTot) ? bias[co]     : 0.f;
            bs2[nb][1] = (HASBIAS && co + 1 < coutTot) ? bias[co + 1] : 0.f;
        }
        #pragma unroll
        for (int mt = 0; mt < 2; mt++) {
            #pragma unroll
            for (int rh = 0; rh < 2; rh++) {
                int px = x0 + mbase + mt * 16 + (lane >> 2) + rh * 8;
                size_t P = ((size_t)b * HH + y) * WW + px;
                #pragma unroll
                for (int nb = 0; nb < 4; nb++) {
                    int cl = nbase + nb * 8 + (lane & 3) * 2;
                    float v0 = acc[nc][mt][nb][rh * 2 + 0] + bs2[nb][0];
                    float v1 = acc[nc][mt][nb][rh * 2 + 1] + bs2[nb][1];
                    size_t ob = P * 64 + cl;

                    if (EPI == 1) {
                        v0 = (v0 > 0.f) ? v0 : 0.1f * v0;
                        v1 = (v1 > 0.f) ? v1 : 0.1f * v1;
                        *(float2*)(outF + ob) = make_float2(v0, v1);
                        __nv_bfloat162 h2 = __floats2bfloat162_rn(v0, v1);
                        float2 hf = __bfloat1622float2(h2);
                        __nv_bfloat162 l2 = __floats2bfloat162_rn(v0 - hf.x, v1 - hf.y);
                        *(uint32_t*)(outH + ob) = *(uint32_t*)&h2;
                        *(uint32_t*)(outL + ob) = *(uint32_t*)&l2;
                    } else if (EPI == 2) {
                        v0 = fmaxf(v0, 0.f); v1 = fmaxf(v1, 0.f);
                        __nv_bfloat162 h2 = __floats2bfloat162_rn(v0, v1);
                        float2 hf = __bfloat1622float2(h2);
                        __nv_bfloat162 l2 = __floats2bfloat162_rn(v0 - hf.x, v1 - hf.y);
                        *(uint32_t*)(outH + ob) = *(uint32_t*)&h2;
                        *(uint32_t*)(outL + ob) = *(uint32_t*)&l2;
                    } else if (EPI == 3) {
                        float2 rv = *(const float2*)(resF + ob);
                        v0 = rv.x + fmaxf(v0, 0.f);
                        v1 = rv.y + fmaxf(v1, 0.f);
                        *(float2*)(outF + ob) = make_float2(v0, v1);
                    } else if (EPI == 4) {
                        float2 rv = *(const float2*)(outF + ob);
                        v0 = rv.x + 0.1f * fmaxf(v0, 0.f);
                        v1 = rv.y + 0.1f * fmaxf(v1, 0.f);
                        *(float2*)(outF + ob) = make_float2(v0, v1);
                    } else if (EPI == 5) {
                        float2 rv = *(const float2*)(resF + ob);
                        v0 = rv.x + 0.1f * fmaxf(v0, 0.f);
                        v1 = rv.y + 0.1f * fmaxf(v1, 0.f);
                        __nv_bfloat162 h2 = __floats2bfloat162_rn(v0, v1);
                        float2 hf = __bfloat1622float2(h2);
                        __nv_bfloat162 l2 = __floats2bfloat162_rn(v0 - hf.x, v1 - hf.y);
                        *(uint32_t*)(outH + ob) = *(uint32_t*)&h2;
                        *(uint32_t*)(outL + ob) = *(uint32_t*)&l2;
                    } else if (EPI == 6) {
                        int co = (chunk * NCH + nc) * 64 + cl;
                        size_t pix = ((size_t)y << 8) + px;
                        if (co < coutTot)
                            outNCHW[(((size_t)b * coutTot + co) << 16) + pix] = v0;
                        if (co + 1 < coutTot)
                            outNCHW[(((size_t)b * coutTot + co + 1) << 16) + pix] = v1;
                    }
                }
            }
        }
    }
}

// ---------------------------------------------------------------------------
// Modulated deformable conv, tensorized; NHWC fp32 gathers + fast
// transcendentals; occupancy 2 (occ-3 reg-caps spill the sampler).
// ---------------------------------------------------------------------------
__global__ void __launch_bounds__(256, 2)
dcn_mma_kernel(const float* __restrict__ suppN, const float* __restrict__ off,
               const float* __restrict__ flow, const __nv_bfloat16* __restrict__ Bimg,
               const float* __restrict__ bias, float* __restrict__ out)
{
    extern __shared__ char smem[];
    uint32_t base = (smem_u32(smem) + 1023u) & ~1023u;
    const uint32_t SM_S = base;            // 32KB: hi 16K | lo 16K
    const uint32_t SM_Bd = base + 32768u;  // 2 x 16KB B double buffer

    int tid = threadIdx.x;
    int lane = tid & 31, w = tid >> 5;
    int b = blockIdx.z, y = blockIdx.y, x0 = blockIdx.x * 128;

    #pragma unroll
    for (int kk = 0; kk < 4; kk++)
        CP_ASYNC16(SM_Bd + (uint32_t)tid * 16u + (uint32_t)kk * 4096u,
                   (const char*)Bimg + tid * 16 + kk * 4096, 16);
    CP_COMMIT();

    int mbase = (w & 3) * 32;
    int nbase = (w >> 2) * 32;
    float acc[2][4][4];
    #pragma unroll
    for (int i = 0; i < 2; i++)
        #pragma unroll
        for (int j = 0; j < 4; j++)
            #pragma unroll
            for (int q = 0; q < 4; q++) acc[i][j][q] = 0.f;

    int lr = (lane & 7) + ((lane >> 3) & 1) * 8;
    int kq = (lane >> 4) * 16;

    const float* fxp  = flow + ((size_t)b*2 + 0)*HWSZ + y*WW + x0;
    const float* fyp  = flow + ((size_t)b*2 + 1)*HWSZ + y*WW + x0;
    const float* offb = off  + (size_t)b*216*HWSZ + y*WW + x0;
    const float* sb   = suppN + (size_t)b*HWSZ*64;

    #pragma unroll 1
    for (int k = 0; k < 9; k++) {
        if (k < 8) {
            const char* bsrc = (const char*)Bimg + (size_t)(k + 1) * 16384;
            uint32_t bB = SM_Bd + (uint32_t)((k + 1) & 1) * 16384u;
            #pragma unroll
            for (int kk = 0; kk < 4; kk++)
                CP_ASYNC16(bB + (uint32_t)tid * 16u + (uint32_t)kk * 4096u,
                           bsrc + tid * 16 + kk * 4096, 16);
            CP_COMMIT();
        }

        int ki = k / 3, kj = k - ki * 3;
        #pragma unroll 1
        for (int it = 0; it < 4; it++) {
            int task = tid + it * 256;
            int px = task & 127;
            int g  = task >> 7;
            int cdy = g*18 + k*2;
            float rawdy = offb[(size_t)cdy          *HWSZ + px];
            float rawdx = offb[(size_t)(cdy + 1)    *HWSZ + px];
            float rawm  = offb[(size_t)(144 + g*9+k)*HWSZ + px];
            float fx = fxp[px], fy = fyp[px];
            float ady = 25.f * fast_tanh(rawdy) + ((cdy     < 72) ? fx : fy);
            float adx = 25.f * fast_tanh(rawdx) + ((cdy + 1 < 72) ? fx : fy);
            float m   = fast_sigmoid(rawm);
            float sy = (float)y         + (float)(ki - 1) + ady;
            float sx = (float)(x0 + px) + (float)(kj - 1) + adx;
            float y0f = floorf(sy), x0f = floorf(sx);
            int iy0 = (int)y0f, ix0 = (int)x0f;
            int iy1 = iy0 + 1,  ix1 = ix0 + 1;
            float wy = sy - y0f, wx = sx - x0f;
            bool vy0 = ((unsigned)iy0 < HH), vy1 = ((unsigned)iy1 < HH);
            bool vx0 = ((unsigned)ix0 < WW), vx1 = ((unsigned)ix1 < WW);
            float w00 = (1.f - wy)*(1.f - wx) * ((vy0 && vx0) ? 1.f : 0.f) * m;
            float w01 = (1.f - wy)*wx         * ((vy0 && vx1) ? 1.f : 0.f) * m;
            float w10 = wy*(1.f - wx)         * ((vy1 && vx0) ? 1.f : 0.f) * m;
            float w11 = wy*wx                 * ((vy1 && vx1) ? 1.f : 0.f) * m;
            int cy0 = min(max(iy0, 0), HH-1), cy1 = min(max(iy1, 0), HH-1);
            int cx0 = min(max(ix0, 0), WW-1), cx1 = min(max(ix1, 0), WW-1);
            const float4* p00 = (const float4*)(sb + (size_t)(cy0*WW + cx0)*64 + g*8);
            const float4* p01 = (const float4*)(sb + (size_t)(cy0*WW + cx1)*64 + g*8);
            const float4* p10 = (const float4*)(sb + (size_t)(cy1*WW + cx0)*64 + g*8);
            const float4* p11 = (const float4*)(sb + (size_t)(cy1*WW + cx1)*64 + g*8);
            float v[8];
            #pragma unroll
            for (int h = 0; h < 2; h++) {
                float4 a = p00[h], bb = p01[h], cc = p10[h], dd = p11[h];
                v[h*4+0] = w00*a.x + w01*bb.x + w10*cc.x + w11*dd.x;
                v[h*4+1] = w00*a.y + w01*bb.y + w10*cc.y + w11*dd.y;
                v[h*4+2] = w00*a.z + w01*bb.z + w10*cc.z + w11*dd.z;
                v[h*4+3] = w00*a.w + w01*bb.w + w10*cc.w + w11*dd.w;
            }
            uint32_t hpk[4], lpk[4];
            #pragma unroll
            for (int q = 0; q < 4; q++) {
                __nv_bfloat162 h2 = __floats2bfloat162_rn(v[q*2], v[q*2+1]);
                float2 hf = __bfloat1622float2(h2);
                __nv_bfloat162 l2 = __floats2bfloat162_rn(v[q*2] - hf.x, v[q*2+1] - hf.y);
                hpk[q] = *(uint32_t*)&h2;
                lpk[q] = *(uint32_t*)&l2;
            }
            uint32_t so = (uint32_t)px * 128u +
                          (((uint32_t)g * 16u) ^ (((uint32_t)px & 7u) * 16u));
            asm volatile("st.shared.v4.b32 [%0], {%1,%2,%3,%4};"
                :: "r"(SM_S + so), "r"(hpk[0]), "r"(hpk[1]), "r"(hpk[2]), "r"(hpk[3]) : "memory");
            asm volatile("st.shared.v4.b32 [%0], {%1,%2,%3,%4};"
                :: "r"(SM_S + 16384u + so), "r"(lpk[0]), "r"(lpk[1]), "r"(lpk[2]), "r"(lpk[3]) : "memory");
        }

        if (k < 8) CP_WAIT1(); else CP_WAIT0();
        __syncthreads();

        uint32_t Bt = SM_Bd + (uint32_t)(k & 1) * 16384u;
        uint32_t rowA0 = (uint32_t)(mbase + lr);
        uint32_t rowB0 = (uint32_t)(nbase + lr);
        #pragma unroll
        for (int ks = 0; ks < 4; ks++) {
            uint32_t kb = (uint32_t)(ks * 32 + kq);
            uint32_t ah0[4], ah1[4], al0[4], al1[4];
            uint32_t bh0[4], bh1[4], bl0[4], bl1[4];
            {
                uint32_t r0 = rowA0, r1 = rowA0 + 16u;
                uint32_t o0 = r0*128u + (kb ^ ((r0 & 7u)*16u));
                uint32_t o1 = r1*128u + (kb ^ ((r1 & 7u)*16u));
                LDSM_X4(ah0[0], ah0[1], ah0[2], ah0[3], SM_S + o0);
                LDSM_X4(ah1[0], ah1[1], ah1[2], ah1[3], SM_S + o1);
                LDSM_X4(al0[0], al0[1], al0[2], al0[3], SM_S + 16384u + o0);
                LDSM_X4(al1[0], al1[1], al1[2], al1[3], SM_S + 16384u + o1);
            }
            {
                uint32_t r0 = rowB0, r1 = rowB0 + 16u;
                uint32_t o0 = r0*128u + (kb ^ ((r0 & 7u)*16u));
                uint32_t o1 = r1*128u + (kb ^ ((r1 & 7u)*16u));
                LDSM_X4(bh0[0], bh0[1], bh0[2], bh0[3], Bt + o0);
                LDSM_X4(bh1[0], bh1[1], bh1[2], bh1[3], Bt + o1);
                LDSM_X4(bl0[0], bl0[1], bl0[2], bl0[3], Bt + 8192u + o0);
                LDSM_X4(bl1[0], bl1[1], bl1[2], bl1[3], Bt + 8192u + o1);
            }
            MMA_BF16(acc[0][0], ah0, bh0[0], bh0[2]);
            MMA_BF16(acc[0][1], ah0, bh0[1], bh0[3]);
            MMA_BF16(acc[0][2], ah0, bh1[0], bh1[2]);
            MMA_BF16(acc[0][3], ah0, bh1[1], bh1[3]);
            MMA_BF16(acc[1][0], ah1, bh0[0], bh0[2]);
            MMA_BF16(acc[1][1], ah1, bh0[1], bh0[3]);
            MMA_BF16(acc[1][2], ah1, bh1[0], bh1[2]);
            MMA_BF16(acc[1][3], ah1, bh1[1], bh1[3]);
            MMA_BF16(acc[0][0], ah0, bl0[0], bl0[2]);
            MMA_BF16(acc[0][1], ah0, bl0[1], bl0[3]);
            MMA_BF16(acc[0][2], ah0, bl1[0], bl1[2]);
            MMA_BF16(acc[0][3], ah0, bl1[1], bl1[3]);
            MMA_BF16(acc[1][0], ah1, bl0[0], bl0[2]);
            MMA_BF16(acc[1][1], ah1, bl0[1], bl0[3]);
            MMA_BF16(acc[1][2], ah1, bl1[0], bl1[2]);
            MMA_BF16(acc[1][3], ah1, bl1[1], bl1[3]);
            MMA_BF16(acc[0][0], al0, bh0[0], bh0[2]);
            MMA_BF16(acc[0][1], al0, bh0[1], bh0[3]);
            MMA_BF16(acc[0][2], al0, bh1[0], bh1[2]);
            MMA_BF16(acc[0][3], al0, bh1[1], bh1[3]);
            MMA_BF16(acc[1][0], al1, bh0[0], bh0[2]);
            MMA_BF16(acc[1][1], al1, bh0[1], bh0[3]);
            MMA_BF16(acc[1][2], al1, bh1[0], bh1[2]);
            MMA_BF16(acc[1][3], al1, bh1[1], bh1[3]);
        }
        __syncthreads();
    }

    // ---- epilogue: bias + NCHW fp32 store ----
    float bs2[4][2];
    #pragma unroll
    for (int nb = 0; nb < 4; nb++) {
        int co = nbase + nb * 8 + (lane & 3) * 2;
        bs2[nb][0] = bias[co];
        bs2[nb][1] = bias[co + 1];
    }
    #pragma unroll
    for (int mt = 0; mt < 2; mt++) {
        #pragma unroll
        for (int rh = 0; rh < 2; rh++) {
            int px = x0 + mbase + mt * 16 + (lane >> 2) + rh * 8;
            size_t pix = ((size_t)y << 8) + px;
            #pragma unroll
            for (int nb = 0; nb < 4; nb++) {
                int co = nbase + nb * 8 + (lane & 3) * 2;
                out[(((size_t)b * 64 + co    ) << 16) + pix] = acc[mt][nb][rh*2+0] + bs2[nb][0];
                out[(((size_t)b * 64 + co + 1) << 16) + pix] = acc[mt][nb][rh*2+1] + bs2[nb][1];
            }
        }
    }
}

// ---------------------------------------------------------------------------
// Launch
// ---------------------------------------------------------------------------
extern "C" void kernel_launch(void* const* d_in, const int* in_sizes, int n_in,
                              void* d_out, int out_size)
{
    const float* ref   = (const float*)d_in[0];
    const float* supp  = (const float*)d_in[1];
    const float* flow  = (const float*)d_in[2];
    const float* fc_w  = (const float*)d_in[3];
    const float* fc_b  = (const float*)d_in[4];
    const float* cw[6], *cb[6];
    for (int i = 0; i < 6; i++) {
        cw[i] = (const float*)d_in[5 + 2*i];
        cb[i] = (const float*)d_in[6 + 2*i];
    }
    const float* off_w = (const float*)d_in[17];
    const float* off_b = (const float*)d_in[18];
    const float* dcn_w = (const float*)d_in[19];
    const float* dcn_b = (const float*)d_in[20];
    float* out = (float*)d_out;

    __nv_bfloat16 *wH, *wL, *rH, *rL, *t0H, *t0L, *tmpH, *tmpL, *ftH, *ftL, *Bg;
    float *f0F, *ffF, *offbuf, *suppN;
    cudaGetSymbolAddress((void**)&wH,  g_wH);   cudaGetSymbolAddress((void**)&wL,  g_wL);
    cudaGetSymbolAddress((void**)&rH,  g_rH);   cudaGetSymbolAddress((void**)&rL,  g_rL);
    cudaGetSymbolAddress((void**)&t0H, g_t0H);  cudaGetSymbolAddress((void**)&t0L, g_t0L);
    cudaGetSymbolAddress((void**)&tmpH,g_tmpH); cudaGetSymbolAddress((void**)&tmpL,g_tmpL);
    cudaGetSymbolAddress((void**)&ftH, g_ftH);  cudaGetSymbolAddress((void**)&ftL, g_ftL);
    cudaGetSymbolAddress((void**)&Bg,  g_B);
    cudaGetSymbolAddress((void**)&f0F,   g_f0F);
    cudaGetSymbolAddress((void**)&ffF,   g_ffF);
    cudaGetSymbolAddress((void**)&offbuf,g_off);
    cudaGetSymbolAddress((void**)&suppN, g_sN);

    // smem: pad + single A (2*(128+2d)*128) + 2*NCH*16KB B
    const int SMB1 = 1024 + 2*(130*128) + 32768;   // 67072 (NCH=1, d=1)
    const int SMB2 = 1024 + 2*(132*128) + 32768;   // 67584 (NCH=1, d=2)
    const int SMB4 = 1024 + 2*(136*128) + 32768;   // 68608 (NCH=1, d=4)
    const int SMO  = 1024 + 2*(130*128) + 65536;   // 99840 (NCH=2, d=1)
    const int SMD  = 1024 + 32768 + 32768;         // 66560
    cudaFuncSetAttribute((const void*)conv_mma_kernel<1,1,1,18,1>, cudaFuncAttributeMaxDynamicSharedMemorySize, SMB1);
    cudaFuncSetAttribute((const void*)conv_mma_kernel<1,2,1,9,1>,  cudaFuncAttributeMaxDynamicSharedMemorySize, SMB1);
    cudaFuncSetAttribute((const void*)conv_mma_kernel<1,3,1,9,1>,  cudaFuncAttributeMaxDynamicSharedMemorySize, SMB1);
    cudaFuncSetAttribute((const void*)conv_mma_kernel<2,2,1,9,1>,  cudaFuncAttributeMaxDynamicSharedMemorySize, SMB2);
    cudaFuncSetAttribute((const void*)conv_mma_kernel<2,4,1,9,1>,  cudaFuncAttributeMaxDynamicSharedMemorySize, SMB2);
    cudaFuncSetAttribute((const void*)conv_mma_kernel<4,5,1,9,1>,  cudaFuncAttributeMaxDynamicSharedMemorySize, SMB4);
    cudaFuncSetAttribute((const void*)conv_mma_kernel<1,6,1,9,2>,  cudaFuncAttributeMaxDynamicSharedMemorySize, SMO);
    cudaFuncSetAttribute((const void*)dcn_mma_kernel, cudaFuncAttributeMaxDynamicSharedMemorySize, SMD);

    // Fused weight prep (13 sets, one launch)
    PrepTable tab;
    tab.d[0]  = {fc_w, 128, 0,  64, 0};
    tab.d[1]  = {fc_w, 128, 64, 64, 0};
    for (int i = 0; i < 6; i++) tab.d[2+i] = {cw[i], 64, 0, 64, 0};
    for (int ch = 0; ch < 4; ch++) tab.d[8+ch] = {off_w, 64, 0, 216, ch*64};
    tab.d[12] = {dcn_w, 64, 0, 64, 0};
    prep_all_kernel<<<dim3(144, 13), 256>>>(tab, Bg);

    // supp NCHW -> NHWC fp32 (feeds warp + dcn gathers)
    supp_nhwc_kernel<<<dim3(HWSZ/64, BB), 256>>>(supp, suppN);
    warp_nhwc_kernel<<<dim3(HWSZ/256, BB), 256>>>(suppN, flow, wH, wL);
    to_nhwc_kernel<<<dim3(HWSZ/256, BB), 256>>>(ref, rH, rL);

    dim3 cg(2, 256, 4);
    // fc (fused 18-tap): lrelu -> feat0 (f32 + hi/lo)
    conv_mma_kernel<1,1,1,18,1><<<cg, 256, SMB1>>>(wH, wL, rH, rL, Bg + 0*BSET, fc_b, 1, 64,
                                                   f0F, t0H, t0L, nullptr, nullptr);
    // c1: relu -> tmp
    conv_mma_kernel<1,2,1,9,1><<<cg, 256, SMB1>>>(t0H, t0L, nullptr, nullptr, Bg + 2*BSET, cb[0], 1, 64,
                                                  nullptr, tmpH, tmpL, nullptr, nullptr);
    // c2: ff = feat0 + relu(v)
    conv_mma_kernel<1,3,1,9,1><<<cg, 256, SMB1>>>(tmpH, tmpL, nullptr, nullptr, Bg + 3*BSET, cb[1], 1, 64,
                                                  ffF, nullptr, nullptr, f0F, nullptr);
    // c3 (dil2): relu -> tmp
    conv_mma_kernel<2,2,1,9,1><<<cg, 256, SMB2>>>(t0H, t0L, nullptr, nullptr, Bg + 4*BSET, cb[2], 1, 64,
                                                  nullptr, tmpH, tmpL, nullptr, nullptr);
    // c4 (dil2): ff += 0.1*relu(v)
    conv_mma_kernel<2,4,1,9,1><<<cg, 256, SMB2>>>(tmpH, tmpL, nullptr, nullptr, Bg + 5*BSET, cb[3], 1, 64,
                                                  ffF, nullptr, nullptr, nullptr, nullptr);
    // c5 (dil2): relu -> tmp
    conv_mma_kernel<2,2,1,9,1><<<cg, 256, SMB2>>>(t0H, t0L, nullptr, nullptr, Bg + 6*BSET, cb[4], 1, 64,
                                                  nullptr, tmpH, tmpL, nullptr, nullptr);
    // c6 (dil4): feat = ff + 0.1*relu(v) -> hi/lo
    conv_mma_kernel<4,5,1,9,1><<<cg, 256, SMB4>>>(tmpH, tmpL, nullptr, nullptr, Bg + 7*BSET, cb[5], 1, 64,
                                                  nullptr, ftH, ftL, ffF, nullptr);
    // offset conv: 216 couts via 2 fused chunk-pairs (128 couts/CTA), NCHW out
    dim3 og(2, 256, BB*2);
    conv_mma_kernel<1,6,1,9,2><<<og, 256, SMO>>>(ftH, ftL, nullptr, nullptr, Bg + 8*BSET, off_b, 2, 216,
                                                 nullptr, nullptr, nullptr, nullptr, offbuf);
    // tensorized deformable conv (fast transcendentals, occupancy 2)
    dcn_mma_kernel<<<cg, 256, SMD>>>(suppN, offbuf, flow, Bg + 12*BSET, dcn_b, out);
}

// round 15
// speedup vs baseline: 1.1692x; 1.0044x over previous
#include <cuda_runtime.h>
#include <cuda_bf16.h>
#include <math.h>
#include <stdint.h>

#define BB 4
#define HH 256
#define WW 256
#define HWSZ 65536
#define NPX (BB*HWSZ)

// ---------------------------------------------------------------------------
// PTX helpers (plain sm_103-safe: ldmatrix + mma.sync + cp.async)
// ---------------------------------------------------------------------------
__device__ __forceinline__ uint32_t smem_u32(const void* p) {
    uint32_t a;
    asm("{ .reg .u64 t; cvta.to.shared.u64 t, %1; cvt.u32.u64 %0, t; }" : "=r"(a) : "l"(p));
    return a;
}

#define LDSM_X4(r0, r1, r2, r3, addr) \
    asm volatile("ldmatrix.sync.aligned.m8n8.x4.shared.b16 {%0,%1,%2,%3}, [%4];" \
        : "=r"(r0), "=r"(r1), "=r"(r2), "=r"(r3) : "r"(addr))

#define MMA_BF16(d, a, b0v, b1v) \
    asm volatile("mma.sync.aligned.m16n8k16.row.col.f32.bf16.bf16.f32 " \
        "{%0,%1,%2,%3},{%4,%5,%6,%7},{%8,%9},{%0,%1,%2,%3};" \
        : "+f"((d)[0]), "+f"((d)[1]), "+f"((d)[2]), "+f"((d)[3]) \
        : "r"((a)[0]), "r"((a)[1]), "r"((a)[2]), "r"((a)[3]), "r"(b0v), "r"(b1v))

#define CP_ASYNC16(dst, src, sz) \
    asm volatile("cp.async.cg.shared.global [%0], [%1], 16, %2;" \
        :: "r"(dst), "l"(src), "r"(sz) : "memory")
#define CP_COMMIT() asm volatile("cp.async.commit_group;" ::: "memory")
#define CP_WAIT1() asm volatile("cp.async.wait_group 1;" ::: "memory")
#define CP_WAIT0() asm volatile("cp.async.wait_group 0;" ::: "memory")

// Fast transcendentals for DCN offsets. Clamp keeps exp finite; tanh(15)==1 in fp32.
__device__ __forceinline__ float fast_tanh(float x) {
    float xc = fminf(fmaxf(x, -15.f), 15.f);
    float e2 = __expf(2.f * xc);
    return __fdividef(e2 - 1.f, e2 + 1.f);
}
__device__ __forceinline__ float fast_sigmoid(float x) {
    return __fdividef(1.f, 1.f + __expf(-x));
}

// ---------------------------------------------------------------------------
// Device global scratch
// ---------------------------------------------------------------------------
#define FEAT_ELEMS ((size_t)NPX*64)
__device__ __nv_bfloat16 g_wH[FEAT_ELEMS], g_wL[FEAT_ELEMS];     // warped supp
__device__ __nv_bfloat16 g_rH[FEAT_ELEMS], g_rL[FEAT_ELEMS];     // ref
__device__ __nv_bfloat16 g_t0H[FEAT_ELEMS], g_t0L[FEAT_ELEMS];   // feat0
__device__ __nv_bfloat16 g_tmpH[FEAT_ELEMS], g_tmpL[FEAT_ELEMS];   // c1 / c3 out
__device__ __nv_bfloat16 g_tm2H[FEAT_ELEMS], g_tm2L[FEAT_ELEMS];   // c5 out
__device__ __nv_bfloat16 g_ftH[FEAT_ELEMS], g_ftL[FEAT_ELEMS];   // final feat
__device__ float g_f0F[FEAT_ELEMS];                               // feat0 fp32
__device__ float g_ffF[FEAT_ELEMS];                               // feat fp32 accum
__device__ float g_off[(size_t)BB*216*HWSZ];                      // NCHW
__device__ float g_sN[FEAT_ELEMS];                                // supp NHWC fp32
// 13 B-sets: 0,1 fc halves; 2 c1; 3 c2; 4 c3; 5 c5 (adjacent for NCH=2 fuse);
// 6 c4; 7 c6; 8-11 off chunks; 12 dcn. Each 9 taps x 16KB.
#define BSET 73728
__device__ __nv_bfloat16 g_B[13*BSET];

// ---------------------------------------------------------------------------
// Fused B prep: all 13 sets in one launch (blockIdx.y = set)
// ---------------------------------------------------------------------------
struct PrepDesc { const float* w; int cinTot, cin0, coutTot, cout0; };
struct PrepTable { PrepDesc d[13]; };

__global__ void prep_all_kernel(PrepTable tab, __nv_bfloat16* __restrict__ outB)
{
    int set = blockIdx.y;
    PrepDesc pd = tab.d[set];
    int idx = blockIdx.x * 256 + threadIdx.x;   // < 36864
    int c = idx & 63;
    int r = (idx >> 6) & 63;
    int t = idx >> 12;
    float v = 0.f;
    int co = pd.cout0 + r;
    if (co < pd.coutTot) v = pd.w[((size_t)co * pd.cinTot + pd.cin0 + c) * 9 + t];
    __nv_bfloat16 h = __float2bfloat16(v);
    __nv_bfloat16 l = __float2bfloat16(v - __bfloat162float(h));
    uint32_t off = (uint32_t)r * 128u + (uint32_t)c * 2u;
    uint32_t so = off ^ ((off >> 3) & 0x70u);
    char* ob = (char*)(outB + (size_t)set * BSET) + (size_t)t * 16384;
    *(__nv_bfloat16*)(ob + so) = h;
    *(__nv_bfloat16*)(ob + 8192 + so) = l;
}

// ---------------------------------------------------------------------------
// supp NCHW fp32 -> NHWC fp32 (smem-tiled transpose, 64px x 64ch per block)
// ---------------------------------------------------------------------------
__global__ void supp_nhwc_kernel(const float* __restrict__ src, float* __restrict__ dst)
{
    __shared__ float s[64 * 65];
    int b  = blockIdx.y;
    int x0 = blockIdx.x * 64;     // linear pixel base
    int tid = threadIdx.x;
    int lc = tid >> 6;            // 0..3
    int lp = tid & 63;
    #pragma unroll
    for (int i = 0; i < 16; i++) {
        int c = i * 4 + lc;
        s[lp * 65 + c] = src[((size_t)b * 64 + c) * HWSZ + x0 + lp];
    }
    __syncthreads();
    int px = tid >> 2, q4 = (tid & 3) * 16;
    float* dp = dst + ((size_t)b * HWSZ + x0 + px) * 64 + q4;
    const float* sp = s + px * 65 + q4;
    #pragma unroll
    for (int q = 0; q < 4; q++)
        ((float4*)dp)[q] = make_float4(sp[q*4], sp[q*4+1], sp[q*4+2], sp[q*4+3]);
}

// ---------------------------------------------------------------------------
// flow_warp (reads NHWC fp32 supp, vectorized corners) -> NHWC bf16 hi/lo
// ---------------------------------------------------------------------------
__global__ void warp_nhwc_kernel(const float* __restrict__ suppN, const float* __restrict__ flow,
                                 __nv_bfloat16* __restrict__ oH, __nv_bfloat16* __restrict__ oL)
{
    int p = blockIdx.x * 256 + threadIdx.x;
    int b = blockIdx.y;
    int y = p >> 8, x = p & 255;
    float fx = flow[((size_t)b*2    )*HWSZ + p];
    float fy = flow[((size_t)b*2 + 1)*HWSZ + p];
    float sy = (float)y + fy, sx = (float)x + fx;
    float y0f = floorf(sy), x0f = floorf(sx);
    int iy0 = (int)y0f, ix0 = (int)x0f, iy1 = iy0+1, ix1 = ix0+1;
    float wy = sy - y0f, wx = sx - x0f;
    bool vy0 = ((unsigned)iy0 < HH), vy1 = ((unsigned)iy1 < HH);
    bool vx0 = ((unsigned)ix0 < WW), vx1 = ((unsigned)ix1 < WW);
    float w00 = (1.f-wy)*(1.f-wx) * ((vy0&&vx0)?1.f:0.f);
    float w01 = (1.f-wy)*wx       * ((vy0&&vx1)?1.f:0.f);
    float w10 = wy*(1.f-wx)       * ((vy1&&vx0)?1.f:0.f);
    float w11 = wy*wx             * ((vy1&&vx1)?1.f:0.f);
    int cy0 = min(max(iy0,0),HH-1), cy1 = min(max(iy1,0),HH-1);
    int cx0 = min(max(ix0,0),WW-1), cx1 = min(max(ix1,0),WW-1);
    size_t i00 = (size_t)(cy0*WW+cx0)*64, i01 = (size_t)(cy0*WW+cx1)*64;
    size_t i10 = (size_t)(cy1*WW+cx0)*64, i11 = (size_t)(cy1*WW+cx1)*64;
    const float* sb = suppN + (size_t)b*HWSZ*64;
    __nv_bfloat16* ohp = oH + ((size_t)b*HWSZ + p)*64;
    __nv_bfloat16* olp = oL + ((size_t)b*HWSZ + p)*64;
    #pragma unroll 1
    for (int g = 0; g < 8; g++) {
        const float4* p00 = (const float4*)(sb + i00 + g*8);
        const float4* p01 = (const float4*)(sb + i01 + g*8);
        const float4* p10 = (const float4*)(sb + i10 + g*8);
        const float4* p11 = (const float4*)(sb + i11 + g*8);
        float v[8];
        #pragma unroll
        for (int h = 0; h < 2; h++) {
            float4 a = p00[h], bb = p01[h], cc = p10[h], dd = p11[h];
            v[h*4+0] = w00*a.x + w01*bb.x + w10*cc.x + w11*dd.x;
            v[h*4+1] = w00*a.y + w01*bb.y + w10*cc.y + w11*dd.y;
            v[h*4+2] = w00*a.z + w01*bb.z + w10*cc.z + w11*dd.z;
            v[h*4+3] = w00*a.w + w01*bb.w + w10*cc.w + w11*dd.w;
        }
        uint4 uh, ul;
        uint32_t* ph = (uint32_t*)&uh;
        uint32_t* pl = (uint32_t*)&ul;
        #pragma unroll
        for (int q = 0; q < 4; q++) {
            __nv_bfloat162 h2 = __floats2bfloat162_rn(v[q*2], v[q*2+1]);
            float2 hf = __bfloat1622float2(h2);
            __nv_bfloat162 l2 = __floats2bfloat162_rn(v[q*2] - hf.x, v[q*2+1] - hf.y);
            ph[q] = *(uint32_t*)&h2;
            pl[q] = *(uint32_t*)&l2;
        }
        ((uint4*)ohp)[g] = uh;
        ((uint4*)olp)[g] = ul;
    }
}

// NCHW fp32 -> NHWC bf16 hi/lo (ref)
__global__ void to_nhwc_kernel(const float* __restrict__ src,
                               __nv_bfloat16* __restrict__ oH, __nv_bfloat16* __restrict__ oL)
{
    int p = blockIdx.x * 256 + threadIdx.x;
    int b = blockIdx.y;
    const float* sp = src + (size_t)b*64*HWSZ + p;
    __nv_bfloat16* ohp = oH + ((size_t)b*HWSZ + p)*64;
    __nv_bfloat16* olp = oL + ((size_t)b*HWSZ + p)*64;
    for (int g = 0; g < 8; g++) {
        uint4 uh, ul;
        uint32_t* ph = (uint32_t*)&uh;
        uint32_t* pl = (uint32_t*)&ul;
        #pragma unroll
        for (int q = 0; q < 4; q++) {
            float v0 = sp[(size_t)(g*8 + q*2    )*HWSZ];
            float v1 = sp[(size_t)(g*8 + q*2 + 1)*HWSZ];
            __nv_bfloat162 h2 = __floats2bfloat162_rn(v0, v1);
            float2 hf = __bfloat1622float2(h2);
            __nv_bfloat162 l2 = __floats2bfloat162_rn(v0 - hf.x, v1 - hf.y);
            ph[q] = *(uint32_t*)&h2;
            pl[q] = *(uint32_t*)&l2;
        }
        ((uint4*)ohp)[g] = uh;
        ((uint4*)olp)[g] = ul;
    }
}

// ---------------------------------------------------------------------------
// mma.sync conv: single A buffer per ki group, double-buffered B (NCH chunk
// sets per tap), group-accounting wait invariant. NCH=1: 3 CTAs/SM (proven).
// NCH=2: 128 couts/CTA (or 2 fused layers), A staged once, 2 CTAs/SM.
// EPI 7: per-chunk relu->hi/lo; nc0 -> outH/outL (bias), nc1 -> outH2/outL2 (bias2).
// ---------------------------------------------------------------------------
template<int DIL, int EPI, int HASBIAS, int NT, int NCH>
__global__ void __launch_bounds__(256, (NCH == 2 ? 2 : 3))
conv_mma_kernel(const __nv_bfloat16* __restrict__ inH,
                const __nv_bfloat16* __restrict__ inL,
                const __nv_bfloat16* __restrict__ inH2,
                const __nv_bfloat16* __restrict__ inL2,
                const __nv_bfloat16* __restrict__ Bimg,
                const float* __restrict__ bias,
                const float* __restrict__ bias2,
                int nchunk, int coutTot,
                float* __restrict__ outF,
                __nv_bfloat16* __restrict__ outH,
                __nv_bfloat16* __restrict__ outL,
                __nv_bfloat16* __restrict__ outH2,
                __nv_bfloat16* __restrict__ outL2,
                const float* __restrict__ resF,
                float* __restrict__ outNCHW)
{
    constexpr uint32_t R = 128 + 2 * DIL;
    constexpr uint32_t AHALF = R * 128u;
    constexpr uint32_t ABUF = 2u * AHALF;
    constexpr uint32_t BSTEP = (uint32_t)NCH * 16384u;

    extern __shared__ char smem[];
    uint32_t base = (smem_u32(smem) + 1023u) & ~1023u;

    int tid = threadIdx.x;
    int lane = tid & 31, w = tid >> 5;
    int z = blockIdx.z;
    int b = z / nchunk, chunk = z - b * nchunk;
    int y = blockIdx.y, x0 = blockIdx.x * 128;

    const char* Bbase = (const char*)Bimg + (size_t)chunk * NCH * 147456;

    auto stageA = [&](int s) {
        int ki = (NT == 18 && s >= 3) ? s - 3 : s;
        const __nv_bfloat16* iH = (NT == 18 && s >= 3) ? inH2 : inH;
        const __nv_bfloat16* iL = (NT == 18 && s >= 3) ? inL2 : inL;
        int gy = y + (ki - 1) * DIL;
        bool rowok = ((unsigned)gy < HH);
        for (int i = tid; i < (int)(R * 8); i += 256) {
            int r = i >> 3, j = i & 7;
            int gx = x0 - DIL + r;
            bool ok = rowok && ((unsigned)gx < WW);
            size_t gidx = ok ? ((((size_t)b * HH + gy) * WW + gx) * 64) : 0;
            int sz = ok ? 16 : 0;
            uint32_t dst = base + (uint32_t)r * 128u +
                           (((uint32_t)j * 16u) ^ (((uint32_t)r & 7u) * 16u));
            CP_ASYNC16(dst, (const char*)(iH + gidx) + j * 16, sz);
            CP_ASYNC16(dst + AHALF, (const char*)(iL + gidx) + j * 16, sz);
        }
    };
    auto stageB = [&](int t2) {
        uint32_t bB = base + ABUF + (uint32_t)(t2 & 1) * BSTEP;
        #pragma unroll
        for (int nc = 0; nc < NCH; nc++) {
            const char* bsrc = Bbase + (size_t)nc * 147456 + (size_t)t2 * 16384;
            #pragma unroll
            for (int kk = 0; kk < 4; kk++)
                CP_ASYNC16(bB + (uint32_t)nc * 16384u + (uint32_t)tid * 16u + (uint32_t)kk * 4096u,
                           bsrc + tid * 16 + kk * 4096, 16);
        }
    };

    stageA(0);
    stageB(0);
    CP_COMMIT();

    int mbase = (w & 3) * 32;
    int nbase = (w >> 2) * 32;

    float acc[NCH][2][4][4];
    #pragma unroll
    for (int nc = 0; nc < NCH; nc++)
        #pragma unroll
        for (int i = 0; i < 2; i++)
            #pragma unroll
            for (int j = 0; j < 4; j++)
                #pragma unroll
                for (int q = 0; q < 4; q++) acc[nc][i][j][q] = 0.f;

    int lr = (lane & 7) + ((lane >> 3) & 1) * 8;
    int kq = (lane >> 4) * 16;

    #pragma unroll 1
    for (int tt = 0; tt < NT; tt++) {
        if (tt + 1 < NT && (tt + 1) % 3 != 0) {
            stageB(tt + 1);
            CP_COMMIT();
            CP_WAIT1();
        } else {
            CP_WAIT0();
        }
        __syncthreads();

        int s = tt / 3, kj = tt - s * 3;
        uint32_t Bt = base + ABUF + (uint32_t)(tt & 1) * BSTEP;
        uint32_t rowA0 = (uint32_t)(kj * DIL + mbase + lr);
        uint32_t rowB0 = (uint32_t)(nbase + lr);

        #pragma unroll
        for (int ks = 0; ks < 4; ks++) {
            uint32_t kb = (uint32_t)(ks * 32 + kq);
            uint32_t ah0[4], ah1[4], al0[4], al1[4];
            {
                uint32_t r0 = rowA0, r1 = rowA0 + 16u;
                uint32_t o0 = r0*128u + (kb ^ ((r0 & 7u)*16u));
                uint32_t o1 = r1*128u + (kb ^ ((r1 & 7u)*16u));
                LDSM_X4(ah0[0], ah0[1], ah0[2], ah0[3], base + o0);
                LDSM_X4(ah1[0], ah1[1], ah1[2], ah1[3], base + o1);
                LDSM_X4(al0[0], al0[1], al0[2], al0[3], base + AHALF + o0);
                LDSM_X4(al1[0], al1[1], al1[2], al1[3], base + AHALF + o1);
            }
            #pragma unroll
            for (int nc = 0; nc < NCH; nc++) {
                uint32_t Bc = Bt + (uint32_t)nc * 16384u;
                uint32_t bh0[4], bh1[4], bl0[4], bl1[4];
                uint32_t r0 = rowB0, r1 = rowB0 + 16u;
                uint32_t o0 = r0*128u + (kb ^ ((r0 & 7u)*16u));
                uint32_t o1 = r1*128u + (kb ^ ((r1 & 7u)*16u));
                LDSM_X4(bh0[0], bh0[1], bh0[2], bh0[3], Bc + o0);
                LDSM_X4(bh1[0], bh1[1], bh1[2], bh1[3], Bc + o1);
                LDSM_X4(bl0[0], bl0[1], bl0[2], bl0[3], Bc + 8192u + o0);
                LDSM_X4(bl1[0], bl1[1], bl1[2], bl1[3], Bc + 8192u + o1);
                MMA_BF16(acc[nc][0][0], ah0, bh0[0], bh0[2]);
                MMA_BF16(acc[nc][0][1], ah0, bh0[1], bh0[3]);
                MMA_BF16(acc[nc][0][2], ah0, bh1[0], bh1[2]);
                MMA_BF16(acc[nc][0][3], ah0, bh1[1], bh1[3]);
                MMA_BF16(acc[nc][1][0], ah1, bh0[0], bh0[2]);
                MMA_BF16(acc[nc][1][1], ah1, bh0[1], bh0[3]);
                MMA_BF16(acc[nc][1][2], ah1, bh1[0], bh1[2]);
                MMA_BF16(acc[nc][1][3], ah1, bh1[1], bh1[3]);
                MMA_BF16(acc[nc][0][0], ah0, bl0[0], bl0[2]);
                MMA_BF16(acc[nc][0][1], ah0, bl0[1], bl0[3]);
                MMA_BF16(acc[nc][0][2], ah0, bl1[0], bl1[2]);
                MMA_BF16(acc[nc][0][3], ah0, bl1[1], bl1[3]);
                MMA_BF16(acc[nc][1][0], ah1, bl0[0], bl0[2]);
                MMA_BF16(acc[nc][1][1], ah1, bl0[1], bl0[3]);
                MMA_BF16(acc[nc][1][2], ah1, bl1[0], bl1[2]);
                MMA_BF16(acc[nc][1][3], ah1, bl1[1], bl1[3]);
                MMA_BF16(acc[nc][0][0], al0, bh0[0], bh0[2]);
                MMA_BF16(acc[nc][0][1], al0, bh0[1], bh0[3]);
                MMA_BF16(acc[nc][0][2], al0, bh1[0], bh1[2]);
                MMA_BF16(acc[nc][0][3], al0, bh1[1], bh1[3]);
                MMA_BF16(acc[nc][1][0], al1, bh0[0], bh0[2]);
                MMA_BF16(acc[nc][1][1], al1, bh0[1], bh0[3]);
                MMA_BF16(acc[nc][1][2], al1, bh1[0], bh1[2]);
                MMA_BF16(acc[nc][1][3], al1, bh1[1], bh1[3]);
            }
        }
        __syncthreads();

        if (tt + 1 < NT && (tt + 1) % 3 == 0) {
            stageA((tt + 1) / 3);
            stageB(tt + 1);
            CP_COMMIT();
        }
    }

    // ---- epilogue ----
    #pragma unroll
    for (int nc = 0; nc < NCH; nc++) {
        const float* bp = (EPI == 7 && nc == 1) ? bias2 : bias;
        float bs2[4][2];
        #pragma unroll
        for (int nb = 0; nb < 4; nb++) {
            int co = (EPI == 7) ? (nbase + nb * 8 + (lane & 3) * 2)
                                : ((chunk * NCH + nc) * 64 + nbase + nb * 8 + (lane & 3) * 2);
            bs2[nb][0] = (HASBIAS && co     < coutTot) ? bp[co]     : 0.f;
            bs2[nb][1] = (HASBIAS && co + 1 < coutTot) ? bp[co + 1] : 0.f;
        }
        #pragma unroll
        for (int mt = 0; mt < 2; mt++) {
            #pragma unroll
            for (int rh = 0; rh < 2; rh++) {
                int px = x0 + mbase + mt * 16 + (lane >> 2) + rh * 8;
                size_t P = ((size_t)b * HH + y) * WW + px;
                #pragma unroll
                for (int nb = 0; nb < 4; nb++) {
                    int cl = nbase + nb * 8 + (lane & 3) * 2;
                    float v0 = acc[nc][mt][nb][rh * 2 + 0] + bs2[nb][0];
                    float v1 = acc[nc][mt][nb][rh * 2 + 1] + bs2[nb][1];
                    size_t ob = P * 64 + cl;

                    if (EPI == 1) {
                        v0 = (v0 > 0.f) ? v0 : 0.1f * v0;
                        v1 = (v1 > 0.f) ? v1 : 0.1f * v1;
                        *(float2*)(outF + ob) = make_float2(v0, v1);
                        __nv_bfloat162 h2 = __floats2bfloat162_rn(v0, v1);
                        float2 hf = __bfloat1622float2(h2);
                        __nv_bfloat162 l2 = __floats2bfloat162_rn(v0 - hf.x, v1 - hf.y);
                        *(uint32_t*)(outH + ob) = *(uint32_t*)&h2;
                        *(uint32_t*)(outL + ob) = *(uint32_t*)&l2;
                    } else if (EPI == 2) {
                        v0 = fmaxf(v0, 0.f); v1 = fmaxf(v1, 0.f);
                        __nv_bfloat162 h2 = __floats2bfloat162_rn(v0, v1);
                        float2 hf = __bfloat1622float2(h2);
                        __nv_bfloat162 l2 = __floats2bfloat162_rn(v0 - hf.x, v1 - hf.y);
                        *(uint32_t*)(outH + ob) = *(uint32_t*)&h2;
                        *(uint32_t*)(outL + ob) = *(uint32_t*)&l2;
                    } else if (EPI == 3) {
                        float2 rv = *(const float2*)(resF + ob);
                        v0 = rv.x + fmaxf(v0, 0.f);
                        v1 = rv.y + fmaxf(v1, 0.f);
                        *(float2*)(outF + ob) = make_float2(v0, v1);
                    } else if (EPI == 4) {
                        float2 rv = *(const float2*)(outF + ob);
                        v0 = rv.x + 0.1f * fmaxf(v0, 0.f);
                        v1 = rv.y + 0.1f * fmaxf(v1, 0.f);
                        *(float2*)(outF + ob) = make_float2(v0, v1);
                    } else if (EPI == 5) {
                        float2 rv = *(const float2*)(resF + ob);
                        v0 = rv.x + 0.1f * fmaxf(v0, 0.f);
                        v1 = rv.y + 0.1f * fmaxf(v1, 0.f);
                        __nv_bfloat162 h2 = __floats2bfloat162_rn(v0, v1);
                        float2 hf = __bfloat1622float2(h2);
                        __nv_bfloat162 l2 = __floats2bfloat162_rn(v0 - hf.x, v1 - hf.y);
                        *(uint32_t*)(outH + ob) = *(uint32_t*)&h2;
                        *(uint32_t*)(outL + ob) = *(uint32_t*)&l2;
                    } else if (EPI == 6) {
                        int co = (chunk * NCH + nc) * 64 + cl;
                        size_t pix = ((size_t)y << 8) + px;
                        if (co < coutTot)
                            outNCHW[(((size_t)b * coutTot + co) << 16) + pix] = v0;
                        if (co + 1 < coutTot)
                            outNCHW[(((size_t)b * coutTot + co + 1) << 16) + pix] = v1;
                    } else if (EPI == 7) {
                        v0 = fmaxf(v0, 0.f); v1 = fmaxf(v1, 0.f);
                        __nv_bfloat16* oh = (nc == 0) ? outH : outH2;
                        __nv_bfloat16* ol = (nc == 0) ? outL : outL2;
                        __nv_bfloat162 h2 = __floats2bfloat162_rn(v0, v1);
                        float2 hf = __bfloat1622float2(h2);
                        __nv_bfloat162 l2 = __floats2bfloat162_rn(v0 - hf.x, v1 - hf.y);
                        *(uint32_t*)(oh + ob) = *(uint32_t*)&h2;
                        *(uint32_t*)(ol + ob) = *(uint32_t*)&l2;
                    }
                }
            }
        }
    }
}

// ---------------------------------------------------------------------------
// Modulated deformable conv, tensorized; NHWC fp32 gathers + fast
// transcendentals; occupancy 2 (occ-3 reg-caps spill the sampler).
// ---------------------------------------------------------------------------
__global__ void __launch_bounds__(256, 2)
dcn_mma_kernel(const float* __restrict__ suppN, const float* __restrict__ off,
               const float* __restrict__ flow, const __nv_bfloat16* __restrict__ Bimg,
               const float* __restrict__ bias, float* __restrict__ out)
{
    extern __shared__ char smem[];
    uint32_t base = (smem_u32(smem) + 1023u) & ~1023u;
    const uint32_t SM_S = base;            // 32KB: hi 16K | lo 16K
    const uint32_t SM_Bd = base + 32768u;  // 2 x 16KB B double buffer

    int tid = threadIdx.x;
    int lane = tid & 31, w = tid >> 5;
    int b = blockIdx.z, y = blockIdx.y, x0 = blockIdx.x * 128;

    #pragma unroll
    for (int kk = 0; kk < 4; kk++)
        CP_ASYNC16(SM_Bd + (uint32_t)tid * 16u + (uint32_t)kk * 4096u,
                   (const char*)Bimg + tid * 16 + kk * 4096, 16);
    CP_COMMIT();

    int mbase = (w & 3) * 32;
    int nbase = (w >> 2) * 32;
    float acc[2][4][4];
    #pragma unroll
    for (int i = 0; i < 2; i++)
        #pragma unroll
        for (int j = 0; j < 4; j++)
            #pragma unroll
            for (int q = 0; q < 4; q++) acc[i][j][q] = 0.f;

    int lr = (lane & 7) + ((lane >> 3) & 1) * 8;
    int kq = (lane >> 4) * 16;

    const float* fxp  = flow + ((size_t)b*2 + 0)*HWSZ + y*WW + x0;
    const float* fyp  = flow + ((size_t)b*2 + 1)*HWSZ + y*WW + x0;
    const float* offb = off  + (size_t)b*216*HWSZ + y*WW + x0;
    const float* sb   = suppN + (size_t)b*HWSZ*64;

    #pragma unroll 1
    for (int k = 0; k < 9; k++) {
        if (k < 8) {
            const char* bsrc = (const char*)Bimg + (size_t)(k + 1) * 16384;
            uint32_t bB = SM_Bd + (uint32_t)((k + 1) & 1) * 16384u;
            #pragma unroll
            for (int kk = 0; kk < 4; kk++)
                CP_ASYNC16(bB + (uint32_t)tid * 16u + (uint32_t)kk * 4096u,
                           bsrc + tid * 16 + kk * 4096, 16);
            CP_COMMIT();
        }

        int ki = k / 3, kj = k - ki * 3;
        #pragma unroll 1
        for (int it = 0; it < 4; it++) {
            int task = tid + it * 256;
            int px = task & 127;
            int g  = task >> 7;
            int cdy = g*18 + k*2;
            float rawdy = offb[(size_t)cdy          *HWSZ + px];
            float rawdx = offb[(size_t)(cdy + 1)    *HWSZ + px];
            float rawm  = offb[(size_t)(144 + g*9+k)*HWSZ + px];
            float fx = fxp[px], fy = fyp[px];
            float ady = 25.f * fast_tanh(rawdy) + ((cdy     < 72) ? fx : fy);
            float adx = 25.f * fast_tanh(rawdx) + ((cdy + 1 < 72) ? fx : fy);
            float m   = fast_sigmoid(rawm);
            float sy = (float)y         + (float)(ki - 1) + ady;
            float sx = (float)(x0 + px) + (float)(kj - 1) + adx;
            float y0f = floorf(sy), x0f = floorf(sx);
            int iy0 = (int)y0f, ix0 = (int)x0f;
            int iy1 = iy0 + 1,  ix1 = ix0 + 1;
            float wy = sy - y0f, wx = sx - x0f;
            bool vy0 = ((unsigned)iy0 < HH), vy1 = ((unsigned)iy1 < HH);
            bool vx0 = ((unsigned)ix0 < WW), vx1 = ((unsigned)ix1 < WW);
            float w00 = (1.f - wy)*(1.f - wx) * ((vy0 && vx0) ? 1.f : 0.f) * m;
            float w01 = (1.f - wy)*wx         * ((vy0 && vx1) ? 1.f : 0.f) * m;
            float w10 = wy*(1.f - wx)         * ((vy1 && vx0) ? 1.f : 0.f) * m;
            float w11 = wy*wx                 * ((vy1 && vx1) ? 1.f : 0.f) * m;
            int cy0 = min(max(iy0, 0), HH-1), cy1 = min(max(iy1, 0), HH-1);
            int cx0 = min(max(ix0, 0), WW-1), cx1 = min(max(ix1, 0), WW-1);
            const float4* p00 = (const float4*)(sb + (size_t)(cy0*WW + cx0)*64 + g*8);
            const float4* p01 = (const float4*)(sb + (size_t)(cy0*WW + cx1)*64 + g*8);
            const float4* p10 = (const float4*)(sb + (size_t)(cy1*WW + cx0)*64 + g*8);
            const float4* p11 = (const float4*)(sb + (size_t)(cy1*WW + cx1)*64 + g*8);
            float v[8];
            #pragma unroll
            for (int h = 0; h < 2; h++) {
                float4 a = p00[h], bb = p01[h], cc = p10[h], dd = p11[h];
                v[h*4+0] = w00*a.x + w01*bb.x + w10*cc.x + w11*dd.x;
                v[h*4+1] = w00*a.y + w01*bb.y + w10*cc.y + w11*dd.y;
                v[h*4+2] = w00*a.z + w01*bb.z + w10*cc.z + w11*dd.z;
                v[h*4+3] = w00*a.w + w01*bb.w + w10*cc.w + w11*dd.w;
            }
            uint32_t hpk[4], lpk[4];
            #pragma unroll
            for (int q = 0; q < 4; q++) {
                __nv_bfloat162 h2 = __floats2bfloat162_rn(v[q*2], v[q*2+1]);
                float2 hf = __bfloat1622float2(h2);
                __nv_bfloat162 l2 = __floats2bfloat162_rn(v[q*2] - hf.x, v[q*2+1] - hf.y);
                hpk[q] = *(uint32_t*)&h2;
                lpk[q] = *(uint32_t*)&l2;
            }
            uint32_t so = (uint32_t)px * 128u +
                          (((uint32_t)g * 16u) ^ (((uint32_t)px & 7u) * 16u));
            asm volatile("st.shared.v4.b32 [%0], {%1,%2,%3,%4};"
                :: "r"(SM_S + so), "r"(hpk[0]), "r"(hpk[1]), "r"(hpk[2]), "r"(hpk[3]) : "memory");
            asm volatile("st.shared.v4.b32 [%0], {%1,%2,%3,%4};"
                :: "r"(SM_S + 16384u + so), "r"(lpk[0]), "r"(lpk[1]), "r"(lpk[2]), "r"(lpk[3]) : "memory");
        }

        if (k < 8) CP_WAIT1(); else CP_WAIT0();
        __syncthreads();

        uint32_t Bt = SM_Bd + (uint32_t)(k & 1) * 16384u;
        uint32_t rowA0 = (uint32_t)(mbase + lr);
        uint32_t rowB0 = (uint32_t)(nbase + lr);
        #pragma unroll
        for (int ks = 0; ks < 4; ks++) {
            uint32_t kb = (uint32_t)(ks * 32 + kq);
            uint32_t ah0[4], ah1[4], al0[4], al1[4];
            uint32_t bh0[4], bh1[4], bl0[4], bl1[4];
            {
                uint32_t r0 = rowA0, r1 = rowA0 + 16u;
                uint32_t o0 = r0*128u + (kb ^ ((r0 & 7u)*16u));
                uint32_t o1 = r1*128u + (kb ^ ((r1 & 7u)*16u));
                LDSM_X4(ah0[0], ah0[1], ah0[2], ah0[3], SM_S + o0);
                LDSM_X4(ah1[0], ah1[1], ah1[2], ah1[3], SM_S + o1);
                LDSM_X4(al0[0], al0[1], al0[2], al0[3], SM_S + 16384u + o0);
                LDSM_X4(al1[0], al1[1], al1[2], al1[3], SM_S + 16384u + o1);
            }
            {
                uint32_t r0 = rowB0, r1 = rowB0 + 16u;
                uint32_t o0 = r0*128u + (kb ^ ((r0 & 7u)*16u));
                uint32_t o1 = r1*128u + (kb ^ ((r1 & 7u)*16u));
                LDSM_X4(bh0[0], bh0[1], bh0[2], bh0[3], Bt + o0);
                LDSM_X4(bh1[0], bh1[1], bh1[2], bh1[3], Bt + o1);
                LDSM_X4(bl0[0], bl0[1], bl0[2], bl0[3], Bt + 8192u + o0);
                LDSM_X4(bl1[0], bl1[1], bl1[2], bl1[3], Bt + 8192u + o1);
            }
            MMA_BF16(acc[0][0], ah0, bh0[0], bh0[2]);
            MMA_BF16(acc[0][1], ah0, bh0[1], bh0[3]);
            MMA_BF16(acc[0][2], ah0, bh1[0], bh1[2]);
            MMA_BF16(acc[0][3], ah0, bh1[1], bh1[3]);
            MMA_BF16(acc[1][0], ah1, bh0[0], bh0[2]);
            MMA_BF16(acc[1][1], ah1, bh0[1], bh0[3]);
            MMA_BF16(acc[1][2], ah1, bh1[0], bh1[2]);
            MMA_BF16(acc[1][3], ah1, bh1[1], bh1[3]);
            MMA_BF16(acc[0][0], ah0, bl0[0], bl0[2]);
            MMA_BF16(acc[0][1], ah0, bl0[1], bl0[3]);
            MMA_BF16(acc[0][2], ah0, bl1[0], bl1[2]);
            MMA_BF16(acc[0][3], ah0, bl1[1], bl1[3]);
            MMA_BF16(acc[1][0], ah1, bl0[0], bl0[2]);
            MMA_BF16(acc[1][1], ah1, bl0[1], bl0[3]);
            MMA_BF16(acc[1][2], ah1, bl1[0], bl1[2]);
            MMA_BF16(acc[1][3], ah1, bl1[1], bl1[3]);
            MMA_BF16(acc[0][0], al0, bh0[0], bh0[2]);
            MMA_BF16(acc[0][1], al0, bh0[1], bh0[3]);
            MMA_BF16(acc[0][2], al0, bh1[0], bh1[2]);
            MMA_BF16(acc[0][3], al0, bh1[1], bh1[3]);
            MMA_BF16(acc[1][0], al1, bh0[0], bh0[2]);
            MMA_BF16(acc[1][1], al1, bh0[1], bh0[3]);
            MMA_BF16(acc[1][2], al1, bh1[0], bh1[2]);
            MMA_BF16(acc[1][3], al1, bh1[1], bh1[3]);
        }
        __syncthreads();
    }

    // ---- epilogue: bias + NCHW fp32 store ----
    float bs2[4][2];
    #pragma unroll
    for (int nb = 0; nb < 4; nb++) {
        int co = nbase + nb * 8 + (lane & 3) * 2;
        bs2[nb][0] = bias[co];
        bs2[nb][1] = bias[co + 1];
    }
    #pragma unroll
    for (int mt = 0; mt < 2; mt++) {
        #pragma unroll
        for (int rh = 0; rh < 2; rh++) {
            int px = x0 + mbase + mt * 16 + (lane >> 2) + rh * 8;
            size_t pix = ((size_t)y << 8) + px;
            #pragma unroll
            for (int nb = 0; nb < 4; nb++) {
                int co = nbase + nb * 8 + (lane & 3) * 2;
                out[(((size_t)b * 64 + co    ) << 16) + pix] = acc[mt][nb][rh*2+0] + bs2[nb][0];
                out[(((size_t)b * 64 + co + 1) << 16) + pix] = acc[mt][nb][rh*2+1] + bs2[nb][1];
            }
        }
    }
}

// ---------------------------------------------------------------------------
// Launch
// ---------------------------------------------------------------------------
extern "C" void kernel_launch(void* const* d_in, const int* in_sizes, int n_in,
                              void* d_out, int out_size)
{
    const float* ref   = (const float*)d_in[0];
    const float* supp  = (const float*)d_in[1];
    const float* flow  = (const float*)d_in[2];
    const float* fc_w  = (const float*)d_in[3];
    const float* fc_b  = (const float*)d_in[4];
    const float* cw[6], *cb[6];
    for (int i = 0; i < 6; i++) {
        cw[i] = (const float*)d_in[5 + 2*i];
        cb[i] = (const float*)d_in[6 + 2*i];
    }
    const float* off_w = (const float*)d_in[17];
    const float* off_b = (const float*)d_in[18];
    const float* dcn_w = (const float*)d_in[19];
    const float* dcn_b = (const float*)d_in[20];
    float* out = (float*)d_out;

    __nv_bfloat16 *wH, *wL, *rH, *rL, *t0H, *t0L, *tmpH, *tmpL, *tm2H, *tm2L, *ftH, *ftL, *Bg;
    float *f0F, *ffF, *offbuf, *suppN;
    cudaGetSymbolAddress((void**)&wH,  g_wH);   cudaGetSymbolAddress((void**)&wL,  g_wL);
    cudaGetSymbolAddress((void**)&rH,  g_rH);   cudaGetSymbolAddress((void**)&rL,  g_rL);
    cudaGetSymbolAddress((void**)&t0H, g_t0H);  cudaGetSymbolAddress((void**)&t0L, g_t0L);
    cudaGetSymbolAddress((void**)&tmpH,g_tmpH); cudaGetSymbolAddress((void**)&tmpL,g_tmpL);
    cudaGetSymbolAddress((void**)&tm2H,g_tm2H); cudaGetSymbolAddress((void**)&tm2L,g_tm2L);
    cudaGetSymbolAddress((void**)&ftH, g_ftH);  cudaGetSymbolAddress((void**)&ftL, g_ftL);
    cudaGetSymbolAddress((void**)&Bg,  g_B);
    cudaGetSymbolAddress((void**)&f0F,   g_f0F);
    cudaGetSymbolAddress((void**)&ffF,   g_ffF);
    cudaGetSymbolAddress((void**)&offbuf,g_off);
    cudaGetSymbolAddress((void**)&suppN, g_sN);

    // smem: pad + single A (2*(128+2d)*128) + 2*NCH*16KB B
    const int SMB1 = 1024 + 2*(130*128) + 32768;   // 67072 (NCH=1, d=1)
    const int SMB2 = 1024 + 2*(132*128) + 32768;   // 67584 (NCH=1, d=2)
    const int SMB4 = 1024 + 2*(136*128) + 32768;   // 68608 (NCH=1, d=4)
    const int SMO  = 1024 + 2*(130*128) + 65536;   // 99840 (NCH=2, d=1)
    const int SMC  = 1024 + 2*(132*128) + 65536;   // 100352 (NCH=2, d=2)
    const int SMD  = 1024 + 32768 + 32768;         // 66560
    cudaFuncSetAttribute((const void*)conv_mma_kernel<1,1,1,18,1>, cudaFuncAttributeMaxDynamicSharedMemorySize, SMB1);
    cudaFuncSetAttribute((const void*)conv_mma_kernel<1,2,1,9,1>,  cudaFuncAttributeMaxDynamicSharedMemorySize, SMB1);
    cudaFuncSetAttribute((const void*)conv_mma_kernel<1,3,1,9,1>,  cudaFuncAttributeMaxDynamicSharedMemorySize, SMB1);
    cudaFuncSetAttribute((const void*)conv_mma_kernel<2,7,1,9,2>,  cudaFuncAttributeMaxDynamicSharedMemorySize, SMC);
    cudaFuncSetAttribute((const void*)conv_mma_kernel<2,4,1,9,1>,  cudaFuncAttributeMaxDynamicSharedMemorySize, SMB2);
    cudaFuncSetAttribute((const void*)conv_mma_kernel<4,5,1,9,1>,  cudaFuncAttributeMaxDynamicSharedMemorySize, SMB4);
    cudaFuncSetAttribute((const void*)conv_mma_kernel<1,6,1,9,2>,  cudaFuncAttributeMaxDynamicSharedMemorySize, SMO);
    cudaFuncSetAttribute((const void*)dcn_mma_kernel, cudaFuncAttributeMaxDynamicSharedMemorySize, SMD);

    // Fused weight prep (13 sets; c3,c5 adjacent at 4,5 for NCH=2 fusion)
    PrepTable tab;
    tab.d[0]  = {fc_w, 128, 0,  64, 0};
    tab.d[1]  = {fc_w, 128, 64, 64, 0};
    tab.d[2]  = {cw[0], 64, 0, 64, 0};   // c1
    tab.d[3]  = {cw[1], 64, 0, 64, 0};   // c2
    tab.d[4]  = {cw[2], 64, 0, 64, 0};   // c3
    tab.d[5]  = {cw[4], 64, 0, 64, 0};   // c5 (adjacent to c3)
    tab.d[6]  = {cw[3], 64, 0, 64, 0};   // c4
    tab.d[7]  = {cw[5], 64, 0, 64, 0};   // c6
    for (int ch = 0; ch < 4; ch++) tab.d[8+ch] = {off_w, 64, 0, 216, ch*64};
    tab.d[12] = {dcn_w, 64, 0, 64, 0};
    prep_all_kernel<<<dim3(144, 13), 256>>>(tab, Bg);

    // supp NCHW -> NHWC fp32 (feeds warp + dcn gathers)
    supp_nhwc_kernel<<<dim3(HWSZ/64, BB), 256>>>(supp, suppN);
    warp_nhwc_kernel<<<dim3(HWSZ/256, BB), 256>>>(suppN, flow, wH, wL);
    to_nhwc_kernel<<<dim3(HWSZ/256, BB), 256>>>(ref, rH, rL);

    dim3 cg(2, 256, 4);
    // fc (fused 18-tap): lrelu -> feat0 (f32 + hi/lo)
    conv_mma_kernel<1,1,1,18,1><<<cg, 256, SMB1>>>(wH, wL, rH, rL, Bg + 0*BSET, fc_b, nullptr, 1, 64,
                                                   f0F, t0H, t0L, nullptr, nullptr, nullptr, nullptr);
    // c1: relu -> tmp
    conv_mma_kernel<1,2,1,9,1><<<cg, 256, SMB1>>>(t0H, t0L, nullptr, nullptr, Bg + 2*BSET, cb[0], nullptr, 1, 64,
                                                  nullptr, tmpH, tmpL, nullptr, nullptr, nullptr, nullptr);
    // c2: ff = feat0 + relu(v)
    conv_mma_kernel<1,3,1,9,1><<<cg, 256, SMB1>>>(tmpH, tmpL, nullptr, nullptr, Bg + 3*BSET, cb[1], nullptr, 1, 64,
                                                  ffF, nullptr, nullptr, nullptr, nullptr, f0F, nullptr);
    // c3+c5 fused (dil2, NCH=2, same input feat0): relu -> tmp (c3), tm2 (c5)
    conv_mma_kernel<2,7,1,9,2><<<cg, 256, SMC>>>(t0H, t0L, nullptr, nullptr, Bg + 4*BSET, cb[2], cb[4], 1, 64,
                                                 nullptr, tmpH, tmpL, tm2H, tm2L, nullptr, nullptr);
    // c4 (dil2): ff += 0.1*relu(v)  [reads c3 out = tmp]
    conv_mma_kernel<2,4,1,9,1><<<cg, 256, SMB2>>>(tmpH, tmpL, nullptr, nullptr, Bg + 6*BSET, cb[3], nullptr, 1, 64,
                                                  ffF, nullptr, nullptr, nullptr, nullptr, nullptr, nullptr);
    // c6 (dil4): feat = ff + 0.1*relu(v) -> hi/lo  [reads c5 out = tm2]
    conv_mma_kernel<4,5,1,9,1><<<cg, 256, SMB4>>>(tm2H, tm2L, nullptr, nullptr, Bg + 7*BSET, cb[5], nullptr, 1, 64,
                                                  nullptr, ftH, ftL, nullptr, nullptr, ffF, nullptr);
    // offset conv: 216 couts via 2 fused chunk-pairs (128 couts/CTA), NCHW out
    dim3 og(2, 256, BB*2);
    conv_mma_kernel<1,6,1,9,2><<<og, 256, SMO>>>(ftH, ftL, nullptr, nullptr, Bg + 8*BSET, off_b, nullptr, 2, 216,
                                                 nullptr, nullptr, nullptr, nullptr, nullptr, nullptr, offbuf);
    // tensorized deformable conv (fast transcendentals, occupancy 2)
    dcn_mma_kernel<<<cg, 256, SMD>>>(suppN, offbuf, flow, Bg + 12*BSET, dcn_b, out);
}

// round 16
// speedup vs baseline: 1.1878x; 1.0159x over previous
#include <cuda_runtime.h>
#include <cuda_bf16.h>
#include <math.h>
#include <stdint.h>

#define BB 4
#define HH 256
#define WW 256
#define HWSZ 65536
#define NPX (BB*HWSZ)

// ---------------------------------------------------------------------------
// PTX helpers (plain sm_103-safe: ldmatrix + mma.sync + cp.async)
// ---------------------------------------------------------------------------
__device__ __forceinline__ uint32_t smem_u32(const void* p) {
    uint32_t a;
    asm("{ .reg .u64 t; cvta.to.shared.u64 t, %1; cvt.u32.u64 %0, t; }" : "=r"(a) : "l"(p));
    return a;
}

#define LDSM_X4(r0, r1, r2, r3, addr) \
    asm volatile("ldmatrix.sync.aligned.m8n8.x4.shared.b16 {%0,%1,%2,%3}, [%4];" \
        : "=r"(r0), "=r"(r1), "=r"(r2), "=r"(r3) : "r"(addr))

#define MMA_BF16(d, a, b0v, b1v) \
    asm volatile("mma.sync.aligned.m16n8k16.row.col.f32.bf16.bf16.f32 " \
        "{%0,%1,%2,%3},{%4,%5,%6,%7},{%8,%9},{%0,%1,%2,%3};" \
        : "+f"((d)[0]), "+f"((d)[1]), "+f"((d)[2]), "+f"((d)[3]) \
        : "r"((a)[0]), "r"((a)[1]), "r"((a)[2]), "r"((a)[3]), "r"(b0v), "r"(b1v))

#define CP_ASYNC16(dst, src, sz) \
    asm volatile("cp.async.cg.shared.global [%0], [%1], 16, %2;" \
        :: "r"(dst), "l"(src), "r"(sz) : "memory")
#define CP_COMMIT() asm volatile("cp.async.commit_group;" ::: "memory")
#define CP_WAIT1() asm volatile("cp.async.wait_group 1;" ::: "memory")
#define CP_WAIT0() asm volatile("cp.async.wait_group 0;" ::: "memory")

// Fast transcendentals for DCN offsets. Clamp keeps exp finite; tanh(15)==1 in fp32.
__device__ __forceinline__ float fast_tanh(float x) {
    float xc = fminf(fmaxf(x, -15.f), 15.f);
    float e2 = __expf(2.f * xc);
    return __fdividef(e2 - 1.f, e2 + 1.f);
}
__device__ __forceinline__ float fast_sigmoid(float x) {
    return __fdividef(1.f, 1.f + __expf(-x));
}

// ---------------------------------------------------------------------------
// Device global scratch
// ---------------------------------------------------------------------------
#define FEAT_ELEMS ((size_t)NPX*64)
__device__ __nv_bfloat16 g_wH[FEAT_ELEMS], g_wL[FEAT_ELEMS];     // warped supp
__device__ __nv_bfloat16 g_rH[FEAT_ELEMS], g_rL[FEAT_ELEMS];     // ref
__device__ __nv_bfloat16 g_t0H[FEAT_ELEMS], g_t0L[FEAT_ELEMS];   // feat0
__device__ __nv_bfloat16 g_tmpH[FEAT_ELEMS], g_tmpL[FEAT_ELEMS];   // c1 / c3 out
__device__ __nv_bfloat16 g_tm2H[FEAT_ELEMS], g_tm2L[FEAT_ELEMS];   // c5 out
__device__ __nv_bfloat16 g_ftH[FEAT_ELEMS], g_ftL[FEAT_ELEMS];   // final feat
__device__ float g_ffF[FEAT_ELEMS];                               // feat fp32 accum
__device__ float g_off[(size_t)BB*216*HWSZ];                      // NCHW
__device__ float g_sN[FEAT_ELEMS];                                // supp NHWC fp32
// 13 B-sets: 0,1 fc halves; 2 c1; 3 c2; 4 c3; 5 c5 (adjacent for NCH=2 fuse);
// 6 c4; 7 c6; 8-11 off chunks; 12 dcn. Each 9 taps x 16KB.
#define BSET 73728
__device__ __nv_bfloat16 g_B[13*BSET];

// ---------------------------------------------------------------------------
// Fused B prep: all 13 sets in one launch (blockIdx.y = set)
// ---------------------------------------------------------------------------
struct PrepDesc { const float* w; int cinTot, cin0, coutTot, cout0; };
struct PrepTable { PrepDesc d[13]; };

__global__ void prep_all_kernel(PrepTable tab, __nv_bfloat16* __restrict__ outB)
{
    int set = blockIdx.y;
    PrepDesc pd = tab.d[set];
    int idx = blockIdx.x * 256 + threadIdx.x;   // < 36864
    int c = idx & 63;
    int r = (idx >> 6) & 63;
    int t = idx >> 12;
    float v = 0.f;
    int co = pd.cout0 + r;
    if (co < pd.coutTot) v = pd.w[((size_t)co * pd.cinTot + pd.cin0 + c) * 9 + t];
    __nv_bfloat16 h = __float2bfloat16(v);
    __nv_bfloat16 l = __float2bfloat16(v - __bfloat162float(h));
    uint32_t off = (uint32_t)r * 128u + (uint32_t)c * 2u;
    uint32_t so = off ^ ((off >> 3) & 0x70u);
    char* ob = (char*)(outB + (size_t)set * BSET) + (size_t)t * 16384;
    *(__nv_bfloat16*)(ob + so) = h;
    *(__nv_bfloat16*)(ob + 8192 + so) = l;
}

// ---------------------------------------------------------------------------
// Combined converter (smem-tiled transpose, 64px x 64ch per block):
//   z==0: supp NCHW fp32 -> NHWC fp32 (feeds warp + dcn gathers)
//   z==1: ref  NCHW fp32 -> NHWC bf16 hi/lo
// ---------------------------------------------------------------------------
__global__ void convert_kernel(const float* __restrict__ supp, float* __restrict__ suppN,
                               const float* __restrict__ ref,
                               __nv_bfloat16* __restrict__ rH, __nv_bfloat16* __restrict__ rL)
{
    __shared__ float s[64 * 65];
    int b  = blockIdx.y;
    int x0 = blockIdx.x * 64;     // linear pixel base
    int tid = threadIdx.x;
    int path = blockIdx.z;
    const float* src = (path == 0) ? supp : ref;
    int lc = tid >> 6;            // 0..3
    int lp = tid & 63;
    #pragma unroll
    for (int i = 0; i < 16; i++) {
        int c = i * 4 + lc;
        s[lp * 65 + c] = src[((size_t)b * 64 + c) * HWSZ + x0 + lp];
    }
    __syncthreads();
    int px = tid >> 2, q4 = (tid & 3) * 16;
    const float* sp = s + px * 65 + q4;
    if (path == 0) {
        float* dp = suppN + ((size_t)b * HWSZ + x0 + px) * 64 + q4;
        #pragma unroll
        for (int q = 0; q < 4; q++)
            ((float4*)dp)[q] = make_float4(sp[q*4], sp[q*4+1], sp[q*4+2], sp[q*4+3]);
    } else {
        size_t base = ((size_t)b * HWSZ + x0 + px) * 64 + q4;
        __nv_bfloat16* oh = rH + base;
        __nv_bfloat16* ol = rL + base;
        #pragma unroll
        for (int h = 0; h < 2; h++) {   // 8 channels per uint4
            uint4 uh, ul;
            uint32_t* ph = (uint32_t*)&uh;
            uint32_t* pl = (uint32_t*)&ul;
            #pragma unroll
            for (int q = 0; q < 4; q++) {
                float v0 = sp[h*8 + q*2], v1 = sp[h*8 + q*2 + 1];
                __nv_bfloat162 h2 = __floats2bfloat162_rn(v0, v1);
                float2 hf = __bfloat1622float2(h2);
                __nv_bfloat162 l2 = __floats2bfloat162_rn(v0 - hf.x, v1 - hf.y);
                ph[q] = *(uint32_t*)&h2;
                pl[q] = *(uint32_t*)&l2;
            }
            ((uint4*)oh)[h] = uh;
            ((uint4*)ol)[h] = ul;
        }
    }
}

// ---------------------------------------------------------------------------
// flow_warp (reads NHWC fp32 supp, vectorized corners) -> NHWC bf16 hi/lo
// ---------------------------------------------------------------------------
__global__ void warp_nhwc_kernel(const float* __restrict__ suppN, const float* __restrict__ flow,
                                 __nv_bfloat16* __restrict__ oH, __nv_bfloat16* __restrict__ oL)
{
    int p = blockIdx.x * 256 + threadIdx.x;
    int b = blockIdx.y;
    int y = p >> 8, x = p & 255;
    float fx = flow[((size_t)b*2    )*HWSZ + p];
    float fy = flow[((size_t)b*2 + 1)*HWSZ + p];
    float sy = (float)y + fy, sx = (float)x + fx;
    float y0f = floorf(sy), x0f = floorf(sx);
    int iy0 = (int)y0f, ix0 = (int)x0f, iy1 = iy0+1, ix1 = ix0+1;
    float wy = sy - y0f, wx = sx - x0f;
    bool vy0 = ((unsigned)iy0 < HH), vy1 = ((unsigned)iy1 < HH);
    bool vx0 = ((unsigned)ix0 < WW), vx1 = ((unsigned)ix1 < WW);
    float w00 = (1.f-wy)*(1.f-wx) * ((vy0&&vx0)?1.f:0.f);
    float w01 = (1.f-wy)*wx       * ((vy0&&vx1)?1.f:0.f);
    float w10 = wy*(1.f-wx)       * ((vy1&&vx0)?1.f:0.f);
    float w11 = wy*wx             * ((vy1&&vx1)?1.f:0.f);
    int cy0 = min(max(iy0,0),HH-1), cy1 = min(max(iy1,0),HH-1);
    int cx0 = min(max(ix0,0),WW-1), cx1 = min(max(ix1,0),WW-1);
    size_t i00 = (size_t)(cy0*WW+cx0)*64, i01 = (size_t)(cy0*WW+cx1)*64;
    size_t i10 = (size_t)(cy1*WW+cx0)*64, i11 = (size_t)(cy1*WW+cx1)*64;
    const float* sb = suppN + (size_t)b*HWSZ*64;
    __nv_bfloat16* ohp = oH + ((size_t)b*HWSZ + p)*64;
    __nv_bfloat16* olp = oL + ((size_t)b*HWSZ + p)*64;
    #pragma unroll 1
    for (int g = 0; g < 8; g++) {
        const float4* p00 = (const float4*)(sb + i00 + g*8);
        const float4* p01 = (const float4*)(sb + i01 + g*8);
        const float4* p10 = (const float4*)(sb + i10 + g*8);
        const float4* p11 = (const float4*)(sb + i11 + g*8);
        float v[8];
        #pragma unroll
        for (int h = 0; h < 2; h++) {
            float4 a = p00[h], bb = p01[h], cc = p10[h], dd = p11[h];
            v[h*4+0] = w00*a.x + w01*bb.x + w10*cc.x + w11*dd.x;
            v[h*4+1] = w00*a.y + w01*bb.y + w10*cc.y + w11*dd.y;
            v[h*4+2] = w00*a.z + w01*bb.z + w10*cc.z + w11*dd.z;
            v[h*4+3] = w00*a.w + w01*bb.w + w10*cc.w + w11*dd.w;
        }
        uint4 uh, ul;
        uint32_t* ph = (uint32_t*)&uh;
        uint32_t* pl = (uint32_t*)&ul;
        #pragma unroll
        for (int q = 0; q < 4; q++) {
            __nv_bfloat162 h2 = __floats2bfloat162_rn(v[q*2], v[q*2+1]);
            float2 hf = __bfloat1622float2(h2);
            __nv_bfloat162 l2 = __floats2bfloat162_rn(v[q*2] - hf.x, v[q*2+1] - hf.y);
            ph[q] = *(uint32_t*)&h2;
            pl[q] = *(uint32_t*)&l2;
        }
        ((uint4*)ohp)[g] = uh;
        ((uint4*)olp)[g] = ul;
    }
}

// ---------------------------------------------------------------------------
// mma.sync conv: single A buffer per ki group, double-buffered B (NCH chunk
// sets per tap), group-accounting wait invariant. NCH=1: 3 CTAs/SM (proven).
// NCH=2: A staged once for both B sets, 2 CTAs/SM.
// EPI: 2 relu->hi/lo; 3 relu res(f32)+v ->f32; 4 relu outF+=0.1v;
//      5 relu res+0.1v ->hi/lo; 6 NCHW f32 (coutTot guard);
//      7 per-chunk relu->hi/lo (nc0: outH/L + bias, nc1: outH2/L2 + bias2);
//      8 relu + res(hi+lo from inH2/inL2) -> f32; 9 lrelu -> hi/lo.
// ---------------------------------------------------------------------------
template<int DIL, int EPI, int HASBIAS, int NT, int NCH>
__global__ void __launch_bounds__(256, (NCH == 2 ? 2 : 3))
conv_mma_kernel(const __nv_bfloat16* __restrict__ inH,
                const __nv_bfloat16* __restrict__ inL,
                const __nv_bfloat16* __restrict__ inH2,
                const __nv_bfloat16* __restrict__ inL2,
                const __nv_bfloat16* __restrict__ Bimg,
                const float* __restrict__ bias,
                const float* __restrict__ bias2,
                int nchunk, int coutTot,
                float* __restrict__ outF,
                __nv_bfloat16* __restrict__ outH,
                __nv_bfloat16* __restrict__ outL,
                __nv_bfloat16* __restrict__ outH2,
                __nv_bfloat16* __restrict__ outL2,
                const float* __restrict__ resF,
                float* __restrict__ outNCHW)
{
    constexpr uint32_t R = 128 + 2 * DIL;
    constexpr uint32_t AHALF = R * 128u;
    constexpr uint32_t ABUF = 2u * AHALF;
    constexpr uint32_t BSTEP = (uint32_t)NCH * 16384u;

    extern __shared__ char smem[];
    uint32_t base = (smem_u32(smem) + 1023u) & ~1023u;

    int tid = threadIdx.x;
    int lane = tid & 31, w = tid >> 5;
    int z = blockIdx.z;
    int b = z / nchunk, chunk = z - b * nchunk;
    int y = blockIdx.y, x0 = blockIdx.x * 128;

    const char* Bbase = (const char*)Bimg + (size_t)chunk * NCH * 147456;

    auto stageA = [&](int s) {
        int ki = (NT == 18 && s >= 3) ? s - 3 : s;
        const __nv_bfloat16* iH = (NT == 18 && s >= 3) ? inH2 : inH;
        const __nv_bfloat16* iL = (NT == 18 && s >= 3) ? inL2 : inL;
        int gy = y + (ki - 1) * DIL;
        bool rowok = ((unsigned)gy < HH);
        for (int i = tid; i < (int)(R * 8); i += 256) {
            int r = i >> 3, j = i & 7;
            int gx = x0 - DIL + r;
            bool ok = rowok && ((unsigned)gx < WW);
            size_t gidx = ok ? ((((size_t)b * HH + gy) * WW + gx) * 64) : 0;
            int sz = ok ? 16 : 0;
            uint32_t dst = base + (uint32_t)r * 128u +
                           (((uint32_t)j * 16u) ^ (((uint32_t)r & 7u) * 16u));
            CP_ASYNC16(dst, (const char*)(iH + gidx) + j * 16, sz);
            CP_ASYNC16(dst + AHALF, (const char*)(iL + gidx) + j * 16, sz);
        }
    };
    auto stageB = [&](int t2) {
        uint32_t bB = base + ABUF + (uint32_t)(t2 & 1) * BSTEP;
        #pragma unroll
        for (int nc = 0; nc < NCH; nc++) {
            const char* bsrc = Bbase + (size_t)nc * 147456 + (size_t)t2 * 16384;
            #pragma unroll
            for (int kk = 0; kk < 4; kk++)
                CP_ASYNC16(bB + (uint32_t)nc * 16384u + (uint32_t)tid * 16u + (uint32_t)kk * 4096u,
                           bsrc + tid * 16 + kk * 4096, 16);
        }
    };

    stageA(0);
    stageB(0);
    CP_COMMIT();

    int mbase = (w & 3) * 32;
    int nbase = (w >> 2) * 32;

    float acc[NCH][2][4][4];
    #pragma unroll
    for (int nc = 0; nc < NCH; nc++)
        #pragma unroll
        for (int i = 0; i < 2; i++)
            #pragma unroll
            for (int j = 0; j < 4; j++)
                #pragma unroll
                for (int q = 0; q < 4; q++) acc[nc][i][j][q] = 0.f;

    int lr = (lane & 7) + ((lane >> 3) & 1) * 8;
    int kq = (lane >> 4) * 16;

    #pragma unroll 1
    for (int tt = 0; tt < NT; tt++) {
        if (tt + 1 < NT && (tt + 1) % 3 != 0) {
            stageB(tt + 1);
            CP_COMMIT();
            CP_WAIT1();
        } else {
            CP_WAIT0();
        }
        __syncthreads();

        int s = tt / 3, kj = tt - s * 3;
        uint32_t Bt = base + ABUF + (uint32_t)(tt & 1) * BSTEP;
        uint32_t rowA0 = (uint32_t)(kj * DIL + mbase + lr);
        uint32_t rowB0 = (uint32_t)(nbase + lr);

        #pragma unroll
        for (int ks = 0; ks < 4; ks++) {
            uint32_t kb = (uint32_t)(ks * 32 + kq);
            uint32_t ah0[4], ah1[4], al0[4], al1[4];
            {
                uint32_t r0 = rowA0, r1 = rowA0 + 16u;
                uint32_t o0 = r0*128u + (kb ^ ((r0 & 7u)*16u));
                uint32_t o1 = r1*128u + (kb ^ ((r1 & 7u)*16u));
                LDSM_X4(ah0[0], ah0[1], ah0[2], ah0[3], base + o0);
                LDSM_X4(ah1[0], ah1[1], ah1[2], ah1[3], base + o1);
                LDSM_X4(al0[0], al0[1], al0[2], al0[3], base + AHALF + o0);
                LDSM_X4(al1[0], al1[1], al1[2], al1[3], base + AHALF + o1);
            }
            #pragma unroll
            for (int nc = 0; nc < NCH; nc++) {
                uint32_t Bc = Bt + (uint32_t)nc * 16384u;
                uint32_t bh0[4], bh1[4], bl0[4], bl1[4];
                uint32_t r0 = rowB0, r1 = rowB0 + 16u;
                uint32_t o0 = r0*128u + (kb ^ ((r0 & 7u)*16u));
                uint32_t o1 = r1*128u + (kb ^ ((r1 & 7u)*16u));
                LDSM_X4(bh0[0], bh0[1], bh0[2], bh0[3], Bc + o0);
                LDSM_X4(bh1[0], bh1[1], bh1[2], bh1[3], Bc + o1);
                LDSM_X4(bl0[0], bl0[1], bl0[2], bl0[3], Bc + 8192u + o0);
                LDSM_X4(bl1[0], bl1[1], bl1[2], bl1[3], Bc + 8192u + o1);
                MMA_BF16(acc[nc][0][0], ah0, bh0[0], bh0[2]);
                MMA_BF16(acc[nc][0][1], ah0, bh0[1], bh0[3]);
                MMA_BF16(acc[nc][0][2], ah0, bh1[0], bh1[2]);
                MMA_BF16(acc[nc][0][3], ah0, bh1[1], bh1[3]);
                MMA_BF16(acc[nc][1][0], ah1, bh0[0], bh0[2]);
                MMA_BF16(acc[nc][1][1], ah1, bh0[1], bh0[3]);
                MMA_BF16(acc[nc][1][2], ah1, bh1[0], bh1[2]);
                MMA_BF16(acc[nc][1][3], ah1, bh1[1], bh1[3]);
                MMA_BF16(acc[nc][0][0], ah0, bl0[0], bl0[2]);
                MMA_BF16(acc[nc][0][1], ah0, bl0[1], bl0[3]);
                MMA_BF16(acc[nc][0][2], ah0, bl1[0], bl1[2]);
                MMA_BF16(acc[nc][0][3], ah0, bl1[1], bl1[3]);
                MMA_BF16(acc[nc][1][0], ah1, bl0[0], bl0[2]);
                MMA_BF16(acc[nc][1][1], ah1, bl0[1], bl0[3]);
                MMA_BF16(acc[nc][1][2], ah1, bl1[0], bl1[2]);
                MMA_BF16(acc[nc][1][3], ah1, bl1[1], bl1[3]);
                MMA_BF16(acc[nc][0][0], al0, bh0[0], bh0[2]);
                MMA_BF16(acc[nc][0][1], al0, bh0[1], bh0[3]);
                MMA_BF16(acc[nc][0][2], al0, bh1[0], bh1[2]);
                MMA_BF16(acc[nc][0][3], al0, bh1[1], bh1[3]);
                MMA_BF16(acc[nc][1][0], al1, bh0[0], bh0[2]);
                MMA_BF16(acc[nc][1][1], al1, bh0[1], bh0[3]);
                MMA_BF16(acc[nc][1][2], al1, bh1[0], bh1[2]);
                MMA_BF16(acc[nc][1][3], al1, bh1[1], bh1[3]);
            }
        }
        __syncthreads();

        if (tt + 1 < NT && (tt + 1) % 3 == 0) {
            stageA((tt + 1) / 3);
            stageB(tt + 1);
            CP_COMMIT();
        }
    }

    // ---- epilogue ----
    #pragma unroll
    for (int nc = 0; nc < NCH; nc++) {
        const float* bp = (EPI == 7 && nc == 1) ? bias2 : bias;
        float bs2[4][2];
        #pragma unroll
        for (int nb = 0; nb < 4; nb++) {
            int co = (EPI == 7) ? (nbase + nb * 8 + (lane & 3) * 2)
                                : ((chunk * NCH + nc) * 64 + nbase + nb * 8 + (lane & 3) * 2);
            bs2[nb][0] = (HASBIAS && co     < coutTot) ? bp[co]     : 0.f;
            bs2[nb][1] = (HASBIAS && co + 1 < coutTot) ? bp[co + 1] : 0.f;
        }
        #pragma unroll
        for (int mt = 0; mt < 2; mt++) {
            #pragma unroll
            for (int rh = 0; rh < 2; rh++) {
                int px = x0 + mbase + mt * 16 + (lane >> 2) + rh * 8;
                size_t P = ((size_t)b * HH + y) * WW + px;
                #pragma unroll
                for (int nb = 0; nb < 4; nb++) {
                    int cl = nbase + nb * 8 + (lane & 3) * 2;
                    float v0 = acc[nc][mt][nb][rh * 2 + 0] + bs2[nb][0];
                    float v1 = acc[nc][mt][nb][rh * 2 + 1] + bs2[nb][1];
                    size_t ob = P * 64 + cl;

                    if (EPI == 2) {
                        v0 = fmaxf(v0, 0.f); v1 = fmaxf(v1, 0.f);
                        __nv_bfloat162 h2 = __floats2bfloat162_rn(v0, v1);
                        float2 hf = __bfloat1622float2(h2);
                        __nv_bfloat162 l2 = __floats2bfloat162_rn(v0 - hf.x, v1 - hf.y);
                        *(uint32_t*)(outH + ob) = *(uint32_t*)&h2;
                        *(uint32_t*)(outL + ob) = *(uint32_t*)&l2;
                    } else if (EPI == 3) {
                        float2 rv = *(const float2*)(resF + ob);
                        v0 = rv.x + fmaxf(v0, 0.f);
                        v1 = rv.y + fmaxf(v1, 0.f);
                        *(float2*)(outF + ob) = make_float2(v0, v1);
                    } else if (EPI == 4) {
                        float2 rv = *(const float2*)(outF + ob);
                        v0 = rv.x + 0.1f * fmaxf(v0, 0.f);
                        v1 = rv.y + 0.1f * fmaxf(v1, 0.f);
                        *(float2*)(outF + ob) = make_float2(v0, v1);
                    } else if (EPI == 5) {
                        float2 rv = *(const float2*)(resF + ob);
                        v0 = rv.x + 0.1f * fmaxf(v0, 0.f);
                        v1 = rv.y + 0.1f * fmaxf(v1, 0.f);
                        __nv_bfloat162 h2 = __floats2bfloat162_rn(v0, v1);
                        float2 hf = __bfloat1622float2(h2);
                        __nv_bfloat162 l2 = __floats2bfloat162_rn(v0 - hf.x, v1 - hf.y);
                        *(uint32_t*)(outH + ob) = *(uint32_t*)&h2;
                        *(uint32_t*)(outL + ob) = *(uint32_t*)&l2;
                    } else if (EPI == 6) {
                        int co = (chunk * NCH + nc) * 64 + cl;
                        size_t pix = ((size_t)y << 8) + px;
                        if (co < coutTot)
                            outNCHW[(((size_t)b * coutTot + co) << 16) + pix] = v0;
                        if (co + 1 < coutTot)
                            outNCHW[(((size_t)b * coutTot + co + 1) << 16) + pix] = v1;
                    } else if (EPI == 7) {
                        v0 = fmaxf(v0, 0.f); v1 = fmaxf(v1, 0.f);
                        __nv_bfloat16* oh = (nc == 0) ? outH : outH2;
                        __nv_bfloat16* ol = (nc == 0) ? outL : outL2;
                        __nv_bfloat162 h2 = __floats2bfloat162_rn(v0, v1);
                        float2 hf = __bfloat1622float2(h2);
                        __nv_bfloat162 l2 = __floats2bfloat162_rn(v0 - hf.x, v1 - hf.y);
                        *(uint32_t*)(oh + ob) = *(uint32_t*)&h2;
                        *(uint32_t*)(ol + ob) = *(uint32_t*)&l2;
                    } else if (EPI == 8) {
                        // res = hi+lo reconstructed from inH2/inL2 (feat0)
                        uint32_t rhw = *(const uint32_t*)(inH2 + ob);
                        uint32_t rlw = *(const uint32_t*)(inL2 + ob);
                        float2 hf = __bfloat1622float2(*(__nv_bfloat162*)&rhw);
                        float2 lf = __bfloat1622float2(*(__nv_bfloat162*)&rlw);
                        v0 = (hf.x + lf.x) + fmaxf(v0, 0.f);
                        v1 = (hf.y + lf.y) + fmaxf(v1, 0.f);
                        *(float2*)(outF + ob) = make_float2(v0, v1);
                    } else if (EPI == 9) {
                        v0 = (v0 > 0.f) ? v0 : 0.1f * v0;
                        v1 = (v1 > 0.f) ? v1 : 0.1f * v1;
                        __nv_bfloat162 h2 = __floats2bfloat162_rn(v0, v1);
                        float2 hf = __bfloat1622float2(h2);
                        __nv_bfloat162 l2 = __floats2bfloat162_rn(v0 - hf.x, v1 - hf.y);
                        *(uint32_t*)(outH + ob) = *(uint32_t*)&h2;
                        *(uint32_t*)(outL + ob) = *(uint32_t*)&l2;
                    }
                }
            }
        }
    }
}

// ---------------------------------------------------------------------------
// Modulated deformable conv, tensorized; NHWC fp32 gathers + fast
// transcendentals; occupancy 2 (occ-3 reg-caps spill the sampler).
// ---------------------------------------------------------------------------
__global__ void __launch_bounds__(256, 2)
dcn_mma_kernel(const float* __restrict__ suppN, const float* __restrict__ off,
               const float* __restrict__ flow, const __nv_bfloat16* __restrict__ Bimg,
               const float* __restrict__ bias, float* __restrict__ out)
{
    extern __shared__ char smem[];
    uint32_t base = (smem_u32(smem) + 1023u) & ~1023u;
    const uint32_t SM_S = base;            // 32KB: hi 16K | lo 16K
    const uint32_t SM_Bd = base + 32768u;  // 2 x 16KB B double buffer

    int tid = threadIdx.x;
    int lane = tid & 31, w = tid >> 5;
    int b = blockIdx.z, y = blockIdx.y, x0 = blockIdx.x * 128;

    #pragma unroll
    for (int kk = 0; kk < 4; kk++)
        CP_ASYNC16(SM_Bd + (uint32_t)tid * 16u + (uint32_t)kk * 4096u,
                   (const char*)Bimg + tid * 16 + kk * 4096, 16);
    CP_COMMIT();

    int mbase = (w & 3) * 32;
    int nbase = (w >> 2) * 32;
    float acc[2][4][4];
    #pragma unroll
    for (int i = 0; i < 2; i++)
        #pragma unroll
        for (int j = 0; j < 4; j++)
            #pragma unroll
            for (int q = 0; q < 4; q++) acc[i][j][q] = 0.f;

    int lr = (lane & 7) + ((lane >> 3) & 1) * 8;
    int kq = (lane >> 4) * 16;

    const float* fxp  = flow + ((size_t)b*2 + 0)*HWSZ + y*WW + x0;
    const float* fyp  = flow + ((size_t)b*2 + 1)*HWSZ + y*WW + x0;
    const float* offb = off  + (size_t)b*216*HWSZ + y*WW + x0;
    const float* sb   = suppN + (size_t)b*HWSZ*64;

    #pragma unroll 1
    for (int k = 0; k < 9; k++) {
        if (k < 8) {
            const char* bsrc = (const char*)Bimg + (size_t)(k + 1) * 16384;
            uint32_t bB = SM_Bd + (uint32_t)((k + 1) & 1) * 16384u;
            #pragma unroll
            for (int kk = 0; kk < 4; kk++)
                CP_ASYNC16(bB + (uint32_t)tid * 16u + (uint32_t)kk * 4096u,
                           bsrc + tid * 16 + kk * 4096, 16);
            CP_COMMIT();
        }

        int ki = k / 3, kj = k - ki * 3;
        #pragma unroll 1
        for (int it = 0; it < 4; it++) {
            int task = tid + it * 256;
            int px = task & 127;
            int g  = task >> 7;
            int cdy = g*18 + k*2;
            float rawdy = offb[(size_t)cdy          *HWSZ + px];
            float rawdx = offb[(size_t)(cdy + 1)    *HWSZ + px];
            float rawm  = offb[(size_t)(144 + g*9+k)*HWSZ + px];
            float fx = fxp[px], fy = fyp[px];
            float ady = 25.f * fast_tanh(rawdy) + ((cdy     < 72) ? fx : fy);
            float adx = 25.f * fast_tanh(rawdx) + ((cdy + 1 < 72) ? fx : fy);
            float m   = fast_sigmoid(rawm);
            float sy = (float)y         + (float)(ki - 1) + ady;
            float sx = (float)(x0 + px) + (float)(kj - 1) + adx;
            float y0f = floorf(sy), x0f = floorf(sx);
            int iy0 = (int)y0f, ix0 = (int)x0f;
            int iy1 = iy0 + 1,  ix1 = ix0 + 1;
            float wy = sy - y0f, wx = sx - x0f;
            bool vy0 = ((unsigned)iy0 < HH), vy1 = ((unsigned)iy1 < HH);
            bool vx0 = ((unsigned)ix0 < WW), vx1 = ((unsigned)ix1 < WW);
            float w00 = (1.f - wy)*(1.f - wx) * ((vy0 && vx0) ? 1.f : 0.f) * m;
            float w01 = (1.f - wy)*wx         * ((vy0 && vx1) ? 1.f : 0.f) * m;
            float w10 = wy*(1.f - wx)         * ((vy1 && vx0) ? 1.f : 0.f) * m;
            float w11 = wy*wx                 * ((vy1 && vx1) ? 1.f : 0.f) * m;
            int cy0 = min(max(iy0, 0), HH-1), cy1 = min(max(iy1, 0), HH-1);
            int cx0 = min(max(ix0, 0), WW-1), cx1 = min(max(ix1, 0), WW-1);
            const float4* p00 = (const float4*)(sb + (size_t)(cy0*WW + cx0)*64 + g*8);
            const float4* p01 = (const float4*)(sb + (size_t)(cy0*WW + cx1)*64 + g*8);
            const float4* p10 = (const float4*)(sb + (size_t)(cy1*WW + cx0)*64 + g*8);
            const float4* p11 = (const float4*)(sb + (size_t)(cy1*WW + cx1)*64 + g*8);
            float v[8];
            #pragma unroll
            for (int h = 0; h < 2; h++) {
                float4 a = p00[h], bb = p01[h], cc = p10[h], dd = p11[h];
                v[h*4+0] = w00*a.x + w01*bb.x + w10*cc.x + w11*dd.x;
                v[h*4+1] = w00*a.y + w01*bb.y + w10*cc.y + w11*dd.y;
                v[h*4+2] = w00*a.z + w01*bb.z + w10*cc.z + w11*dd.z;
                v[h*4+3] = w00*a.w + w01*bb.w + w10*cc.w + w11*dd.w;
            }
            uint32_t hpk[4], lpk[4];
            #pragma unroll
            for (int q = 0; q < 4; q++) {
                __nv_bfloat162 h2 = __floats2bfloat162_rn(v[q*2], v[q*2+1]);
                float2 hf = __bfloat1622float2(h2);
                __nv_bfloat162 l2 = __floats2bfloat162_rn(v[q*2] - hf.x, v[q*2+1] - hf.y);
                hpk[q] = *(uint32_t*)&h2;
                lpk[q] = *(uint32_t*)&l2;
            }
            uint32_t so = (uint32_t)px * 128u +
                          (((uint32_t)g * 16u) ^ (((uint32_t)px & 7u) * 16u));
            asm volatile("st.shared.v4.b32 [%0], {%1,%2,%3,%4};"
                :: "r"(SM_S + so), "r"(hpk[0]), "r"(hpk[1]), "r"(hpk[2]), "r"(hpk[3]) : "memory");
            asm volatile("st.shared.v4.b32 [%0], {%1,%2,%3,%4};"
                :: "r"(SM_S + 16384u + so), "r"(lpk[0]), "r"(lpk[1]), "r"(lpk[2]), "r"(lpk[3]) : "memory");
        }

        if (k < 8) CP_WAIT1(); else CP_WAIT0();
        __syncthreads();

        uint32_t Bt = SM_Bd + (uint32_t)(k & 1) * 16384u;
        uint32_t rowA0 = (uint32_t)(mbase + lr);
        uint32_t rowB0 = (uint32_t)(nbase + lr);
        #pragma unroll
        for (int ks = 0; ks < 4; ks++) {
            uint32_t kb = (uint32_t)(ks * 32 + kq);
            uint32_t ah0[4], ah1[4], al0[4], al1[4];
            uint32_t bh0[4], bh1[4], bl0[4], bl1[4];
            {
                uint32_t r0 = rowA0, r1 = rowA0 + 16u;
                uint32_t o0 = r0*128u + (kb ^ ((r0 & 7u)*16u));
                uint32_t o1 = r1*128u + (kb ^ ((r1 & 7u)*16u));
                LDSM_X4(ah0[0], ah0[1], ah0[2], ah0[3], SM_S + o0);
                LDSM_X4(ah1[0], ah1[1], ah1[2], ah1[3], SM_S + o1);
                LDSM_X4(al0[0], al0[1], al0[2], al0[3], SM_S + 16384u + o0);
                LDSM_X4(al1[0], al1[1], al1[2], al1[3], SM_S + 16384u + o1);
            }
            {
                uint32_t r0 = rowB0, r1 = rowB0 + 16u;
                uint32_t o0 = r0*128u + (kb ^ ((r0 & 7u)*16u));
                uint32_t o1 = r1*128u + (kb ^ ((r1 & 7u)*16u));
                LDSM_X4(bh0[0], bh0[1], bh0[2], bh0[3], Bt + o0);
                LDSM_X4(bh1[0], bh1[1], bh1[2], bh1[3], Bt + o1);
                LDSM_X4(bl0[0], bl0[1], bl0[2], bl0[3], Bt + 8192u + o0);
                LDSM_X4(bl1[0], bl1[1], bl1[2], bl1[3], Bt + 8192u + o1);
            }
            MMA_BF16(acc[0][0], ah0, bh0[0], bh0[2]);
            MMA_BF16(acc[0][1], ah0, bh0[1], bh0[3]);
            MMA_BF16(acc[0][2], ah0, bh1[0], bh1[2]);
            MMA_BF16(acc[0][3], ah0, bh1[1], bh1[3]);
            MMA_BF16(acc[1][0], ah1, bh0[0], bh0[2]);
            MMA_BF16(acc[1][1], ah1, bh0[1], bh0[3]);
            MMA_BF16(acc[1][2], ah1, bh1[0], bh1[2]);
            MMA_BF16(acc[1][3], ah1, bh1[1], bh1[3]);
            MMA_BF16(acc[0][0], ah0, bl0[0], bl0[2]);
            MMA_BF16(acc[0][1], ah0, bl0[1], bl0[3]);
            MMA_BF16(acc[0][2], ah0, bl1[0], bl1[2]);
            MMA_BF16(acc[0][3], ah0, bl1[1], bl1[3]);
            MMA_BF16(acc[1][0], ah1, bl0[0], bl0[2]);
            MMA_BF16(acc[1][1], ah1, bl0[1], bl0[3]);
            MMA_BF16(acc[1][2], ah1, bl1[0], bl1[2]);
            MMA_BF16(acc[1][3], ah1, bl1[1], bl1[3]);
            MMA_BF16(acc[0][0], al0, bh0[0], bh0[2]);
            MMA_BF16(acc[0][1], al0, bh0[1], bh0[3]);
            MMA_BF16(acc[0][2], al0, bh1[0], bh1[2]);
            MMA_BF16(acc[0][3], al0, bh1[1], bh1[3]);
            MMA_BF16(acc[1][0], al1, bh0[0], bh0[2]);
            MMA_BF16(acc[1][1], al1, bh0[1], bh0[3]);
            MMA_BF16(acc[1][2], al1, bh1[0], bh1[2]);
            MMA_BF16(acc[1][3], al1, bh1[1], bh1[3]);
        }
        __syncthreads();
    }

    // ---- epilogue: bias + NCHW fp32 store ----
    float bs2[4][2];
    #pragma unroll
    for (int nb = 0; nb < 4; nb++) {
        int co = nbase + nb * 8 + (lane & 3) * 2;
        bs2[nb][0] = bias[co];
        bs2[nb][1] = bias[co + 1];
    }
    #pragma unroll
    for (int mt = 0; mt < 2; mt++) {
        #pragma unroll
        for (int rh = 0; rh < 2; rh++) {
            int px = x0 + mbase + mt * 16 + (lane >> 2) + rh * 8;
            size_t pix = ((size_t)y << 8) + px;
            #pragma unroll
            for (int nb = 0; nb < 4; nb++) {
                int co = nbase + nb * 8 + (lane & 3) * 2;
                out[(((size_t)b * 64 + co    ) << 16) + pix] = acc[mt][nb][rh*2+0] + bs2[nb][0];
                out[(((size_t)b * 64 + co + 1) << 16) + pix] = acc[mt][nb][rh*2+1] + bs2[nb][1];
            }
        }
    }
}

// ---------------------------------------------------------------------------
// Launch
// ---------------------------------------------------------------------------
extern "C" void kernel_launch(void* const* d_in, const int* in_sizes, int n_in,
                              void* d_out, int out_size)
{
    const float* ref   = (const float*)d_in[0];
    const float* supp  = (const float*)d_in[1];
    const float* flow  = (const float*)d_in[2];
    const float* fc_w  = (const float*)d_in[3];
    const float* fc_b  = (const float*)d_in[4];
    const float* cw[6], *cb[6];
    for (int i = 0; i < 6; i++) {
        cw[i] = (const float*)d_in[5 + 2*i];
        cb[i] = (const float*)d_in[6 + 2*i];
    }
    const float* off_w = (const float*)d_in[17];
    const float* off_b = (const float*)d_in[18];
    const float* dcn_w = (const float*)d_in[19];
    const float* dcn_b = (const float*)d_in[20];
    float* out = (float*)d_out;

    __nv_bfloat16 *wH, *wL, *rH, *rL, *t0H, *t0L, *tmpH, *tmpL, *tm2H, *tm2L, *ftH, *ftL, *Bg;
    float *ffF, *offbuf, *suppN;
    cudaGetSymbolAddress((void**)&wH,  g_wH);   cudaGetSymbolAddress((void**)&wL,  g_wL);
    cudaGetSymbolAddress((void**)&rH,  g_rH);   cudaGetSymbolAddress((void**)&rL,  g_rL);
    cudaGetSymbolAddress((void**)&t0H, g_t0H);  cudaGetSymbolAddress((void**)&t0L, g_t0L);
    cudaGetSymbolAddress((void**)&tmpH,g_tmpH); cudaGetSymbolAddress((void**)&tmpL,g_tmpL);
    cudaGetSymbolAddress((void**)&tm2H,g_tm2H); cudaGetSymbolAddress((void**)&tm2L,g_tm2L);
    cudaGetSymbolAddress((void**)&ftH, g_ftH);  cudaGetSymbolAddress((void**)&ftL, g_ftL);
    cudaGetSymbolAddress((void**)&Bg,  g_B);
    cudaGetSymbolAddress((void**)&ffF,   g_ffF);
    cudaGetSymbolAddress((void**)&offbuf,g_off);
    cudaGetSymbolAddress((void**)&suppN, g_sN);

    // smem: pad + single A (2*(128+2d)*128) + 2*NCH*16KB B
    const int SMB1 = 1024 + 2*(130*128) + 32768;   // 67072 (NCH=1, d=1)
    const int SMB2 = 1024 + 2*(132*128) + 32768;   // 67584 (NCH=1, d=2)
    const int SMB4 = 1024 + 2*(136*128) + 32768;   // 68608 (NCH=1, d=4)
    const int SMO  = 1024 + 2*(130*128) + 65536;   // 99840 (NCH=2, d=1)
    const int SMC  = 1024 + 2*(132*128) + 65536;   // 100352 (NCH=2, d=2)
    const int SMD  = 1024 + 32768 + 32768;         // 66560
    cudaFuncSetAttribute((const void*)conv_mma_kernel<1,9,1,18,1>, cudaFuncAttributeMaxDynamicSharedMemorySize, SMB1);
    cudaFuncSetAttribute((const void*)conv_mma_kernel<1,2,1,9,1>,  cudaFuncAttributeMaxDynamicSharedMemorySize, SMB1);
    cudaFuncSetAttribute((const void*)conv_mma_kernel<1,8,1,9,1>,  cudaFuncAttributeMaxDynamicSharedMemorySize, SMB1);
    cudaFuncSetAttribute((const void*)conv_mma_kernel<2,7,1,9,2>,  cudaFuncAttributeMaxDynamicSharedMemorySize, SMC);
    cudaFuncSetAttribute((const void*)conv_mma_kernel<2,4,1,9,1>,  cudaFuncAttributeMaxDynamicSharedMemorySize, SMB2);
    cudaFuncSetAttribute((const void*)conv_mma_kernel<4,5,1,9,1>,  cudaFuncAttributeMaxDynamicSharedMemorySize, SMB4);
    cudaFuncSetAttribute((const void*)conv_mma_kernel<1,6,1,9,2>,  cudaFuncAttributeMaxDynamicSharedMemorySize, SMO);
    cudaFuncSetAttribute((const void*)dcn_mma_kernel, cudaFuncAttributeMaxDynamicSharedMemorySize, SMD);

    // Fused weight prep (13 sets; c3,c5 adjacent at 4,5 for NCH=2 fusion)
    PrepTable tab;
    tab.d[0]  = {fc_w, 128, 0,  64, 0};
    tab.d[1]  = {fc_w, 128, 64, 64, 0};
    tab.d[2]  = {cw[0], 64, 0, 64, 0};   // c1
    tab.d[3]  = {cw[1], 64, 0, 64, 0};   // c2
    tab.d[4]  = {cw[2], 64, 0, 64, 0};   // c3
    tab.d[5]  = {cw[4], 64, 0, 64, 0};   // c5 (adjacent to c3)
    tab.d[6]  = {cw[3], 64, 0, 64, 0};   // c4
    tab.d[7]  = {cw[5], 64, 0, 64, 0};   // c6
    for (int ch = 0; ch < 4; ch++) tab.d[8+ch] = {off_w, 64, 0, 216, ch*64};
    tab.d[12] = {dcn_w, 64, 0, 64, 0};
    prep_all_kernel<<<dim3(144, 13), 256>>>(tab, Bg);

    // Combined converters: z=0 supp->NHWC fp32, z=1 ref->NHWC hi/lo
    convert_kernel<<<dim3(HWSZ/64, BB, 2), 256>>>(supp, suppN, ref, rH, rL);
    // flow warp (reads NHWC supp)
    warp_nhwc_kernel<<<dim3(HWSZ/256, BB), 256>>>(suppN, flow, wH, wL);

    dim3 cg(2, 256, 4);
    // fc (fused 18-tap): lrelu -> feat0 hi/lo only
    conv_mma_kernel<1,9,1,18,1><<<cg, 256, SMB1>>>(wH, wL, rH, rL, Bg + 0*BSET, fc_b, nullptr, 1, 64,
                                                   nullptr, t0H, t0L, nullptr, nullptr, nullptr, nullptr);
    // c1: relu -> tmp
    conv_mma_kernel<1,2,1,9,1><<<cg, 256, SMB1>>>(t0H, t0L, nullptr, nullptr, Bg + 2*BSET, cb[0], nullptr, 1, 64,
                                                  nullptr, tmpH, tmpL, nullptr, nullptr, nullptr, nullptr);
    // c2: ff = feat0(hi+lo) + relu(v) -> f32
    conv_mma_kernel<1,8,1,9,1><<<cg, 256, SMB1>>>(tmpH, tmpL, t0H, t0L, Bg + 3*BSET, cb[1], nullptr, 1, 64,
                                                  ffF, nullptr, nullptr, nullptr, nullptr, nullptr, nullptr);
    // c3+c5 fused (dil2, NCH=2, same input feat0): relu -> tmp (c3), tm2 (c5)
    conv_mma_kernel<2,7,1,9,2><<<cg, 256, SMC>>>(t0H, t0L, nullptr, nullptr, Bg + 4*BSET, cb[2], cb[4], 1, 64,
                                                 nullptr, tmpH, tmpL, tm2H, tm2L, nullptr, nullptr);
    // c4 (dil2): ff += 0.1*relu(v)  [reads c3 out = tmp]
    conv_mma_kernel<2,4,1,9,1><<<cg, 256, SMB2>>>(tmpH, tmpL, nullptr, nullptr, Bg + 6*BSET, cb[3], nullptr, 1, 64,
                                                  ffF, nullptr, nullptr, nullptr, nullptr, nullptr, nullptr);
    // c6 (dil4): feat = ff + 0.1*relu(v) -> hi/lo  [reads c5 out = tm2]
    conv_mma_kernel<4,5,1,9,1><<<cg, 256, SMB4>>>(tm2H, tm2L, nullptr, nullptr, Bg + 7*BSET, cb[5], nullptr, 1, 64,
                                                  nullptr, ftH, ftL, nullptr, nullptr, ffF, nullptr);
    // offset conv: 216 couts via 2 fused chunk-pairs (128 couts/CTA), NCHW out
    dim3 og(2, 256, BB*2);
    conv_mma_kernel<1,6,1,9,2><<<og, 256, SMO>>>(ftH, ftL, nullptr, nullptr, Bg + 8*BSET, off_b, nullptr, 2, 216,
                                                 nullptr, nullptr, nullptr, nullptr, nullptr, nullptr, offbuf);
    // tensorized deformable conv (fast transcendentals, occupancy 2)
    dcn_mma_kernel<<<cg, 256, SMD>>>(suppN, offbuf, flow, Bg + 12*BSET, dcn_b, out);
}

// round 17
// speedup vs baseline: 1.2042x; 1.0138x over previous
#include <cuda_runtime.h>
#include <cuda_bf16.h>
#include <math.h>
#include <stdint.h>

#define BB 4
#define HH 256
#define WW 256
#define HWSZ 65536
#define NPX (BB*HWSZ)

// ---------------------------------------------------------------------------
// PTX helpers (plain sm_103-safe: ldmatrix + mma.sync + cp.async)
// ---------------------------------------------------------------------------
__device__ __forceinline__ uint32_t smem_u32(const void* p) {
    uint32_t a;
    asm("{ .reg .u64 t; cvta.to.shared.u64 t, %1; cvt.u32.u64 %0, t; }" : "=r"(a) : "l"(p));
    return a;
}

#define LDSM_X4(r0, r1, r2, r3, addr) \
    asm volatile("ldmatrix.sync.aligned.m8n8.x4.shared.b16 {%0,%1,%2,%3}, [%4];" \
        : "=r"(r0), "=r"(r1), "=r"(r2), "=r"(r3) : "r"(addr))

#define MMA_BF16(d, a, b0v, b1v) \
    asm volatile("mma.sync.aligned.m16n8k16.row.col.f32.bf16.bf16.f32 " \
        "{%0,%1,%2,%3},{%4,%5,%6,%7},{%8,%9},{%0,%1,%2,%3};" \
        : "+f"((d)[0]), "+f"((d)[1]), "+f"((d)[2]), "+f"((d)[3]) \
        : "r"((a)[0]), "r"((a)[1]), "r"((a)[2]), "r"((a)[3]), "r"(b0v), "r"(b1v))

#define CP_ASYNC16(dst, src, sz) \
    asm volatile("cp.async.cg.shared.global [%0], [%1], 16, %2;" \
        :: "r"(dst), "l"(src), "r"(sz) : "memory")
#define CP_COMMIT() asm volatile("cp.async.commit_group;" ::: "memory")
#define CP_WAIT1() asm volatile("cp.async.wait_group 1;" ::: "memory")
#define CP_WAIT0() asm volatile("cp.async.wait_group 0;" ::: "memory")

// Fast transcendentals for DCN offsets. Clamp keeps exp finite; tanh(15)==1 in fp32.
__device__ __forceinline__ float fast_tanh(float x) {
    float xc = fminf(fmaxf(x, -15.f), 15.f);
    float e2 = __expf(2.f * xc);
    return __fdividef(e2 - 1.f, e2 + 1.f);
}
__device__ __forceinline__ float fast_sigmoid(float x) {
    return __fdividef(1.f, 1.f + __expf(-x));
}

// ---------------------------------------------------------------------------
// Device global scratch
// ---------------------------------------------------------------------------
#define FEAT_ELEMS ((size_t)NPX*64)
__device__ __nv_bfloat16 g_wH[FEAT_ELEMS], g_wL[FEAT_ELEMS];     // warped supp
__device__ __nv_bfloat16 g_rH[FEAT_ELEMS], g_rL[FEAT_ELEMS];     // ref
__device__ __nv_bfloat16 g_t0H[FEAT_ELEMS], g_t0L[FEAT_ELEMS];   // feat0
__device__ __nv_bfloat16 g_tmpH[FEAT_ELEMS], g_tmpL[FEAT_ELEMS];   // c1 / c3 out
__device__ __nv_bfloat16 g_tm2H[FEAT_ELEMS], g_tm2L[FEAT_ELEMS];   // c5 out
__device__ __nv_bfloat16 g_ftH[FEAT_ELEMS], g_ftL[FEAT_ELEMS];   // final feat
__device__ float g_ffF[FEAT_ELEMS];                               // feat fp32 accum
__device__ float g_off[(size_t)BB*216*HWSZ];                      // NCHW
__device__ float g_sN[FEAT_ELEMS];                                // supp NHWC fp32
// 13 B-sets: 0,1 fc halves; 2 c1; 3 c2; 4 c3; 5 c5 (adjacent for NCH=2 fuse);
// 6 c4; 7 c6; 8-11 off chunks; 12 dcn. Each 9 taps x 16KB.
#define BSET 73728
__device__ __nv_bfloat16 g_B[13*BSET];

// ---------------------------------------------------------------------------
// Fused B prep: all 13 sets in one launch (blockIdx.y = set)
// ---------------------------------------------------------------------------
struct PrepDesc { const float* w; int cinTot, cin0, coutTot, cout0; };
struct PrepTable { PrepDesc d[13]; };

__global__ void prep_all_kernel(PrepTable tab, __nv_bfloat16* __restrict__ outB)
{
    int set = blockIdx.y;
    PrepDesc pd = tab.d[set];
    int idx = blockIdx.x * 256 + threadIdx.x;   // < 36864
    int c = idx & 63;
    int r = (idx >> 6) & 63;
    int t = idx >> 12;
    float v = 0.f;
    int co = pd.cout0 + r;
    if (co < pd.coutTot) v = pd.w[((size_t)co * pd.cinTot + pd.cin0 + c) * 9 + t];
    __nv_bfloat16 h = __float2bfloat16(v);
    __nv_bfloat16 l = __float2bfloat16(v - __bfloat162float(h));
    uint32_t off = (uint32_t)r * 128u + (uint32_t)c * 2u;
    uint32_t so = off ^ ((off >> 3) & 0x70u);
    char* ob = (char*)(outB + (size_t)set * BSET) + (size_t)t * 16384;
    *(__nv_bfloat16*)(ob + so) = h;
    *(__nv_bfloat16*)(ob + 8192 + so) = l;
}

// ---------------------------------------------------------------------------
// Combined converter (smem-tiled transpose, 64px x 64ch per block):
//   z==0: supp NCHW fp32 -> NHWC fp32 (feeds warp + dcn gathers)
//   z==1: ref  NCHW fp32 -> NHWC bf16 hi/lo
// ---------------------------------------------------------------------------
__global__ void convert_kernel(const float* __restrict__ supp, float* __restrict__ suppN,
                               const float* __restrict__ ref,
                               __nv_bfloat16* __restrict__ rH, __nv_bfloat16* __restrict__ rL)
{
    __shared__ float s[64 * 65];
    int b  = blockIdx.y;
    int x0 = blockIdx.x * 64;     // linear pixel base
    int tid = threadIdx.x;
    int path = blockIdx.z;
    const float* src = (path == 0) ? supp : ref;
    int lc = tid >> 6;            // 0..3
    int lp = tid & 63;
    #pragma unroll
    for (int i = 0; i < 16; i++) {
        int c = i * 4 + lc;
        s[lp * 65 + c] = src[((size_t)b * 64 + c) * HWSZ + x0 + lp];
    }
    __syncthreads();
    int px = tid >> 2, q4 = (tid & 3) * 16;
    const float* sp = s + px * 65 + q4;
    if (path == 0) {
        float* dp = suppN + ((size_t)b * HWSZ + x0 + px) * 64 + q4;
        #pragma unroll
        for (int q = 0; q < 4; q++)
            ((float4*)dp)[q] = make_float4(sp[q*4], sp[q*4+1], sp[q*4+2], sp[q*4+3]);
    } else {
        size_t base = ((size_t)b * HWSZ + x0 + px) * 64 + q4;
        __nv_bfloat16* oh = rH + base;
        __nv_bfloat16* ol = rL + base;
        #pragma unroll
        for (int h = 0; h < 2; h++) {   // 8 channels per uint4
            uint4 uh, ul;
            uint32_t* ph = (uint32_t*)&uh;
            uint32_t* pl = (uint32_t*)&ul;
            #pragma unroll
            for (int q = 0; q < 4; q++) {
                float v0 = sp[h*8 + q*2], v1 = sp[h*8 + q*2 + 1];
                __nv_bfloat162 h2 = __floats2bfloat162_rn(v0, v1);
                float2 hf = __bfloat1622float2(h2);
                __nv_bfloat162 l2 = __floats2bfloat162_rn(v0 - hf.x, v1 - hf.y);
                ph[q] = *(uint32_t*)&h2;
                pl[q] = *(uint32_t*)&l2;
            }
            ((uint4*)oh)[h] = uh;
            ((uint4*)ol)[h] = ul;
        }
    }
}

// ---------------------------------------------------------------------------
// flow_warp (reads NHWC fp32 supp, vectorized corners) -> NHWC bf16 hi/lo
// ---------------------------------------------------------------------------
__global__ void warp_nhwc_kernel(const float* __restrict__ suppN, const float* __restrict__ flow,
                                 __nv_bfloat16* __restrict__ oH, __nv_bfloat16* __restrict__ oL)
{
    int p = blockIdx.x * 256 + threadIdx.x;
    int b = blockIdx.y;
    int y = p >> 8, x = p & 255;
    float fx = flow[((size_t)b*2    )*HWSZ + p];
    float fy = flow[((size_t)b*2 + 1)*HWSZ + p];
    float sy = (float)y + fy, sx = (float)x + fx;
    float y0f = floorf(sy), x0f = floorf(sx);
    int iy0 = (int)y0f, ix0 = (int)x0f, iy1 = iy0+1, ix1 = ix0+1;
    float wy = sy - y0f, wx = sx - x0f;
    bool vy0 = ((unsigned)iy0 < HH), vy1 = ((unsigned)iy1 < HH);
    bool vx0 = ((unsigned)ix0 < WW), vx1 = ((unsigned)ix1 < WW);
    float w00 = (1.f-wy)*(1.f-wx) * ((vy0&&vx0)?1.f:0.f);
    float w01 = (1.f-wy)*wx       * ((vy0&&vx1)?1.f:0.f);
    float w10 = wy*(1.f-wx)       * ((vy1&&vx0)?1.f:0.f);
    float w11 = wy*wx             * ((vy1&&vx1)?1.f:0.f);
    int cy0 = min(max(iy0,0),HH-1), cy1 = min(max(iy1,0),HH-1);
    int cx0 = min(max(ix0,0),WW-1), cx1 = min(max(ix1,0),WW-1);
    size_t i00 = (size_t)(cy0*WW+cx0)*64, i01 = (size_t)(cy0*WW+cx1)*64;
    size_t i10 = (size_t)(cy1*WW+cx0)*64, i11 = (size_t)(cy1*WW+cx1)*64;
    const float* sb = suppN + (size_t)b*HWSZ*64;
    __nv_bfloat16* ohp = oH + ((size_t)b*HWSZ + p)*64;
    __nv_bfloat16* olp = oL + ((size_t)b*HWSZ + p)*64;
    #pragma unroll 1
    for (int g = 0; g < 8; g++) {
        const float4* p00 = (const float4*)(sb + i00 + g*8);
        const float4* p01 = (const float4*)(sb + i01 + g*8);
        const float4* p10 = (const float4*)(sb + i10 + g*8);
        const float4* p11 = (const float4*)(sb + i11 + g*8);
        float v[8];
        #pragma unroll
        for (int h = 0; h < 2; h++) {
            float4 a = p00[h], bb = p01[h], cc = p10[h], dd = p11[h];
            v[h*4+0] = w00*a.x + w01*bb.x + w10*cc.x + w11*dd.x;
            v[h*4+1] = w00*a.y + w01*bb.y + w10*cc.y + w11*dd.y;
            v[h*4+2] = w00*a.z + w01*bb.z + w10*cc.z + w11*dd.z;
            v[h*4+3] = w00*a.w + w01*bb.w + w10*cc.w + w11*dd.w;
        }
        uint4 uh, ul;
        uint32_t* ph = (uint32_t*)&uh;
        uint32_t* pl = (uint32_t*)&ul;
        #pragma unroll
        for (int q = 0; q < 4; q++) {
            __nv_bfloat162 h2 = __floats2bfloat162_rn(v[q*2], v[q*2+1]);
            float2 hf = __bfloat1622float2(h2);
            __nv_bfloat162 l2 = __floats2bfloat162_rn(v[q*2] - hf.x, v[q*2+1] - hf.y);
            ph[q] = *(uint32_t*)&h2;
            pl[q] = *(uint32_t*)&l2;
        }
        ((uint4*)ohp)[g] = uh;
        ((uint4*)olp)[g] = ul;
    }
}

// ---------------------------------------------------------------------------
// mma.sync conv: single A buffer per ki group, double-buffered B (NCH chunk
// sets per tap), group-accounting wait invariant. NCH=1: 3 CTAs/SM (proven).
// NCH=2: A staged once for both B sets, 2 CTAs/SM.
// EPI: 2 relu->hi/lo; 3 relu res(f32)+v ->f32; 4 relu outF+=0.1v;
//      5 relu res+0.1v ->hi/lo; 6 NCHW f32 (coutTot guard);
//      7 per-chunk relu->hi/lo (nc0: outH/L + bias, nc1: outH2/L2 + bias2);
//      8 relu + res(hi+lo from inH2/inL2) -> f32; 9 lrelu -> hi/lo.
// ---------------------------------------------------------------------------
template<int DIL, int EPI, int HASBIAS, int NT, int NCH>
__global__ void __launch_bounds__(256, (NCH == 2 ? 2 : 3))
conv_mma_kernel(const __nv_bfloat16* __restrict__ inH,
                const __nv_bfloat16* __restrict__ inL,
                const __nv_bfloat16* __restrict__ inH2,
                const __nv_bfloat16* __restrict__ inL2,
                const __nv_bfloat16* __restrict__ Bimg,
                const float* __restrict__ bias,
                const float* __restrict__ bias2,
                int nchunk, int coutTot,
                float* __restrict__ outF,
                __nv_bfloat16* __restrict__ outH,
                __nv_bfloat16* __restrict__ outL,
                __nv_bfloat16* __restrict__ outH2,
                __nv_bfloat16* __restrict__ outL2,
                const float* __restrict__ resF,
                float* __restrict__ outNCHW)
{
    constexpr uint32_t R = 128 + 2 * DIL;
    constexpr uint32_t AHALF = R * 128u;
    constexpr uint32_t ABUF = 2u * AHALF;
    constexpr uint32_t BSTEP = (uint32_t)NCH * 16384u;

    extern __shared__ char smem[];
    uint32_t base = (smem_u32(smem) + 1023u) & ~1023u;

    int tid = threadIdx.x;
    int lane = tid & 31, w = tid >> 5;
    int z = blockIdx.z;
    int b = z / nchunk, chunk = z - b * nchunk;
    int y = blockIdx.y, x0 = blockIdx.x * 128;

    const char* Bbase = (const char*)Bimg + (size_t)chunk * NCH * 147456;

    auto stageA = [&](int s) {
        int ki = (NT == 18 && s >= 3) ? s - 3 : s;
        const __nv_bfloat16* iH = (NT == 18 && s >= 3) ? inH2 : inH;
        const __nv_bfloat16* iL = (NT == 18 && s >= 3) ? inL2 : inL;
        int gy = y + (ki - 1) * DIL;
        bool rowok = ((unsigned)gy < HH);
        for (int i = tid; i < (int)(R * 8); i += 256) {
            int r = i >> 3, j = i & 7;
            int gx = x0 - DIL + r;
            bool ok = rowok && ((unsigned)gx < WW);
            size_t gidx = ok ? ((((size_t)b * HH + gy) * WW + gx) * 64) : 0;
            int sz = ok ? 16 : 0;
            uint32_t dst = base + (uint32_t)r * 128u +
                           (((uint32_t)j * 16u) ^ (((uint32_t)r & 7u) * 16u));
            CP_ASYNC16(dst, (const char*)(iH + gidx) + j * 16, sz);
            CP_ASYNC16(dst + AHALF, (const char*)(iL + gidx) + j * 16, sz);
        }
    };
    auto stageB = [&](int t2) {
        uint32_t bB = base + ABUF + (uint32_t)(t2 & 1) * BSTEP;
        #pragma unroll
        for (int nc = 0; nc < NCH; nc++) {
            const char* bsrc = Bbase + (size_t)nc * 147456 + (size_t)t2 * 16384;
            #pragma unroll
            for (int kk = 0; kk < 4; kk++)
                CP_ASYNC16(bB + (uint32_t)nc * 16384u + (uint32_t)tid * 16u + (uint32_t)kk * 4096u,
                           bsrc + tid * 16 + kk * 4096, 16);
        }
    };

    stageA(0);
    stageB(0);
    CP_COMMIT();

    int mbase = (w & 3) * 32;
    int nbase = (w >> 2) * 32;

    float acc[NCH][2][4][4];
    #pragma unroll
    for (int nc = 0; nc < NCH; nc++)
        #pragma unroll
        for (int i = 0; i < 2; i++)
            #pragma unroll
            for (int j = 0; j < 4; j++)
                #pragma unroll
                for (int q = 0; q < 4; q++) acc[nc][i][j][q] = 0.f;

    int lr = (lane & 7) + ((lane >> 3) & 1) * 8;
    int kq = (lane >> 4) * 16;

    #pragma unroll 1
    for (int tt = 0; tt < NT; tt++) {
        if (tt + 1 < NT && (tt + 1) % 3 != 0) {
            stageB(tt + 1);
            CP_COMMIT();
            CP_WAIT1();
        } else {
            CP_WAIT0();
        }
        __syncthreads();

        int s = tt / 3, kj = tt - s * 3;
        uint32_t Bt = base + ABUF + (uint32_t)(tt & 1) * BSTEP;
        uint32_t rowA0 = (uint32_t)(kj * DIL + mbase + lr);
        uint32_t rowB0 = (uint32_t)(nbase + lr);

        #pragma unroll
        for (int ks = 0; ks < 4; ks++) {
            uint32_t kb = (uint32_t)(ks * 32 + kq);
            uint32_t ah0[4], ah1[4], al0[4], al1[4];
            {
                uint32_t r0 = rowA0, r1 = rowA0 + 16u;
                uint32_t o0 = r0*128u + (kb ^ ((r0 & 7u)*16u));
                uint32_t o1 = r1*128u + (kb ^ ((r1 & 7u)*16u));
                LDSM_X4(ah0[0], ah0[1], ah0[2], ah0[3], base + o0);
                LDSM_X4(ah1[0], ah1[1], ah1[2], ah1[3], base + o1);
                LDSM_X4(al0[0], al0[1], al0[2], al0[3], base + AHALF + o0);
                LDSM_X4(al1[0], al1[1], al1[2], al1[3], base + AHALF + o1);
            }
            #pragma unroll
            for (int nc = 0; nc < NCH; nc++) {
                uint32_t Bc = Bt + (uint32_t)nc * 16384u;
                uint32_t bh0[4], bh1[4], bl0[4], bl1[4];
                uint32_t r0 = rowB0, r1 = rowB0 + 16u;
                uint32_t o0 = r0*128u + (kb ^ ((r0 & 7u)*16u));
                uint32_t o1 = r1*128u + (kb ^ ((r1 & 7u)*16u));
                LDSM_X4(bh0[0], bh0[1], bh0[2], bh0[3], Bc + o0);
                LDSM_X4(bh1[0], bh1[1], bh1[2], bh1[3], Bc + o1);
                LDSM_X4(bl0[0], bl0[1], bl0[2], bl0[3], Bc + 8192u + o0);
                LDSM_X4(bl1[0], bl1[1], bl1[2], bl1[3], Bc + 8192u + o1);
                MMA_BF16(acc[nc][0][0], ah0, bh0[0], bh0[2]);
                MMA_BF16(acc[nc][0][1], ah0, bh0[1], bh0[3]);
                MMA_BF16(acc[nc][0][2], ah0, bh1[0], bh1[2]);
                MMA_BF16(acc[nc][0][3], ah0, bh1[1], bh1[3]);
                MMA_BF16(acc[nc][1][0], ah1, bh0[0], bh0[2]);
                MMA_BF16(acc[nc][1][1], ah1, bh0[1], bh0[3]);
                MMA_BF16(acc[nc][1][2], ah1, bh1[0], bh1[2]);
                MMA_BF16(acc[nc][1][3], ah1, bh1[1], bh1[3]);
                MMA_BF16(acc[nc][0][0], ah0, bl0[0], bl0[2]);
                MMA_BF16(acc[nc][0][1], ah0, bl0[1], bl0[3]);
                MMA_BF16(acc[nc][0][2], ah0, bl1[0], bl1[2]);
                MMA_BF16(acc[nc][0][3], ah0, bl1[1], bl1[3]);
                MMA_BF16(acc[nc][1][0], ah1, bl0[0], bl0[2]);
                MMA_BF16(acc[nc][1][1], ah1, bl0[1], bl0[3]);
                MMA_BF16(acc[nc][1][2], ah1, bl1[0], bl1[2]);
                MMA_BF16(acc[nc][1][3], ah1, bl1[1], bl1[3]);
                MMA_BF16(acc[nc][0][0], al0, bh0[0], bh0[2]);
                MMA_BF16(acc[nc][0][1], al0, bh0[1], bh0[3]);
                MMA_BF16(acc[nc][0][2], al0, bh1[0], bh1[2]);
                MMA_BF16(acc[nc][0][3], al0, bh1[1], bh1[3]);
                MMA_BF16(acc[nc][1][0], al1, bh0[0], bh0[2]);
                MMA_BF16(acc[nc][1][1], al1, bh0[1], bh0[3]);
                MMA_BF16(acc[nc][1][2], al1, bh1[0], bh1[2]);
                MMA_BF16(acc[nc][1][3], al1, bh1[1], bh1[3]);
            }
        }
        __syncthreads();

        if (tt + 1 < NT && (tt + 1) % 3 == 0) {
            stageA((tt + 1) / 3);
            stageB(tt + 1);
            CP_COMMIT();
        }
    }

    // ---- epilogue ----
    #pragma unroll
    for (int nc = 0; nc < NCH; nc++) {
        const float* bp = (EPI == 7 && nc == 1) ? bias2 : bias;
        float bs2[4][2];
        #pragma unroll
        for (int nb = 0; nb < 4; nb++) {
            int co = (EPI == 7) ? (nbase + nb * 8 + (lane & 3) * 2)
                                : ((chunk * NCH + nc) * 64 + nbase + nb * 8 + (lane & 3) * 2);
            bs2[nb][0] = (HASBIAS && co     < coutTot) ? bp[co]     : 0.f;
            bs2[nb][1] = (HASBIAS && co + 1 < coutTot) ? bp[co + 1] : 0.f;
        }
        #pragma unroll
        for (int mt = 0; mt < 2; mt++) {
            #pragma unroll
            for (int rh = 0; rh < 2; rh++) {
                int px = x0 + mbase + mt * 16 + (lane >> 2) + rh * 8;
                size_t P = ((size_t)b * HH + y) * WW + px;
                #pragma unroll
                for (int nb = 0; nb < 4; nb++) {
                    int cl = nbase + nb * 8 + (lane & 3) * 2;
                    float v0 = acc[nc][mt][nb][rh * 2 + 0] + bs2[nb][0];
                    float v1 = acc[nc][mt][nb][rh * 2 + 1] + bs2[nb][1];
                    size_t ob = P * 64 + cl;

                    if (EPI == 2) {
                        v0 = fmaxf(v0, 0.f); v1 = fmaxf(v1, 0.f);
                        __nv_bfloat162 h2 = __floats2bfloat162_rn(v0, v1);
                        float2 hf = __bfloat1622float2(h2);
                        __nv_bfloat162 l2 = __floats2bfloat162_rn(v0 - hf.x, v1 - hf.y);
                        *(uint32_t*)(outH + ob) = *(uint32_t*)&h2;
                        *(uint32_t*)(outL + ob) = *(uint32_t*)&l2;
                    } else if (EPI == 3) {
                        float2 rv = *(const float2*)(resF + ob);
                        v0 = rv.x + fmaxf(v0, 0.f);
                        v1 = rv.y + fmaxf(v1, 0.f);
                        *(float2*)(outF + ob) = make_float2(v0, v1);
                    } else if (EPI == 4) {
                        float2 rv = *(const float2*)(outF + ob);
                        v0 = rv.x + 0.1f * fmaxf(v0, 0.f);
                        v1 = rv.y + 0.1f * fmaxf(v1, 0.f);
                        *(float2*)(outF + ob) = make_float2(v0, v1);
                    } else if (EPI == 5) {
                        float2 rv = *(const float2*)(resF + ob);
                        v0 = rv.x + 0.1f * fmaxf(v0, 0.f);
                        v1 = rv.y + 0.1f * fmaxf(v1, 0.f);
                        __nv_bfloat162 h2 = __floats2bfloat162_rn(v0, v1);
                        float2 hf = __bfloat1622float2(h2);
                        __nv_bfloat162 l2 = __floats2bfloat162_rn(v0 - hf.x, v1 - hf.y);
                        *(uint32_t*)(outH + ob) = *(uint32_t*)&h2;
                        *(uint32_t*)(outL + ob) = *(uint32_t*)&l2;
                    } else if (EPI == 6) {
                        int co = (chunk * NCH + nc) * 64 + cl;
                        size_t pix = ((size_t)y << 8) + px;
                        if (co < coutTot)
                            outNCHW[(((size_t)b * coutTot + co) << 16) + pix] = v0;
                        if (co + 1 < coutTot)
                            outNCHW[(((size_t)b * coutTot + co + 1) << 16) + pix] = v1;
                    } else if (EPI == 7) {
                        v0 = fmaxf(v0, 0.f); v1 = fmaxf(v1, 0.f);
                        __nv_bfloat16* oh = (nc == 0) ? outH : outH2;
                        __nv_bfloat16* ol = (nc == 0) ? outL : outL2;
                        __nv_bfloat162 h2 = __floats2bfloat162_rn(v0, v1);
                        float2 hf = __bfloat1622float2(h2);
                        __nv_bfloat162 l2 = __floats2bfloat162_rn(v0 - hf.x, v1 - hf.y);
                        *(uint32_t*)(oh + ob) = *(uint32_t*)&h2;
                        *(uint32_t*)(ol + ob) = *(uint32_t*)&l2;
                    } else if (EPI == 8) {
                        // res = hi+lo reconstructed from inH2/inL2 (feat0)
                        uint32_t rhw = *(const uint32_t*)(inH2 + ob);
                        uint32_t rlw = *(const uint32_t*)(inL2 + ob);
                        float2 hf = __bfloat1622float2(*(__nv_bfloat162*)&rhw);
                        float2 lf = __bfloat1622float2(*(__nv_bfloat162*)&rlw);
                        v0 = (hf.x + lf.x) + fmaxf(v0, 0.f);
                        v1 = (hf.y + lf.y) + fmaxf(v1, 0.f);
                        *(float2*)(outF + ob) = make_float2(v0, v1);
                    } else if (EPI == 9) {
                        v0 = (v0 > 0.f) ? v0 : 0.1f * v0;
                        v1 = (v1 > 0.f) ? v1 : 0.1f * v1;
                        __nv_bfloat162 h2 = __floats2bfloat162_rn(v0, v1);
                        float2 hf = __bfloat1622float2(h2);
                        __nv_bfloat162 l2 = __floats2bfloat162_rn(v0 - hf.x, v1 - hf.y);
                        *(uint32_t*)(outH + ob) = *(uint32_t*)&h2;
                        *(uint32_t*)(outL + ob) = *(uint32_t*)&l2;
                    }
                }
            }
        }
    }
}

// ---------------------------------------------------------------------------
// Modulated deformable conv, tensorized; NHWC fp32 gathers + fast
// transcendentals; occupancy 2; sampling loop unrolled 2x for MLP.
// ---------------------------------------------------------------------------
__global__ void __launch_bounds__(256, 2)
dcn_mma_kernel(const float* __restrict__ suppN, const float* __restrict__ off,
               const float* __restrict__ flow, const __nv_bfloat16* __restrict__ Bimg,
               const float* __restrict__ bias, float* __restrict__ out)
{
    extern __shared__ char smem[];
    uint32_t base = (smem_u32(smem) + 1023u) & ~1023u;
    const uint32_t SM_S = base;            // 32KB: hi 16K | lo 16K
    const uint32_t SM_Bd = base + 32768u;  // 2 x 16KB B double buffer

    int tid = threadIdx.x;
    int lane = tid & 31, w = tid >> 5;
    int b = blockIdx.z, y = blockIdx.y, x0 = blockIdx.x * 128;

    #pragma unroll
    for (int kk = 0; kk < 4; kk++)
        CP_ASYNC16(SM_Bd + (uint32_t)tid * 16u + (uint32_t)kk * 4096u,
                   (const char*)Bimg + tid * 16 + kk * 4096, 16);
    CP_COMMIT();

    int mbase = (w & 3) * 32;
    int nbase = (w >> 2) * 32;
    float acc[2][4][4];
    #pragma unroll
    for (int i = 0; i < 2; i++)
        #pragma unroll
        for (int j = 0; j < 4; j++)
            #pragma unroll
            for (int q = 0; q < 4; q++) acc[i][j][q] = 0.f;

    int lr = (lane & 7) + ((lane >> 3) & 1) * 8;
    int kq = (lane >> 4) * 16;

    const float* fxp  = flow + ((size_t)b*2 + 0)*HWSZ + y*WW + x0;
    const float* fyp  = flow + ((size_t)b*2 + 1)*HWSZ + y*WW + x0;
    const float* offb = off  + (size_t)b*216*HWSZ + y*WW + x0;
    const float* sb   = suppN + (size_t)b*HWSZ*64;

    #pragma unroll 1
    for (int k = 0; k < 9; k++) {
        if (k < 8) {
            const char* bsrc = (const char*)Bimg + (size_t)(k + 1) * 16384;
            uint32_t bB = SM_Bd + (uint32_t)((k + 1) & 1) * 16384u;
            #pragma unroll
            for (int kk = 0; kk < 4; kk++)
                CP_ASYNC16(bB + (uint32_t)tid * 16u + (uint32_t)kk * 4096u,
                           bsrc + tid * 16 + kk * 4096, 16);
            CP_COMMIT();
        }

        int ki = k / 3, kj = k - ki * 3;
        #pragma unroll 2
        for (int it = 0; it < 4; it++) {
            int task = tid + it * 256;
            int px = task & 127;
            int g  = task >> 7;
            int cdy = g*18 + k*2;
            float rawdy = offb[(size_t)cdy          *HWSZ + px];
            float rawdx = offb[(size_t)(cdy + 1)    *HWSZ + px];
            float rawm  = offb[(size_t)(144 + g*9+k)*HWSZ + px];
            float fx = fxp[px], fy = fyp[px];
            float ady = 25.f * fast_tanh(rawdy) + ((cdy     < 72) ? fx : fy);
            float adx = 25.f * fast_tanh(rawdx) + ((cdy + 1 < 72) ? fx : fy);
            float m   = fast_sigmoid(rawm);
            float sy = (float)y         + (float)(ki - 1) + ady;
            float sx = (float)(x0 + px) + (float)(kj - 1) + adx;
            float y0f = floorf(sy), x0f = floorf(sx);
            int iy0 = (int)y0f, ix0 = (int)x0f;
            int iy1 = iy0 + 1,  ix1 = ix0 + 1;
            float wy = sy - y0f, wx = sx - x0f;
            bool vy0 = ((unsigned)iy0 < HH), vy1 = ((unsigned)iy1 < HH);
            bool vx0 = ((unsigned)ix0 < WW), vx1 = ((unsigned)ix1 < WW);
            float w00 = (1.f - wy)*(1.f - wx) * ((vy0 && vx0) ? 1.f : 0.f) * m;
            float w01 = (1.f - wy)*wx         * ((vy0 && vx1) ? 1.f : 0.f) * m;
            float w10 = wy*(1.f - wx)         * ((vy1 && vx0) ? 1.f : 0.f) * m;
            float w11 = wy*wx                 * ((vy1 && vx1) ? 1.f : 0.f) * m;
            int cy0 = min(max(iy0, 0), HH-1), cy1 = min(max(iy1, 0), HH-1);
            int cx0 = min(max(ix0, 0), WW-1), cx1 = min(max(ix1, 0), WW-1);
            const float4* p00 = (const float4*)(sb + (size_t)(cy0*WW + cx0)*64 + g*8);
            const float4* p01 = (const float4*)(sb + (size_t)(cy0*WW + cx1)*64 + g*8);
            const float4* p10 = (const float4*)(sb + (size_t)(cy1*WW + cx0)*64 + g*8);
            const float4* p11 = (const float4*)(sb + (size_t)(cy1*WW + cx1)*64 + g*8);
            float v[8];
            #pragma unroll
            for (int h = 0; h < 2; h++) {
                float4 a = p00[h], bb = p01[h], cc = p10[h], dd = p11[h];
                v[h*4+0] = w00*a.x + w01*bb.x + w10*cc.x + w11*dd.x;
                v[h*4+1] = w00*a.y + w01*bb.y + w10*cc.y + w11*dd.y;
                v[h*4+2] = w00*a.z + w01*bb.z + w10*cc.z + w11*dd.z;
                v[h*4+3] = w00*a.w + w01*bb.w + w10*cc.w + w11*dd.w;
            }
            uint32_t hpk[4], lpk[4];
            #pragma unroll
            for (int q = 0; q < 4; q++) {
                __nv_bfloat162 h2 = __floats2bfloat162_rn(v[q*2], v[q*2+1]);
                float2 hf = __bfloat1622float2(h2);
                __nv_bfloat162 l2 = __floats2bfloat162_rn(v[q*2] - hf.x, v[q*2+1] - hf.y);
                hpk[q] = *(uint32_t*)&h2;
                lpk[q] = *(uint32_t*)&l2;
            }
            uint32_t so = (uint32_t)px * 128u +
                          (((uint32_t)g * 16u) ^ (((uint32_t)px & 7u) * 16u));
            asm volatile("st.shared.v4.b32 [%0], {%1,%2,%3,%4};"
                :: "r"(SM_S + so), "r"(hpk[0]), "r"(hpk[1]), "r"(hpk[2]), "r"(hpk[3]) : "memory");
            asm volatile("st.shared.v4.b32 [%0], {%1,%2,%3,%4};"
                :: "r"(SM_S + 16384u + so), "r"(lpk[0]), "r"(lpk[1]), "r"(lpk[2]), "r"(lpk[3]) : "memory");
        }

        if (k < 8) CP_WAIT1(); else CP_WAIT0();
        __syncthreads();

        uint32_t Bt = SM_Bd + (uint32_t)(k & 1) * 16384u;
        uint32_t rowA0 = (uint32_t)(mbase + lr);
        uint32_t rowB0 = (uint32_t)(nbase + lr);
        #pragma unroll
        for (int ks = 0; ks < 4; ks++) {
            uint32_t kb = (uint32_t)(ks * 32 + kq);
            uint32_t ah0[4], ah1[4], al0[4], al1[4];
            uint32_t bh0[4], bh1[4], bl0[4], bl1[4];
            {
                uint32_t r0 = rowA0, r1 = rowA0 + 16u;
                uint32_t o0 = r0*128u + (kb ^ ((r0 & 7u)*16u));
                uint32_t o1 = r1*128u + (kb ^ ((r1 & 7u)*16u));
                LDSM_X4(ah0[0], ah0[1], ah0[2], ah0[3], SM_S + o0);
                LDSM_X4(ah1[0], ah1[1], ah1[2], ah1[3], SM_S + o1);
                LDSM_X4(al0[0], al0[1], al0[2], al0[3], SM_S + 16384u + o0);
                LDSM_X4(al1[0], al1[1], al1[2], al1[3], SM_S + 16384u + o1);
            }
            {
                uint32_t r0 = rowB0, r1 = rowB0 + 16u;
                uint32_t o0 = r0*128u + (kb ^ ((r0 & 7u)*16u));
                uint32_t o1 = r1*128u + (kb ^ ((r1 & 7u)*16u));
                LDSM_X4(bh0[0], bh0[1], bh0[2], bh0[3], Bt + o0);
                LDSM_X4(bh1[0], bh1[1], bh1[2], bh1[3], Bt + o1);
                LDSM_X4(bl0[0], bl0[1], bl0[2], bl0[3], Bt + 8192u + o0);
                LDSM_X4(bl1[0], bl1[1], bl1[2], bl1[3], Bt + 8192u + o1);
            }
            MMA_BF16(acc[0][0], ah0, bh0[0], bh0[2]);
            MMA_BF16(acc[0][1], ah0, bh0[1], bh0[3]);
            MMA_BF16(acc[0][2], ah0, bh1[0], bh1[2]);
            MMA_BF16(acc[0][3], ah0, bh1[1], bh1[3]);
            MMA_BF16(acc[1][0], ah1, bh0[0], bh0[2]);
            MMA_BF16(acc[1][1], ah1, bh0[1], bh0[3]);
            MMA_BF16(acc[1][2], ah1, bh1[0], bh1[2]);
            MMA_BF16(acc[1][3], ah1, bh1[1], bh1[3]);
            MMA_BF16(acc[0][0], ah0, bl0[0], bl0[2]);
            MMA_BF16(acc[0][1], ah0, bl0[1], bl0[3]);
            MMA_BF16(acc[0][2], ah0, bl1[0], bl1[2]);
            MMA_BF16(acc[0][3], ah0, bl1[1], bl1[3]);
            MMA_BF16(acc[1][0], ah1, bl0[0], bl0[2]);
            MMA_BF16(acc[1][1], ah1, bl0[1], bl0[3]);
            MMA_BF16(acc[1][2], ah1, bl1[0], bl1[2]);
            MMA_BF16(acc[1][3], ah1, bl1[1], bl1[3]);
            MMA_BF16(acc[0][0], al0, bh0[0], bh0[2]);
            MMA_BF16(acc[0][1], al0, bh0[1], bh0[3]);
            MMA_BF16(acc[0][2], al0, bh1[0], bh1[2]);
            MMA_BF16(acc[0][3], al0, bh1[1], bh1[3]);
            MMA_BF16(acc[1][0], al1, bh0[0], bh0[2]);
            MMA_BF16(acc[1][1], al1, bh0[1], bh0[3]);
            MMA_BF16(acc[1][2], al1, bh1[0], bh1[2]);
            MMA_BF16(acc[1][3], al1, bh1[1], bh1[3]);
        }
        __syncthreads();
    }

    // ---- epilogue: bias + NCHW fp32 store ----
    float bs2[4][2];
    #pragma unroll
    for (int nb = 0; nb < 4; nb++) {
        int co = nbase + nb * 8 + (lane & 3) * 2;
        bs2[nb][0] = bias[co];
        bs2[nb][1] = bias[co + 1];
    }
    #pragma unroll
    for (int mt = 0; mt < 2; mt++) {
        #pragma unroll
        for (int rh = 0; rh < 2; rh++) {
            int px = x0 + mbase + mt * 16 + (lane >> 2) + rh * 8;
            size_t pix = ((size_t)y << 8) + px;
            #pragma unroll
            for (int nb = 0; nb < 4; nb++) {
                int co = nbase + nb * 8 + (lane & 3) * 2;
                out[(((size_t)b * 64 + co    ) << 16) + pix] = acc[mt][nb][rh*2+0] + bs2[nb][0];
                out[(((size_t)b * 64 + co + 1) << 16) + pix] = acc[mt][nb][rh*2+1] + bs2[nb][1];
            }
        }
    }
}

// ---------------------------------------------------------------------------
// Launch
// ---------------------------------------------------------------------------
extern "C" void kernel_launch(void* const* d_in, const int* in_sizes, int n_in,
                              void* d_out, int out_size)
{
    const float* ref   = (const float*)d_in[0];
    const float* supp  = (const float*)d_in[1];
    const float* flow  = (const float*)d_in[2];
    const float* fc_w  = (const float*)d_in[3];
    const float* fc_b  = (const float*)d_in[4];
    const float* cw[6], *cb[6];
    for (int i = 0; i < 6; i++) {
        cw[i] = (const float*)d_in[5 + 2*i];
        cb[i] = (const float*)d_in[6 + 2*i];
    }
    const float* off_w = (const float*)d_in[17];
    const float* off_b = (const float*)d_in[18];
    const float* dcn_w = (const float*)d_in[19];
    const float* dcn_b = (const float*)d_in[20];
    float* out = (float*)d_out;

    __nv_bfloat16 *wH, *wL, *rH, *rL, *t0H, *t0L, *tmpH, *tmpL, *tm2H, *tm2L, *ftH, *ftL, *Bg;
    float *ffF, *offbuf, *suppN;
    cudaGetSymbolAddress((void**)&wH,  g_wH);   cudaGetSymbolAddress((void**)&wL,  g_wL);
    cudaGetSymbolAddress((void**)&rH,  g_rH);   cudaGetSymbolAddress((void**)&rL,  g_rL);
    cudaGetSymbolAddress((void**)&t0H, g_t0H);  cudaGetSymbolAddress((void**)&t0L, g_t0L);
    cudaGetSymbolAddress((void**)&tmpH,g_tmpH); cudaGetSymbolAddress((void**)&tmpL,g_tmpL);
    cudaGetSymbolAddress((void**)&tm2H,g_tm2H); cudaGetSymbolAddress((void**)&tm2L,g_tm2L);
    cudaGetSymbolAddress((void**)&ftH, g_ftH);  cudaGetSymbolAddress((void**)&ftL, g_ftL);
    cudaGetSymbolAddress((void**)&Bg,  g_B);
    cudaGetSymbolAddress((void**)&ffF,   g_ffF);
    cudaGetSymbolAddress((void**)&offbuf,g_off);
    cudaGetSymbolAddress((void**)&suppN, g_sN);

    // smem: pad + single A (2*(128+2d)*128) + 2*NCH*16KB B
    const int SMB1 = 1024 + 2*(130*128) + 32768;   // 67072 (NCH=1, d=1)
    const int SMB2 = 1024 + 2*(132*128) + 32768;   // 67584 (NCH=1, d=2)
    const int SMB4 = 1024 + 2*(136*128) + 32768;   // 68608 (NCH=1, d=4)
    const int SMO  = 1024 + 2*(130*128) + 65536;   // 99840 (NCH=2, d=1)
    const int SMC  = 1024 + 2*(132*128) + 65536;   // 100352 (NCH=2, d=2)
    const int SMD  = 1024 + 32768 + 32768;         // 66560
    cudaFuncSetAttribute((const void*)conv_mma_kernel<1,9,1,18,1>, cudaFuncAttributeMaxDynamicSharedMemorySize, SMB1);
    cudaFuncSetAttribute((const void*)conv_mma_kernel<1,2,1,9,1>,  cudaFuncAttributeMaxDynamicSharedMemorySize, SMB1);
    cudaFuncSetAttribute((const void*)conv_mma_kernel<1,8,1,9,1>,  cudaFuncAttributeMaxDynamicSharedMemorySize, SMB1);
    cudaFuncSetAttribute((const void*)conv_mma_kernel<2,7,1,9,2>,  cudaFuncAttributeMaxDynamicSharedMemorySize, SMC);
    cudaFuncSetAttribute((const void*)conv_mma_kernel<2,4,1,9,1>,  cudaFuncAttributeMaxDynamicSharedMemorySize, SMB2);
    cudaFuncSetAttribute((const void*)conv_mma_kernel<4,5,1,9,1>,  cudaFuncAttributeMaxDynamicSharedMemorySize, SMB4);
    cudaFuncSetAttribute((const void*)conv_mma_kernel<1,6,1,9,2>,  cudaFuncAttributeMaxDynamicSharedMemorySize, SMO);
    cudaFuncSetAttribute((const void*)dcn_mma_kernel, cudaFuncAttributeMaxDynamicSharedMemorySize, SMD);

    // Fused weight prep (13 sets; c3,c5 adjacent at 4,5 for NCH=2 fusion)
    PrepTable tab;
    tab.d[0]  = {fc_w, 128, 0,  64, 0};
    tab.d[1]  = {fc_w, 128, 64, 64, 0};
    tab.d[2]  = {cw[0], 64, 0, 64, 0};   // c1
    tab.d[3]  = {cw[1], 64, 0, 64, 0};   // c2
    tab.d[4]  = {cw[2], 64, 0, 64, 0};   // c3
    tab.d[5]  = {cw[4], 64, 0, 64, 0};   // c5 (adjacent to c3)
    tab.d[6]  = {cw[3], 64, 0, 64, 0};   // c4
    tab.d[7]  = {cw[5], 64, 0, 64, 0};   // c6
    for (int ch = 0; ch < 4; ch++) tab.d[8+ch] = {off_w, 64, 0, 216, ch*64};
    tab.d[12] = {dcn_w, 64, 0, 64, 0};
    prep_all_kernel<<<dim3(144, 13), 256>>>(tab, Bg);

    // Combined converters: z=0 supp->NHWC fp32, z=1 ref->NHWC hi/lo
    convert_kernel<<<dim3(HWSZ/64, BB, 2), 256>>>(supp, suppN, ref, rH, rL);
    // flow warp (reads NHWC supp)
    warp_nhwc_kernel<<<dim3(HWSZ/256, BB), 256>>>(suppN, flow, wH, wL);

    dim3 cg(2, 256, 4);
    // fc (fused 18-tap): lrelu -> feat0 hi/lo only
    conv_mma_kernel<1,9,1,18,1><<<cg, 256, SMB1>>>(wH, wL, rH, rL, Bg + 0*BSET, fc_b, nullptr, 1, 64,
                                                   nullptr, t0H, t0L, nullptr, nullptr, nullptr, nullptr);
    // c1: relu -> tmp
    conv_mma_kernel<1,2,1,9,1><<<cg, 256, SMB1>>>(t0H, t0L, nullptr, nullptr, Bg + 2*BSET, cb[0], nullptr, 1, 64,
                                                  nullptr, tmpH, tmpL, nullptr, nullptr, nullptr, nullptr);
    // c2: ff = feat0(hi+lo) + relu(v) -> f32
    conv_mma_kernel<1,8,1,9,1><<<cg, 256, SMB1>>>(tmpH, tmpL, t0H, t0L, Bg + 3*BSET, cb[1], nullptr, 1, 64,
                                                  ffF, nullptr, nullptr, nullptr, nullptr, nullptr, nullptr);
    // c3+c5 fused (dil2, NCH=2, same input feat0): relu -> tmp (c3), tm2 (c5)
    conv_mma_kernel<2,7,1,9,2><<<cg, 256, SMC>>>(t0H, t0L, nullptr, nullptr, Bg + 4*BSET, cb[2], cb[4], 1, 64,
                                                 nullptr, tmpH, tmpL, tm2H, tm2L, nullptr, nullptr);
    // c4 (dil2): ff += 0.1*relu(v)  [reads c3 out = tmp]
    conv_mma_kernel<2,4,1,9,1><<<cg, 256, SMB2>>>(tmpH, tmpL, nullptr, nullptr, Bg + 6*BSET, cb[3], nullptr, 1, 64,
                                                  ffF, nullptr, nullptr, nullptr, nullptr, nullptr, nullptr);
    // c6 (dil4): feat = ff + 0.1*relu(v) -> hi/lo  [reads c5 out = tm2]
    conv_mma_kernel<4,5,1,9,1><<<cg, 256, SMB4>>>(tm2H, tm2L, nullptr, nullptr, Bg + 7*BSET, cb[5], nullptr, 1, 64,
                                                  nullptr, ftH, ftL, nullptr, nullptr, ffF, nullptr);
    // offset conv: 216 couts via 2 fused chunk-pairs (128 couts/CTA), NCHW out
    dim3 og(2, 256, BB*2);
    conv_mma_kernel<1,6,1,9,2><<<og, 256, SMO>>>(ftH, ftL, nullptr, nullptr, Bg + 8*BSET, off_b, nullptr, 2, 216,
                                                 nullptr, nullptr, nullptr, nullptr, nullptr, nullptr, offbuf);
    // tensorized deformable conv (fast transcendentals, occ 2, unroll-2 sampler)
    dcn_mma_kernel<<<cg, 256, SMD>>>(suppN, offbuf, flow, Bg + 12*BSET, dcn_b, out);
}